// round 1
// baseline (speedup 1.0000x reference)
#include <cuda_runtime.h>

// ---------------- problem constants ----------------
#define NB   4
#define SEQ  4096
#define DIMM 512
#define NH   8
#define DHD  64
#define NF   256
#define CSZ  128
#define NCH  32                  // chunks per (b,h)
#define MTOK (NB*SEQ)            // 16384
#define QKVN (3*DIMM)            // 1536
#define NCHUNK (NB*NH*NCH)       // 1024

// ---------------- device scratch (no allocs allowed) ----------------
__device__ float g_qkv [MTOK * QKVN];          // [16384][1536]
__device__ float g_qp  [NB*NH*SEQ*NF];         // [(b*8+h)*4096 + t][256]
__device__ float g_kp  [NB*NH*SEQ*NF];
__device__ float g_ksum[NCHUNK * NF];          // [chunk][256]
__device__ float g_ctx [NCHUNK * NF * DHD];    // [chunk][256][64]
__device__ float g_att [MTOK * DIMM];          // [16384][512]

// =====================================================================
// SGEMM NT: C[m][n] = sum_k A[m][k] * B[n][k] (+ bias[n])
// 128x128 block tile, BK=16, 256 threads, 8x8 microtile, double-buffered
// =====================================================================
template<bool BIAS>
__global__ __launch_bounds__(256, 2)
void sgemm_nt(const float* __restrict__ A, const float* __restrict__ Bm,
              const float* __restrict__ bias, float* __restrict__ C,
              int M, int N, int K)
{
    __shared__ float As[2][16][132];   // [k][m], padded
    __shared__ float Bs[2][16][128];   // [k][n]

    const int tid = threadIdx.x;
    const int tx  = tid & 15;          // n direction (8 cols, stride 16)
    const int ty  = tid >> 4;          // m direction (8 rows, stride 16)
    const int bm  = blockIdx.y * 128;
    const int bn  = blockIdx.x * 128;

    const int lm = tid >> 2;           // 0..63 : row within tile
    const int lk = (tid & 3) * 4;      // k offset of the float4

    const float* Ap = A  + (size_t)(bm + lm) * K + lk;
    const float* Bp = Bm + (size_t)(bn + lm) * K + lk;

    float acc[8][8];
#pragma unroll
    for (int i = 0; i < 8; i++)
#pragma unroll
        for (int j = 0; j < 8; j++) acc[i][j] = 0.f;

    float4 pa0 = *(const float4*)Ap;
    float4 pa1 = *(const float4*)(Ap + (size_t)64 * K);
    float4 pb0 = *(const float4*)Bp;
    float4 pb1 = *(const float4*)(Bp + (size_t)64 * K);

    // store tile 0 into buffer 0
    As[0][lk+0][lm]    = pa0.x; As[0][lk+1][lm]    = pa0.y;
    As[0][lk+2][lm]    = pa0.z; As[0][lk+3][lm]    = pa0.w;
    As[0][lk+0][lm+64] = pa1.x; As[0][lk+1][lm+64] = pa1.y;
    As[0][lk+2][lm+64] = pa1.z; As[0][lk+3][lm+64] = pa1.w;
    Bs[0][lk+0][lm]    = pb0.x; Bs[0][lk+1][lm]    = pb0.y;
    Bs[0][lk+2][lm]    = pb0.z; Bs[0][lk+3][lm]    = pb0.w;
    Bs[0][lk+0][lm+64] = pb1.x; Bs[0][lk+1][lm+64] = pb1.y;
    Bs[0][lk+2][lm+64] = pb1.z; Bs[0][lk+3][lm+64] = pb1.w;
    __syncthreads();

    const int KT = K >> 4;
    for (int kt = 0; kt < KT; ++kt) {
        const int buf = kt & 1;
        if (kt + 1 < KT) {
            const float* Ap2 = Ap + (kt + 1) * 16;
            const float* Bp2 = Bp + (kt + 1) * 16;
            pa0 = *(const float4*)Ap2;
            pa1 = *(const float4*)(Ap2 + (size_t)64 * K);
            pb0 = *(const float4*)Bp2;
            pb1 = *(const float4*)(Bp2 + (size_t)64 * K);
        }
#pragma unroll
        for (int k = 0; k < 16; ++k) {
            float af[8], bf[8];
#pragma unroll
            for (int i = 0; i < 8; i++) af[i] = As[buf][k][ty + 16*i];
#pragma unroll
            for (int j = 0; j < 8; j++) bf[j] = Bs[buf][k][tx + 16*j];
#pragma unroll
            for (int i = 0; i < 8; i++)
#pragma unroll
                for (int j = 0; j < 8; j++)
                    acc[i][j] = fmaf(af[i], bf[j], acc[i][j]);
        }
        if (kt + 1 < KT) {
            const int nb = buf ^ 1;
            As[nb][lk+0][lm]    = pa0.x; As[nb][lk+1][lm]    = pa0.y;
            As[nb][lk+2][lm]    = pa0.z; As[nb][lk+3][lm]    = pa0.w;
            As[nb][lk+0][lm+64] = pa1.x; As[nb][lk+1][lm+64] = pa1.y;
            As[nb][lk+2][lm+64] = pa1.z; As[nb][lk+3][lm+64] = pa1.w;
            Bs[nb][lk+0][lm]    = pb0.x; Bs[nb][lk+1][lm]    = pb0.y;
            Bs[nb][lk+2][lm]    = pb0.z; Bs[nb][lk+3][lm]    = pb0.w;
            Bs[nb][lk+0][lm+64] = pb1.x; Bs[nb][lk+1][lm+64] = pb1.y;
            Bs[nb][lk+2][lm+64] = pb1.z; Bs[nb][lk+3][lm+64] = pb1.w;
            __syncthreads();
        }
    }

#pragma unroll
    for (int i = 0; i < 8; i++) {
        const int row = bm + ty + 16*i;
#pragma unroll
        for (int j = 0; j < 8; j++) {
            const int col = bn + tx + 16*j;
            float v = acc[i][j];
            if (BIAS) v += bias[col];
            C[(size_t)row * N + col] = v;
        }
    }
}

// =====================================================================
// Feature map: per chunk, qp/kp[s][f] = exp( (t*scale)·proj_f - rowmax )
// block = one (chunk, q/k) pair. 512 threads, 8x8 microtile over [128 s][256 f]
// Also computes ksum[f] (k only).
// =====================================================================
__global__ __launch_bounds__(512, 1)
void feature_kernel(const float* __restrict__ proj)
{
    extern __shared__ float sm[];
    float* as  = sm;                 // [64][132]  A^T : [k][s]
    float* pt  = sm + 64*132;        // [64][256]  proj^T : [k][f]
    float* red = pt + 64*256;        // [16][256]  ksum partials

    const int cid = blockIdx.x;           // 0..1023
    const int isK = blockIdx.y;           // 0 = q, 1 = k
    const int b  = cid >> 8;
    const int h  = (cid >> 5) & 7;
    const int cc = cid & 31;
    const size_t row0   = (size_t)b * SEQ + (size_t)cc * CSZ;  // token row in [0,16384)
    const int   colbase = isK * DIMM + h * DHD;
    const float scale   = isK ? 1.0f : 0.125f;   // DH^-0.5 applied to q only
    const int tid = threadIdx.x;

    // load chunk rows [128][64] -> as[k][s] (scaled)
#pragma unroll
    for (int it = 0; it < 4; ++it) {
        const int f4 = it * 512 + tid;        // 0..2047
        const int s  = f4 >> 4;
        const int d  = (f4 & 15) * 4;
        float4 v = *(const float4*)(g_qkv + (row0 + s) * QKVN + colbase + d);
        as[(d+0)*132 + s] = v.x * scale;
        as[(d+1)*132 + s] = v.y * scale;
        as[(d+2)*132 + s] = v.z * scale;
        as[(d+3)*132 + s] = v.w * scale;
    }
    // load proj [256][64] -> pt[k][f]
#pragma unroll
    for (int it = 0; it < 8; ++it) {
        const int f4 = it * 512 + tid;        // 0..4095
        const int f  = f4 >> 4;
        const int d  = (f4 & 15) * 4;
        float4 v = *(const float4*)(proj + f * DHD + d);
        pt[(d+0)*256 + f] = v.x;
        pt[(d+1)*256 + f] = v.y;
        pt[(d+2)*256 + f] = v.z;
        pt[(d+3)*256 + f] = v.w;
    }
    __syncthreads();

    const int ft = tid & 31;   // f = ft + 32*j   (lanes = f direction)
    const int st = tid >> 5;   // s = st + 16*i
    float acc[8][8];
#pragma unroll
    for (int i = 0; i < 8; i++)
#pragma unroll
        for (int j = 0; j < 8; j++) acc[i][j] = 0.f;

    for (int k = 0; k < 64; ++k) {
        float a[8], bb[8];
#pragma unroll
        for (int i = 0; i < 8; i++) a[i]  = as[k*132 + st + 16*i];
#pragma unroll
        for (int j = 0; j < 8; j++) bb[j] = pt[k*256 + ft + 32*j];
#pragma unroll
        for (int i = 0; i < 8; i++)
#pragma unroll
            for (int j = 0; j < 8; j++)
                acc[i][j] = fmaf(a[i], bb[j], acc[i][j]);
    }

    float* outp = isK ? g_kp : g_qp;
    const size_t obase = ((size_t)(b*NH + h) * SEQ + (size_t)cc * CSZ) * NF;
    float psum[8];
#pragma unroll
    for (int j = 0; j < 8; j++) psum[j] = 0.f;

#pragma unroll
    for (int i = 0; i < 8; i++) {
        float m = acc[i][0];
#pragma unroll
        for (int j = 1; j < 8; j++) m = fmaxf(m, acc[i][j]);
#pragma unroll
        for (int off = 16; off > 0; off >>= 1)
            m = fmaxf(m, __shfl_xor_sync(0xffffffffu, m, off));
        const int s = st + 16*i;
#pragma unroll
        for (int j = 0; j < 8; j++) {
            const float e = __expf(acc[i][j] - m);
            outp[obase + (size_t)s * NF + ft + 32*j] = e;
            psum[j] += e;
        }
    }

    if (isK) {
#pragma unroll
        for (int j = 0; j < 8; j++) red[st*256 + ft + 32*j] = psum[j];
        __syncthreads();
        if (tid < NF) {
            float ssum = 0.f;
#pragma unroll
            for (int r = 0; r < 16; r++) ssum += red[r*256 + tid];
            g_ksum[(size_t)cid * NF + tid] = ssum;
        }
    }
}

// =====================================================================
// Context: per chunk, ctx[f][d] = sum_s kp[s][f] * v[s][d]   (256x64x128)
// 256 threads, 8x8 microtile.
// =====================================================================
__global__ __launch_bounds__(256, 1)
void ctx_kernel()
{
    extern __shared__ float sm[];
    float* kps = sm;                // [128][256]
    float* vs  = sm + CSZ * NF;     // [128][64]

    const int cid = blockIdx.x;
    const int b  = cid >> 8;
    const int h  = (cid >> 5) & 7;
    const int cc = cid & 31;
    const size_t row0   = (size_t)b * SEQ + (size_t)cc * CSZ;
    const size_t kpbase = ((size_t)(b*NH + h) * SEQ + (size_t)cc * CSZ) * NF;
    const int vcol = 2 * DIMM + h * DHD;
    const int tid = threadIdx.x;

#pragma unroll
    for (int it = 0; it < 32; ++it) {
        const int f4 = it * 256 + tid;        // 0..8191
        *(float4*)(kps + (size_t)f4 * 4) =
            *(const float4*)(g_kp + kpbase + (size_t)f4 * 4);
    }
#pragma unroll
    for (int it = 0; it < 8; ++it) {
        const int f4 = it * 256 + tid;        // 0..2047
        const int s  = f4 >> 4;
        const int d  = (f4 & 15) * 4;
        *(float4*)(vs + s*64 + d) =
            *(const float4*)(g_qkv + (row0 + s) * QKVN + vcol + d);
    }
    __syncthreads();

    const int ftid = tid >> 3;   // 0..31 : f = ftid + 32*j
    const int dtid = tid & 7;    // d = dtid + 8*i
    float acc[8][8];
#pragma unroll
    for (int j = 0; j < 8; j++)
#pragma unroll
        for (int i = 0; i < 8; i++) acc[j][i] = 0.f;

    for (int s = 0; s < CSZ; ++s) {
        float kf[8], vv[8];
#pragma unroll
        for (int j = 0; j < 8; j++) kf[j] = kps[s*NF + ftid + 32*j];
#pragma unroll
        for (int i = 0; i < 8; i++) vv[i] = vs[s*DHD + dtid + 8*i];
#pragma unroll
        for (int j = 0; j < 8; j++)
#pragma unroll
            for (int i = 0; i < 8; i++)
                acc[j][i] = fmaf(kf[j], vv[i], acc[j][i]);
    }

    float* cb = g_ctx + (size_t)cid * NF * DHD;
#pragma unroll
    for (int j = 0; j < 8; j++)
#pragma unroll
        for (int i = 0; i < 8; i++)
            cb[(ftid + 32*j) * DHD + dtid + 8*i] = acc[j][i];
}

// =====================================================================
// Output: per chunk, D[s] = qp[s]·ksum ; out[s][d] = (qp[s]·ctx[:,d]) / (D+1e-4)
// 256 threads, 4s x 8d microtile; writes att[t][h*64+d].
// =====================================================================
#define QPLD 261   // padded leading dim (gcd(5,32)=1 -> conflict-free)
__global__ __launch_bounds__(256, 1)
void out_kernel()
{
    extern __shared__ float sm[];
    float* qps  = sm;                      // [128][261]
    float* ctxs = sm + CSZ * QPLD;         // [256][64]
    float* ks   = ctxs + NF * DHD;         // [256]

    const int cid = blockIdx.x;
    const int b  = cid >> 8;
    const int h  = (cid >> 5) & 7;
    const int cc = cid & 31;
    const size_t row0   = (size_t)b * SEQ + (size_t)cc * CSZ;
    const size_t qpbase = ((size_t)(b*NH + h) * SEQ + (size_t)cc * CSZ) * NF;
    const int tid = threadIdx.x;

#pragma unroll
    for (int it = 0; it < 32; ++it) {
        const int f4 = it * 256 + tid;        // 0..8191
        const int s  = f4 >> 6;
        const int c  = (f4 & 63) * 4;
        float4 v = *(const float4*)(g_qp + qpbase + (size_t)s * NF + c);
        qps[s*QPLD + c + 0] = v.x;
        qps[s*QPLD + c + 1] = v.y;
        qps[s*QPLD + c + 2] = v.z;
        qps[s*QPLD + c + 3] = v.w;
    }
#pragma unroll
    for (int it = 0; it < 16; ++it) {
        const int f4 = it * 256 + tid;        // 0..4095
        *(float4*)(ctxs + (size_t)f4 * 4) =
            *(const float4*)(g_ctx + (size_t)cid * NF * DHD + (size_t)f4 * 4);
    }
    if (tid < NF) ks[tid] = g_ksum[(size_t)cid * NF + tid];
    __syncthreads();

    const int stid = tid & 31;    // s = stid + 32*i
    const int dt   = tid >> 5;    // 0..7 : d = dt*8 + l
    float acc[4][8];
    float Dacc[4];
#pragma unroll
    for (int i = 0; i < 4; i++) {
        Dacc[i] = 0.f;
#pragma unroll
        for (int l = 0; l < 8; l++) acc[i][l] = 0.f;
    }

    for (int f = 0; f < NF; ++f) {
        const float kk = ks[f];
        const float4 c0 = *(const float4*)(ctxs + f*DHD + dt*8);
        const float4 c1 = *(const float4*)(ctxs + f*DHD + dt*8 + 4);
#pragma unroll
        for (int i = 0; i < 4; i++) {
            const float qv = qps[(stid + 32*i) * QPLD + f];
            Dacc[i]  = fmaf(qv, kk,   Dacc[i]);
            acc[i][0] = fmaf(qv, c0.x, acc[i][0]);
            acc[i][1] = fmaf(qv, c0.y, acc[i][1]);
            acc[i][2] = fmaf(qv, c0.z, acc[i][2]);
            acc[i][3] = fmaf(qv, c0.w, acc[i][3]);
            acc[i][4] = fmaf(qv, c1.x, acc[i][4]);
            acc[i][5] = fmaf(qv, c1.y, acc[i][5]);
            acc[i][6] = fmaf(qv, c1.z, acc[i][6]);
            acc[i][7] = fmaf(qv, c1.w, acc[i][7]);
        }
    }

#pragma unroll
    for (int i = 0; i < 4; i++) {
        const float dinv = 1.0f / (Dacc[i] + 1e-4f);
        const int s = stid + 32*i;
        float* op = g_att + (row0 + s) * DIMM + h * DHD + dt * 8;
        float4 o0 = make_float4(acc[i][0]*dinv, acc[i][1]*dinv,
                                acc[i][2]*dinv, acc[i][3]*dinv);
        float4 o1 = make_float4(acc[i][4]*dinv, acc[i][5]*dinv,
                                acc[i][6]*dinv, acc[i][7]*dinv);
        *(float4*)op       = o0;
        *(float4*)(op + 4) = o1;
    }
}

// =====================================================================
// launch
// =====================================================================
extern "C" void kernel_launch(void* const* d_in, const int* in_sizes, int n_in,
                              void* d_out, int out_size)
{
    const float *x = nullptr, *wqkv = nullptr, *wout = nullptr,
                *bout = nullptr, *proj = nullptr;
    for (int i = 0; i < n_in; i++) {
        switch (in_sizes[i]) {
            case MTOK * DIMM:  x    = (const float*)d_in[i]; break; // 8388608
            case QKVN * DIMM:  wqkv = (const float*)d_in[i]; break; // 786432
            case DIMM * DIMM:  wout = (const float*)d_in[i]; break; // 262144
            case DIMM:         bout = (const float*)d_in[i]; break; // 512
            case NF * DHD:     proj = (const float*)d_in[i]; break; // 16384
        }
    }

    const int FEAT_SMEM = (64*132 + 64*256 + 16*256) * 4;      // 115712
    const int CTX_SMEM  = (CSZ*NF + CSZ*DHD) * 4;              // 163840
    const int OUT_SMEM  = (CSZ*QPLD + NF*DHD + NF) * 4;        // 200192
    cudaFuncSetAttribute(feature_kernel, cudaFuncAttributeMaxDynamicSharedMemorySize, FEAT_SMEM);
    cudaFuncSetAttribute(ctx_kernel,     cudaFuncAttributeMaxDynamicSharedMemorySize, CTX_SMEM);
    cudaFuncSetAttribute(out_kernel,     cudaFuncAttributeMaxDynamicSharedMemorySize, OUT_SMEM);

    float *qkvp = nullptr, *attp = nullptr;
    cudaGetSymbolAddress((void**)&qkvp, g_qkv);
    cudaGetSymbolAddress((void**)&attp, g_att);

    // 1) qkv = x @ w_qkv^T           [16384 x 1536 x 512]
    sgemm_nt<false><<<dim3(QKVN/128, MTOK/128), 256>>>(x, wqkv, nullptr, qkvp,
                                                       MTOK, QKVN, DIMM);
    // 2) q' and k' feature maps (+ ksum for k)
    feature_kernel<<<dim3(NCHUNK, 2), 512, FEAT_SMEM>>>(proj);
    // 3) ctx = k'^T v per chunk
    ctx_kernel<<<NCHUNK, 256, CTX_SMEM>>>();
    // 4) out = (q' @ ctx) * Dinv  -> att
    out_kernel<<<NCHUNK, 256, OUT_SMEM>>>();
    // 5) final = att @ w_out^T + b_out
    sgemm_nt<true><<<dim3(DIMM/128, MTOK/128), 256>>>(attp, wout, bout,
                                                      (float*)d_out,
                                                      MTOK, DIMM, DIMM);
}

// round 2
// speedup vs baseline: 1.5507x; 1.5507x over previous
#include <cuda_runtime.h>
#include <cstdint>

// ---------------- problem constants ----------------
#define NB   4
#define SEQ  4096
#define DIMM 512
#define NH   8
#define DHD  64
#define NF   256
#define CSZ  128
#define NCH  32                  // chunks per (b,h)
#define MTOK (NB*SEQ)            // 16384
#define QKVN (3*DIMM)            // 1536
#define NCHUNK (NB*NH*NCH)       // 1024

// ---------------- device scratch (no allocs allowed) ----------------
__device__ float g_qkv [MTOK * QKVN];          // [16384][1536]
__device__ float g_qp  [NB*NH*SEQ*NF];         // [(b*8+h)*4096 + t][256]
__device__ float g_kp  [NB*NH*SEQ*NF];
__device__ float g_ksum[NCHUNK * NF];          // [chunk][256]
__device__ float g_ctx [NCHUNK * NF * DHD];    // [chunk][256][64]
__device__ float g_att [MTOK * DIMM];          // [16384][512]

__device__ __forceinline__ uint32_t f2tf32(float f) {
    uint32_t r;
    asm("cvt.rna.tf32.f32 %0, %1;" : "=r"(r) : "f"(f));
    return r;
}

// =====================================================================
// TF32 tensor-core GEMM NT: C[m][n] = sum_k A[m][k]*B[n][k] (+bias[n])
// 128x128 block tile, BK=16, 256 threads (8 warps, 4m x 2n),
// warp tile 32(m) x 64(n), mma.m16n8k8.tf32, double-buffered smem.
// =====================================================================
template<bool BIAS>
__global__ __launch_bounds__(256, 2)
void tgemm_nt(const float* __restrict__ A, const float* __restrict__ Bm,
              const float* __restrict__ bias, float* __restrict__ C,
              int M, int N, int K)
{
    __shared__ uint32_t As[2][16][136];   // [k][m], pad 136 -> conflict-free frags
    __shared__ uint32_t Bs[2][16][136];   // [k][n]

    const int tid  = threadIdx.x;
    const int lane = tid & 31;
    const int warp = tid >> 5;
    const int wm   = (warp >> 1) * 32;    // warp m offset in tile
    const int wn   = (warp & 1)  * 64;    // warp n offset in tile
    const int qr   = lane >> 2;           // 0..7
    const int qc   = lane & 3;            // 0..3

    const int bm = blockIdx.y * 128;
    const int bn = blockIdx.x * 128;

    const int lm = tid >> 2;              // 0..63 : row within tile for gmem load
    const int lk = (tid & 3) * 4;         // k offset of the float4

    const float* Ap = A  + (size_t)(bm + lm) * K + lk;
    const float* Bp = Bm + (size_t)(bn + lm) * K + lk;

    float acc[2][8][4];
#pragma unroll
    for (int mt = 0; mt < 2; mt++)
#pragma unroll
        for (int nt = 0; nt < 8; nt++)
#pragma unroll
            for (int c = 0; c < 4; c++) acc[mt][nt][c] = 0.f;

    float4 pa0 = *(const float4*)Ap;
    float4 pa1 = *(const float4*)(Ap + (size_t)64 * K);
    float4 pb0 = *(const float4*)Bp;
    float4 pb1 = *(const float4*)(Bp + (size_t)64 * K);

    // store tile 0 into buffer 0 (converted to tf32)
    As[0][lk+0][lm]    = f2tf32(pa0.x); As[0][lk+1][lm]    = f2tf32(pa0.y);
    As[0][lk+2][lm]    = f2tf32(pa0.z); As[0][lk+3][lm]    = f2tf32(pa0.w);
    As[0][lk+0][lm+64] = f2tf32(pa1.x); As[0][lk+1][lm+64] = f2tf32(pa1.y);
    As[0][lk+2][lm+64] = f2tf32(pa1.z); As[0][lk+3][lm+64] = f2tf32(pa1.w);
    Bs[0][lk+0][lm]    = f2tf32(pb0.x); Bs[0][lk+1][lm]    = f2tf32(pb0.y);
    Bs[0][lk+2][lm]    = f2tf32(pb0.z); Bs[0][lk+3][lm]    = f2tf32(pb0.w);
    Bs[0][lk+0][lm+64] = f2tf32(pb1.x); Bs[0][lk+1][lm+64] = f2tf32(pb1.y);
    Bs[0][lk+2][lm+64] = f2tf32(pb1.z); Bs[0][lk+3][lm+64] = f2tf32(pb1.w);
    __syncthreads();

    const int KT = K >> 4;
    for (int kt = 0; kt < KT; ++kt) {
        const int buf = kt & 1;
        if (kt + 1 < KT) {
            const float* Ap2 = Ap + (kt + 1) * 16;
            const float* Bp2 = Bp + (kt + 1) * 16;
            pa0 = *(const float4*)Ap2;
            pa1 = *(const float4*)(Ap2 + (size_t)64 * K);
            pb0 = *(const float4*)Bp2;
            pb1 = *(const float4*)(Bp2 + (size_t)64 * K);
        }
#pragma unroll
        for (int ks = 0; ks < 16; ks += 8) {
            uint32_t af[2][4], bf[8][2];
#pragma unroll
            for (int mt = 0; mt < 2; mt++) {
                const int row = wm + mt*16 + qr;
                af[mt][0] = As[buf][ks+qc  ][row];
                af[mt][1] = As[buf][ks+qc  ][row+8];
                af[mt][2] = As[buf][ks+qc+4][row];
                af[mt][3] = As[buf][ks+qc+4][row+8];
            }
#pragma unroll
            for (int nt = 0; nt < 8; nt++) {
                const int col = wn + nt*8 + qr;
                bf[nt][0] = Bs[buf][ks+qc  ][col];
                bf[nt][1] = Bs[buf][ks+qc+4][col];
            }
#pragma unroll
            for (int mt = 0; mt < 2; mt++)
#pragma unroll
                for (int nt = 0; nt < 8; nt++) {
                    asm volatile(
                        "mma.sync.aligned.m16n8k8.row.col.f32.tf32.tf32.f32 "
                        "{%0,%1,%2,%3}, {%4,%5,%6,%7}, {%8,%9}, {%0,%1,%2,%3};"
                        : "+f"(acc[mt][nt][0]), "+f"(acc[mt][nt][1]),
                          "+f"(acc[mt][nt][2]), "+f"(acc[mt][nt][3])
                        : "r"(af[mt][0]), "r"(af[mt][1]),
                          "r"(af[mt][2]), "r"(af[mt][3]),
                          "r"(bf[nt][0]), "r"(bf[nt][1]));
                }
        }
        if (kt + 1 < KT) {
            const int nb = buf ^ 1;
            As[nb][lk+0][lm]    = f2tf32(pa0.x); As[nb][lk+1][lm]    = f2tf32(pa0.y);
            As[nb][lk+2][lm]    = f2tf32(pa0.z); As[nb][lk+3][lm]    = f2tf32(pa0.w);
            As[nb][lk+0][lm+64] = f2tf32(pa1.x); As[nb][lk+1][lm+64] = f2tf32(pa1.y);
            As[nb][lk+2][lm+64] = f2tf32(pa1.z); As[nb][lk+3][lm+64] = f2tf32(pa1.w);
            Bs[nb][lk+0][lm]    = f2tf32(pb0.x); Bs[nb][lk+1][lm]    = f2tf32(pb0.y);
            Bs[nb][lk+2][lm]    = f2tf32(pb0.z); Bs[nb][lk+3][lm]    = f2tf32(pb0.w);
            Bs[nb][lk+0][lm+64] = f2tf32(pb1.x); Bs[nb][lk+1][lm+64] = f2tf32(pb1.y);
            Bs[nb][lk+2][lm+64] = f2tf32(pb1.z); Bs[nb][lk+3][lm+64] = f2tf32(pb1.w);
            __syncthreads();
        }
    }

    // epilogue: c0/c1 at (row, 2qc/2qc+1), c2/c3 at (row+8, same)
#pragma unroll
    for (int mt = 0; mt < 2; mt++) {
        const int r0 = bm + wm + mt*16 + qr;
#pragma unroll
        for (int nt = 0; nt < 8; nt++) {
            const int c0 = bn + wn + nt*8 + 2*qc;
            float v0 = acc[mt][nt][0], v1 = acc[mt][nt][1];
            float v2 = acc[mt][nt][2], v3 = acc[mt][nt][3];
            if (BIAS) {
                const float b0 = __ldg(bias + c0), b1 = __ldg(bias + c0 + 1);
                v0 += b0; v1 += b1; v2 += b0; v3 += b1;
            }
            *(float2*)(C + (size_t)r0       * N + c0) = make_float2(v0, v1);
            *(float2*)(C + (size_t)(r0 + 8) * N + c0) = make_float2(v2, v3);
        }
    }
}

// =====================================================================
// Feature map: per chunk, qp/kp[s][f] = exp( (t*scale)·proj_f - rowmax )
// block = one (chunk, q/k) pair. 512 threads, 8x8 microtile over [128 s][256 f]
// Also computes ksum[f] (k only).
// =====================================================================
__global__ __launch_bounds__(512, 1)
void feature_kernel(const float* __restrict__ proj)
{
    extern __shared__ float sm[];
    float* as  = sm;                 // [64][132]  A^T : [k][s]
    float* pt  = sm + 64*132;        // [64][256]  proj^T : [k][f]
    float* red = pt + 64*256;        // [16][256]  ksum partials

    const int cid = blockIdx.x;           // 0..1023
    const int isK = blockIdx.y;           // 0 = q, 1 = k
    const int b  = cid >> 8;
    const int h  = (cid >> 5) & 7;
    const int cc = cid & 31;
    const size_t row0   = (size_t)b * SEQ + (size_t)cc * CSZ;  // token row in [0,16384)
    const int   colbase = isK * DIMM + h * DHD;
    const float scale   = isK ? 1.0f : 0.125f;   // DH^-0.5 applied to q only
    const int tid = threadIdx.x;

    // load chunk rows [128][64] -> as[k][s] (scaled)
#pragma unroll
    for (int it = 0; it < 4; ++it) {
        const int f4 = it * 512 + tid;        // 0..2047
        const int s  = f4 >> 4;
        const int d  = (f4 & 15) * 4;
        float4 v = *(const float4*)(g_qkv + (row0 + s) * QKVN + colbase + d);
        as[(d+0)*132 + s] = v.x * scale;
        as[(d+1)*132 + s] = v.y * scale;
        as[(d+2)*132 + s] = v.z * scale;
        as[(d+3)*132 + s] = v.w * scale;
    }
    // load proj [256][64] -> pt[k][f]
#pragma unroll
    for (int it = 0; it < 8; ++it) {
        const int f4 = it * 512 + tid;        // 0..4095
        const int f  = f4 >> 4;
        const int d  = (f4 & 15) * 4;
        float4 v = *(const float4*)(proj + f * DHD + d);
        pt[(d+0)*256 + f] = v.x;
        pt[(d+1)*256 + f] = v.y;
        pt[(d+2)*256 + f] = v.z;
        pt[(d+3)*256 + f] = v.w;
    }
    __syncthreads();

    const int ft = tid & 31;   // f = ft + 32*j   (lanes = f direction)
    const int st = tid >> 5;   // s = st + 16*i
    float acc[8][8];
#pragma unroll
    for (int i = 0; i < 8; i++)
#pragma unroll
        for (int j = 0; j < 8; j++) acc[i][j] = 0.f;

    for (int k = 0; k < 64; ++k) {
        float a[8], bb[8];
#pragma unroll
        for (int i = 0; i < 8; i++) a[i]  = as[k*132 + st + 16*i];
#pragma unroll
        for (int j = 0; j < 8; j++) bb[j] = pt[k*256 + ft + 32*j];
#pragma unroll
        for (int i = 0; i < 8; i++)
#pragma unroll
            for (int j = 0; j < 8; j++)
                acc[i][j] = fmaf(a[i], bb[j], acc[i][j]);
    }

    float* outp = isK ? g_kp : g_qp;
    const size_t obase = ((size_t)(b*NH + h) * SEQ + (size_t)cc * CSZ) * NF;
    float psum[8];
#pragma unroll
    for (int j = 0; j < 8; j++) psum[j] = 0.f;

#pragma unroll
    for (int i = 0; i < 8; i++) {
        float m = acc[i][0];
#pragma unroll
        for (int j = 1; j < 8; j++) m = fmaxf(m, acc[i][j]);
#pragma unroll
        for (int off = 16; off > 0; off >>= 1)
            m = fmaxf(m, __shfl_xor_sync(0xffffffffu, m, off));
        const int s = st + 16*i;
#pragma unroll
        for (int j = 0; j < 8; j++) {
            const float e = __expf(acc[i][j] - m);
            outp[obase + (size_t)s * NF + ft + 32*j] = e;
            psum[j] += e;
        }
    }

    if (isK) {
#pragma unroll
        for (int j = 0; j < 8; j++) red[st*256 + ft + 32*j] = psum[j];
        __syncthreads();
        if (tid < NF) {
            float ssum = 0.f;
#pragma unroll
            for (int r = 0; r < 16; r++) ssum += red[r*256 + tid];
            g_ksum[(size_t)cid * NF + tid] = ssum;
        }
    }
}

// =====================================================================
// Context: per chunk, ctx[f][d] = sum_s kp[s][f] * v[s][d]   (256x64x128)
// 256 threads, 8x8 microtile.
// =====================================================================
__global__ __launch_bounds__(256, 1)
void ctx_kernel()
{
    extern __shared__ float sm[];
    float* kps = sm;                // [128][256]
    float* vs  = sm + CSZ * NF;     // [128][64]

    const int cid = blockIdx.x;
    const int b  = cid >> 8;
    const int h  = (cid >> 5) & 7;
    const int cc = cid & 31;
    const size_t row0   = (size_t)b * SEQ + (size_t)cc * CSZ;
    const size_t kpbase = ((size_t)(b*NH + h) * SEQ + (size_t)cc * CSZ) * NF;
    const int vcol = 2 * DIMM + h * DHD;
    const int tid = threadIdx.x;

#pragma unroll
    for (int it = 0; it < 32; ++it) {
        const int f4 = it * 256 + tid;        // 0..8191
        *(float4*)(kps + (size_t)f4 * 4) =
            *(const float4*)(g_kp + kpbase + (size_t)f4 * 4);
    }
#pragma unroll
    for (int it = 0; it < 8; ++it) {
        const int f4 = it * 256 + tid;        // 0..2047
        const int s  = f4 >> 4;
        const int d  = (f4 & 15) * 4;
        *(float4*)(vs + s*64 + d) =
            *(const float4*)(g_qkv + (row0 + s) * QKVN + vcol + d);
    }
    __syncthreads();

    const int ftid = tid >> 3;   // 0..31 : f = ftid + 32*j
    const int dtid = tid & 7;    // d = dtid + 8*i
    float acc[8][8];
#pragma unroll
    for (int j = 0; j < 8; j++)
#pragma unroll
        for (int i = 0; i < 8; i++) acc[j][i] = 0.f;

    for (int s = 0; s < CSZ; ++s) {
        float kf[8], vv[8];
#pragma unroll
        for (int j = 0; j < 8; j++) kf[j] = kps[s*NF + ftid + 32*j];
#pragma unroll
        for (int i = 0; i < 8; i++) vv[i] = vs[s*DHD + dtid + 8*i];
#pragma unroll
        for (int j = 0; j < 8; j++)
#pragma unroll
            for (int i = 0; i < 8; i++)
                acc[j][i] = fmaf(kf[j], vv[i], acc[j][i]);
    }

    float* cb = g_ctx + (size_t)cid * NF * DHD;
#pragma unroll
    for (int j = 0; j < 8; j++)
#pragma unroll
        for (int i = 0; i < 8; i++)
            cb[(ftid + 32*j) * DHD + dtid + 8*i] = acc[j][i];
}

// =====================================================================
// Output: per chunk, D[s] = qp[s]·ksum ; out[s][d] = (qp[s]·ctx[:,d]) / (D+1e-4)
// 256 threads, 4s x 8d microtile; writes att[t][h*64+d].
// =====================================================================
#define QPLD 261   // padded leading dim (gcd(5,32)=1 -> conflict-free)
__global__ __launch_bounds__(256, 1)
void out_kernel()
{
    extern __shared__ float sm[];
    float* qps  = sm;                      // [128][261]
    float* ctxs = sm + CSZ * QPLD;         // [256][64]
    float* ks   = ctxs + NF * DHD;         // [256]

    const int cid = blockIdx.x;
    const int b  = cid >> 8;
    const int h  = (cid >> 5) & 7;
    const int cc = cid & 31;
    const size_t row0   = (size_t)b * SEQ + (size_t)cc * CSZ;
    const size_t qpbase = ((size_t)(b*NH + h) * SEQ + (size_t)cc * CSZ) * NF;
    const int tid = threadIdx.x;

#pragma unroll
    for (int it = 0; it < 32; ++it) {
        const int f4 = it * 256 + tid;        // 0..8191
        const int s  = f4 >> 6;
        const int c  = (f4 & 63) * 4;
        float4 v = *(const float4*)(g_qp + qpbase + (size_t)s * NF + c);
        qps[s*QPLD + c + 0] = v.x;
        qps[s*QPLD + c + 1] = v.y;
        qps[s*QPLD + c + 2] = v.z;
        qps[s*QPLD + c + 3] = v.w;
    }
#pragma unroll
    for (int it = 0; it < 16; ++it) {
        const int f4 = it * 256 + tid;        // 0..4095
        *(float4*)(ctxs + (size_t)f4 * 4) =
            *(const float4*)(g_ctx + (size_t)cid * NF * DHD + (size_t)f4 * 4);
    }
    if (tid < NF) ks[tid] = g_ksum[(size_t)cid * NF + tid];
    __syncthreads();

    const int stid = tid & 31;    // s = stid + 32*i
    const int dt   = tid >> 5;    // 0..7 : d = dt*8 + l
    float acc[4][8];
    float Dacc[4];
#pragma unroll
    for (int i = 0; i < 4; i++) {
        Dacc[i] = 0.f;
#pragma unroll
        for (int l = 0; l < 8; l++) acc[i][l] = 0.f;
    }

    for (int f = 0; f < NF; ++f) {
        const float kk = ks[f];
        const float4 c0 = *(const float4*)(ctxs + f*DHD + dt*8);
        const float4 c1 = *(const float4*)(ctxs + f*DHD + dt*8 + 4);
#pragma unroll
        for (int i = 0; i < 4; i++) {
            const float qv = qps[(stid + 32*i) * QPLD + f];
            Dacc[i]  = fmaf(qv, kk,   Dacc[i]);
            acc[i][0] = fmaf(qv, c0.x, acc[i][0]);
            acc[i][1] = fmaf(qv, c0.y, acc[i][1]);
            acc[i][2] = fmaf(qv, c0.z, acc[i][2]);
            acc[i][3] = fmaf(qv, c0.w, acc[i][3]);
            acc[i][4] = fmaf(qv, c1.x, acc[i][4]);
            acc[i][5] = fmaf(qv, c1.y, acc[i][5]);
            acc[i][6] = fmaf(qv, c1.z, acc[i][6]);
            acc[i][7] = fmaf(qv, c1.w, acc[i][7]);
        }
    }

#pragma unroll
    for (int i = 0; i < 4; i++) {
        const float dinv = 1.0f / (Dacc[i] + 1e-4f);
        const int s = stid + 32*i;
        float* op = g_att + (row0 + s) * DIMM + h * DHD + dt * 8;
        float4 o0 = make_float4(acc[i][0]*dinv, acc[i][1]*dinv,
                                acc[i][2]*dinv, acc[i][3]*dinv);
        float4 o1 = make_float4(acc[i][4]*dinv, acc[i][5]*dinv,
                                acc[i][6]*dinv, acc[i][7]*dinv);
        *(float4*)op       = o0;
        *(float4*)(op + 4) = o1;
    }
}

// =====================================================================
// launch
// =====================================================================
extern "C" void kernel_launch(void* const* d_in, const int* in_sizes, int n_in,
                              void* d_out, int out_size)
{
    const float *x = nullptr, *wqkv = nullptr, *wout = nullptr,
                *bout = nullptr, *proj = nullptr;
    for (int i = 0; i < n_in; i++) {
        switch (in_sizes[i]) {
            case MTOK * DIMM:  x    = (const float*)d_in[i]; break; // 8388608
            case QKVN * DIMM:  wqkv = (const float*)d_in[i]; break; // 786432
            case DIMM * DIMM:  wout = (const float*)d_in[i]; break; // 262144
            case DIMM:         bout = (const float*)d_in[i]; break; // 512
            case NF * DHD:     proj = (const float*)d_in[i]; break; // 16384
        }
    }

    const int FEAT_SMEM = (64*132 + 64*256 + 16*256) * 4;      // 115712
    const int CTX_SMEM  = (CSZ*NF + CSZ*DHD) * 4;              // 163840
    const int OUT_SMEM  = (CSZ*QPLD + NF*DHD + NF) * 4;        // 200192
    cudaFuncSetAttribute(feature_kernel, cudaFuncAttributeMaxDynamicSharedMemorySize, FEAT_SMEM);
    cudaFuncSetAttribute(ctx_kernel,     cudaFuncAttributeMaxDynamicSharedMemorySize, CTX_SMEM);
    cudaFuncSetAttribute(out_kernel,     cudaFuncAttributeMaxDynamicSharedMemorySize, OUT_SMEM);

    float *qkvp = nullptr, *attp = nullptr;
    cudaGetSymbolAddress((void**)&qkvp, g_qkv);
    cudaGetSymbolAddress((void**)&attp, g_att);

    // 1) qkv = x @ w_qkv^T           [16384 x 1536 x 512]  (tf32 tensor cores)
    tgemm_nt<false><<<dim3(QKVN/128, MTOK/128), 256>>>(x, wqkv, nullptr, qkvp,
                                                       MTOK, QKVN, DIMM);
    // 2) q' and k' feature maps (+ ksum for k)
    feature_kernel<<<dim3(NCHUNK, 2), 512, FEAT_SMEM>>>(proj);
    // 3) ctx = k'^T v per chunk
    ctx_kernel<<<NCHUNK, 256, CTX_SMEM>>>();
    // 4) out = (q' @ ctx) * Dinv  -> att
    out_kernel<<<NCHUNK, 256, OUT_SMEM>>>();
    // 5) final = att @ w_out^T + b_out   (tf32 tensor cores)
    tgemm_nt<true><<<dim3(DIMM/128, MTOK/128), 256>>>(attp, wout, bout,
                                                      (float*)d_out,
                                                      MTOK, DIMM, DIMM);
}

// round 3
// speedup vs baseline: 1.8169x; 1.1717x over previous
#include <cuda_runtime.h>
#include <cstdint>

// ---------------- problem constants ----------------
#define NB   4
#define SEQ  4096
#define DIMM 512
#define NH   8
#define DHD  64
#define NF   256
#define CSZ  128
#define NCH  32
#define MTOK (NB*SEQ)            // 16384
#define QKVN (3*DIMM)            // 1536
#define NCHUNK (NB*NH*NCH)       // 1024

// ---------------- device scratch ----------------
__device__ float g_qkv [MTOK * QKVN];
__device__ float g_qp  [NB*NH*SEQ*NF];   // stored tf32-rounded
__device__ float g_kp  [NB*NH*SEQ*NF];   // stored tf32-rounded
__device__ float g_ksum[NCHUNK * NF];
__device__ float g_att [MTOK * DIMM];

__device__ __forceinline__ uint32_t f2tf32(float f) {
    uint32_t r;
    asm("cvt.rna.tf32.f32 %0, %1;" : "=r"(r) : "f"(f));
    return r;
}

__device__ __forceinline__ void mma_tf32(float acc[4],
                                         uint32_t a0, uint32_t a1, uint32_t a2, uint32_t a3,
                                         uint32_t b0, uint32_t b1)
{
    asm volatile(
        "mma.sync.aligned.m16n8k8.row.col.f32.tf32.tf32.f32 "
        "{%0,%1,%2,%3}, {%4,%5,%6,%7}, {%8,%9}, {%0,%1,%2,%3};"
        : "+f"(acc[0]), "+f"(acc[1]), "+f"(acc[2]), "+f"(acc[3])
        : "r"(a0), "r"(a1), "r"(a2), "r"(a3), "r"(b0), "r"(b1));
}

// =====================================================================
// TF32 tensor-core GEMM NT (unchanged from R2, correct+passing)
// =====================================================================
template<bool BIAS>
__global__ __launch_bounds__(256, 2)
void tgemm_nt(const float* __restrict__ A, const float* __restrict__ Bm,
              const float* __restrict__ bias, float* __restrict__ C,
              int M, int N, int K)
{
    __shared__ uint32_t As[2][16][136];
    __shared__ uint32_t Bs[2][16][136];

    const int tid  = threadIdx.x;
    const int lane = tid & 31;
    const int warp = tid >> 5;
    const int wm   = (warp >> 1) * 32;
    const int wn   = (warp & 1)  * 64;
    const int qr   = lane >> 2;
    const int qc   = lane & 3;

    const int bm = blockIdx.y * 128;
    const int bn = blockIdx.x * 128;

    const int lm = tid >> 2;
    const int lk = (tid & 3) * 4;

    const float* Ap = A  + (size_t)(bm + lm) * K + lk;
    const float* Bp = Bm + (size_t)(bn + lm) * K + lk;

    float acc[2][8][4];
#pragma unroll
    for (int mt = 0; mt < 2; mt++)
#pragma unroll
        for (int nt = 0; nt < 8; nt++)
#pragma unroll
            for (int c = 0; c < 4; c++) acc[mt][nt][c] = 0.f;

    float4 pa0 = *(const float4*)Ap;
    float4 pa1 = *(const float4*)(Ap + (size_t)64 * K);
    float4 pb0 = *(const float4*)Bp;
    float4 pb1 = *(const float4*)(Bp + (size_t)64 * K);

    As[0][lk+0][lm]    = f2tf32(pa0.x); As[0][lk+1][lm]    = f2tf32(pa0.y);
    As[0][lk+2][lm]    = f2tf32(pa0.z); As[0][lk+3][lm]    = f2tf32(pa0.w);
    As[0][lk+0][lm+64] = f2tf32(pa1.x); As[0][lk+1][lm+64] = f2tf32(pa1.y);
    As[0][lk+2][lm+64] = f2tf32(pa1.z); As[0][lk+3][lm+64] = f2tf32(pa1.w);
    Bs[0][lk+0][lm]    = f2tf32(pb0.x); Bs[0][lk+1][lm]    = f2tf32(pb0.y);
    Bs[0][lk+2][lm]    = f2tf32(pb0.z); Bs[0][lk+3][lm]    = f2tf32(pb0.w);
    Bs[0][lk+0][lm+64] = f2tf32(pb1.x); Bs[0][lk+1][lm+64] = f2tf32(pb1.y);
    Bs[0][lk+2][lm+64] = f2tf32(pb1.z); Bs[0][lk+3][lm+64] = f2tf32(pb1.w);
    __syncthreads();

    const int KT = K >> 4;
    for (int kt = 0; kt < KT; ++kt) {
        const int buf = kt & 1;
        if (kt + 1 < KT) {
            const float* Ap2 = Ap + (kt + 1) * 16;
            const float* Bp2 = Bp + (kt + 1) * 16;
            pa0 = *(const float4*)Ap2;
            pa1 = *(const float4*)(Ap2 + (size_t)64 * K);
            pb0 = *(const float4*)Bp2;
            pb1 = *(const float4*)(Bp2 + (size_t)64 * K);
        }
#pragma unroll
        for (int ks = 0; ks < 16; ks += 8) {
            uint32_t af[2][4], bf[8][2];
#pragma unroll
            for (int mt = 0; mt < 2; mt++) {
                const int row = wm + mt*16 + qr;
                af[mt][0] = As[buf][ks+qc  ][row];
                af[mt][1] = As[buf][ks+qc  ][row+8];
                af[mt][2] = As[buf][ks+qc+4][row];
                af[mt][3] = As[buf][ks+qc+4][row+8];
            }
#pragma unroll
            for (int nt = 0; nt < 8; nt++) {
                const int col = wn + nt*8 + qr;
                bf[nt][0] = Bs[buf][ks+qc  ][col];
                bf[nt][1] = Bs[buf][ks+qc+4][col];
            }
#pragma unroll
            for (int mt = 0; mt < 2; mt++)
#pragma unroll
                for (int nt = 0; nt < 8; nt++)
                    mma_tf32(acc[mt][nt], af[mt][0], af[mt][1], af[mt][2], af[mt][3],
                             bf[nt][0], bf[nt][1]);
        }
        if (kt + 1 < KT) {
            const int nb = buf ^ 1;
            As[nb][lk+0][lm]    = f2tf32(pa0.x); As[nb][lk+1][lm]    = f2tf32(pa0.y);
            As[nb][lk+2][lm]    = f2tf32(pa0.z); As[nb][lk+3][lm]    = f2tf32(pa0.w);
            As[nb][lk+0][lm+64] = f2tf32(pa1.x); As[nb][lk+1][lm+64] = f2tf32(pa1.y);
            As[nb][lk+2][lm+64] = f2tf32(pa1.z); As[nb][lk+3][lm+64] = f2tf32(pa1.w);
            Bs[nb][lk+0][lm]    = f2tf32(pb0.x); Bs[nb][lk+1][lm]    = f2tf32(pb0.y);
            Bs[nb][lk+2][lm]    = f2tf32(pb0.z); Bs[nb][lk+3][lm]    = f2tf32(pb0.w);
            Bs[nb][lk+0][lm+64] = f2tf32(pb1.x); Bs[nb][lk+1][lm+64] = f2tf32(pb1.y);
            Bs[nb][lk+2][lm+64] = f2tf32(pb1.z); Bs[nb][lk+3][lm+64] = f2tf32(pb1.w);
            __syncthreads();
        }
    }

#pragma unroll
    for (int mt = 0; mt < 2; mt++) {
        const int r0 = bm + wm + mt*16 + qr;
#pragma unroll
        for (int nt = 0; nt < 8; nt++) {
            const int c0 = bn + wn + nt*8 + 2*qc;
            float v0 = acc[mt][nt][0], v1 = acc[mt][nt][1];
            float v2 = acc[mt][nt][2], v3 = acc[mt][nt][3];
            if (BIAS) {
                const float b0 = __ldg(bias + c0), b1 = __ldg(bias + c0 + 1);
                v0 += b0; v1 += b1; v2 += b0; v3 += b1;
            }
            *(float2*)(C + (size_t)r0       * N + c0) = make_float2(v0, v1);
            *(float2*)(C + (size_t)(r0 + 8) * N + c0) = make_float2(v2, v3);
        }
    }
}

// =====================================================================
// Feature kernel, tensor-core 3xTF32:
//   S = (t*scale) @ proj^T   [128 x 256 x 64]  (hi/lo compensated)
//   out = exp(S - rowmax(S)) (tf32-rounded), ksum for k.
// 256 threads = 8 warps: 4 m-groups (32 rows) x 2 f-groups (128 f).
// =====================================================================
// smem (u32 units):
//  AH  @ 0       [64][136]  = 8704
//  AL  @ 8704    [64][136]  = 8704      -> 17408
//  PH  @ 17408   [64][264]  = 16896     -> 34304
//  PL  @ 34304   [64][264]  = 16896     -> 51200
//  (sm_e aliases PH/PL region: float [128][260] = 33280 @ 17408)
//  RMAX@ 51200   [2][128]   = 256       -> 51456
#define FEAT_SMEM_BYTES (51456 * 4)

__global__ __launch_bounds__(256, 1)
void feature_mma(const float* __restrict__ proj)
{
    extern __shared__ uint32_t smu[];
    uint32_t* AH = smu;
    uint32_t* AL = smu + 8704;
    uint32_t* PH = smu + 17408;
    uint32_t* PL = smu + 34304;
    float*    sm_e = (float*)(smu + 17408);     // alias (after MMA phase)
    float*    RMAX = (float*)(smu + 51200);

    const int cid = blockIdx.x;
    const int isK = blockIdx.y;
    const int b  = cid >> 8;
    const int h  = (cid >> 5) & 7;
    const int cc = cid & 31;
    const size_t row0   = (size_t)b * SEQ + (size_t)cc * CSZ;
    const int   colbase = isK * DIMM + h * DHD;
    const float scale   = isK ? 1.0f : 0.125f;
    const int tid  = threadIdx.x;
    const int lane = tid & 31;
    const int warp = tid >> 5;
    const int wgm  = warp >> 1;     // 0..3  (m rows 32 each)
    const int fg   = warp & 1;      // 0..1  (f cols 128 each)
    const int qr   = lane >> 2;
    const int qc   = lane & 3;

    // load t chunk [128 s][64 d] -> AH/AL [d][136] (transposed), scaled, split
#pragma unroll
    for (int it = 0; it < 8; ++it) {
        const int idx4 = it * 256 + tid;          // 0..2047
        const int s  = idx4 >> 4;
        const int d  = (idx4 & 15) * 4;
        float4 v = *(const float4*)(g_qkv + (row0 + s) * QKVN + colbase + d);
        float f0 = v.x * scale, f1 = v.y * scale, f2 = v.z * scale, f3 = v.w * scale;
        uint32_t h0 = f2tf32(f0), h1 = f2tf32(f1), h2 = f2tf32(f2), h3 = f2tf32(f3);
        AH[(d+0)*136 + s] = h0; AL[(d+0)*136 + s] = f2tf32(f0 - __uint_as_float(h0));
        AH[(d+1)*136 + s] = h1; AL[(d+1)*136 + s] = f2tf32(f1 - __uint_as_float(h1));
        AH[(d+2)*136 + s] = h2; AL[(d+2)*136 + s] = f2tf32(f2 - __uint_as_float(h2));
        AH[(d+3)*136 + s] = h3; AL[(d+3)*136 + s] = f2tf32(f3 - __uint_as_float(h3));
    }
    // load proj [256 f][64 d] -> PH/PL [d][264]
#pragma unroll
    for (int it = 0; it < 16; ++it) {
        const int idx4 = it * 256 + tid;          // 0..4095
        const int f  = idx4 >> 4;
        const int d  = (idx4 & 15) * 4;
        float4 v = *(const float4*)(proj + f * DHD + d);
        uint32_t h0 = f2tf32(v.x), h1 = f2tf32(v.y), h2 = f2tf32(v.z), h3 = f2tf32(v.w);
        PH[(d+0)*264 + f] = h0; PL[(d+0)*264 + f] = f2tf32(v.x - __uint_as_float(h0));
        PH[(d+1)*264 + f] = h1; PL[(d+1)*264 + f] = f2tf32(v.y - __uint_as_float(h1));
        PH[(d+2)*264 + f] = h2; PL[(d+2)*264 + f] = f2tf32(v.z - __uint_as_float(h2));
        PH[(d+3)*264 + f] = h3; PL[(d+3)*264 + f] = f2tf32(v.w - __uint_as_float(h3));
    }
    __syncthreads();

    float acc[2][16][4];
#pragma unroll
    for (int mt = 0; mt < 2; mt++)
#pragma unroll
        for (int nt = 0; nt < 16; nt++)
#pragma unroll
            for (int c = 0; c < 4; c++) acc[mt][nt][c] = 0.f;

#pragma unroll
    for (int ks = 0; ks < 8; ++ks) {
        const int k0 = ks * 8;
        uint32_t ah[2][4], al[2][4];
#pragma unroll
        for (int mt = 0; mt < 2; mt++) {
            const int row = wgm*32 + mt*16 + qr;
            const int i0 = (k0+qc)*136 + row;
            const int i1 = (k0+qc+4)*136 + row;
            ah[mt][0] = AH[i0]; ah[mt][1] = AH[i0+8];
            ah[mt][2] = AH[i1]; ah[mt][3] = AH[i1+8];
            al[mt][0] = AL[i0]; al[mt][1] = AL[i0+8];
            al[mt][2] = AL[i1]; al[mt][3] = AL[i1+8];
        }
#pragma unroll
        for (int nt = 0; nt < 16; nt++) {
            const int col = fg*128 + nt*8 + qr;
            const uint32_t bh0 = PH[(k0+qc)*264 + col];
            const uint32_t bh1 = PH[(k0+qc+4)*264 + col];
            const uint32_t bl0 = PL[(k0+qc)*264 + col];
            const uint32_t bl1 = PL[(k0+qc+4)*264 + col];
#pragma unroll
            for (int mt = 0; mt < 2; mt++) {
                mma_tf32(acc[mt][nt], ah[mt][0], ah[mt][1], ah[mt][2], ah[mt][3], bh0, bh1);
                mma_tf32(acc[mt][nt], ah[mt][0], ah[mt][1], ah[mt][2], ah[mt][3], bl0, bl1);
                mma_tf32(acc[mt][nt], al[mt][0], al[mt][1], al[mt][2], al[mt][3], bh0, bh1);
            }
        }
    }

    // rowmax: per-thread partial over (nt, 2 cols), then qc-shuffle, then 2 f-warps via smem
    float mloc[2][2];
#pragma unroll
    for (int mt = 0; mt < 2; mt++)
#pragma unroll
        for (int hh = 0; hh < 2; hh++) {
            float m = -1e30f;
#pragma unroll
            for (int nt = 0; nt < 16; nt++) {
                m = fmaxf(m, acc[mt][nt][hh*2+0]);
                m = fmaxf(m, acc[mt][nt][hh*2+1]);
            }
            m = fmaxf(m, __shfl_xor_sync(0xffffffffu, m, 1));
            m = fmaxf(m, __shfl_xor_sync(0xffffffffu, m, 2));
            mloc[mt][hh] = m;
        }
    if (qc == 0) {
#pragma unroll
        for (int mt = 0; mt < 2; mt++)
#pragma unroll
            for (int hh = 0; hh < 2; hh++)
                RMAX[fg*128 + wgm*32 + mt*16 + hh*8 + qr] = mloc[mt][hh];
    }
    __syncthreads();   // also fences MMA-phase smem reads before sm_e aliasing

    float rm[2][2];
#pragma unroll
    for (int mt = 0; mt < 2; mt++)
#pragma unroll
        for (int hh = 0; hh < 2; hh++) {
            const int row = wgm*32 + mt*16 + hh*8 + qr;
            rm[mt][hh] = fmaxf(RMAX[row], RMAX[128 + row]);
        }

    // exp + tf32-round, stage into sm_e[row][260]
#pragma unroll
    for (int mt = 0; mt < 2; mt++)
#pragma unroll
        for (int hh = 0; hh < 2; hh++) {
            const int row = wgm*32 + mt*16 + hh*8 + qr;
#pragma unroll
            for (int nt = 0; nt < 16; nt++) {
                const int f = fg*128 + nt*8 + 2*qc;
                float e0 = __expf(acc[mt][nt][hh*2+0] - rm[mt][hh]);
                float e1 = __expf(acc[mt][nt][hh*2+1] - rm[mt][hh]);
                sm_e[row*260 + f]     = __uint_as_float(f2tf32(e0));
                sm_e[row*260 + f + 1] = __uint_as_float(f2tf32(e1));
            }
        }
    __syncthreads();

    // coalesced global store
    float* outp = isK ? g_kp : g_qp;
    const size_t obase = ((size_t)(b*NH + h) * SEQ + (size_t)cc * CSZ) * NF;
#pragma unroll
    for (int it = 0; it < 32; ++it) {
        const int idx4 = it * 256 + tid;        // 0..8191
        const int r  = idx4 >> 6;
        const int c4 = (idx4 & 63) * 4;
        float4 v;
        v.x = sm_e[r*260 + c4 + 0];
        v.y = sm_e[r*260 + c4 + 1];
        v.z = sm_e[r*260 + c4 + 2];
        v.w = sm_e[r*260 + c4 + 3];
        *(float4*)(outp + obase + (size_t)r * NF + c4) = v;
    }
    if (isK && tid < NF) {
        float s = 0.f;
#pragma unroll 8
        for (int r = 0; r < CSZ; ++r) s += sm_e[r*260 + tid];
        g_ksum[(size_t)cid * NF + tid] = s;
    }
}

// =====================================================================
// Fused ctx + out kernel (per chunk), tf32 tensor cores.
// P1: ctx[f][d] = sum_s k'[s][f] v[s][d]      M=256 N=64 K=128
// P2: out[s][d] = (sum_f q'[s][f] ctx[f][d]) / (q'[s]·ksum + 1e-4)
// 256 threads = 8 warps.
// =====================================================================
// smem (u32 units):
//  KB @ 0      [128][264] = 33792        (P1 k')
//  VB @ 33792  [128][72]  =  9216  -> 43008
//  CB @ 0      [256][72]  = 18432        (P2 ctx, aliases KB front)
//  QB @ 18432  [128][264] = 33792  -> 52224 (aliases KB tail + VB)
//  SK @ 52224  [256] floats -> 52480
//  DB @ 52480  [128] floats -> 52608
#define CO_SMEM_BYTES (52608 * 4)

__global__ __launch_bounds__(256, 1)
void ctx_out_mma()
{
    extern __shared__ uint32_t smu[];
    uint32_t* KB = smu;
    uint32_t* VB = smu + 33792;
    uint32_t* CB = smu;
    uint32_t* QB = smu + 18432;
    float*    SK = (float*)(smu + 52224);
    float*    DB = (float*)(smu + 52480);

    const int cid = blockIdx.x;
    const int b  = cid >> 8;
    const int h  = (cid >> 5) & 7;
    const int cc = cid & 31;
    const size_t row0   = (size_t)b * SEQ + (size_t)cc * CSZ;
    const size_t pbase  = ((size_t)(b*NH + h) * SEQ + (size_t)cc * CSZ) * NF;
    const int vcol = 2 * DIMM + h * DHD;
    const int tid  = threadIdx.x;
    const int lane = tid & 31;
    const int warp = tid >> 5;
    const int qr   = lane >> 2;
    const int qc   = lane & 3;

    // ---- load k' (already tf32-rounded floats; reinterpret bits) ----
#pragma unroll
    for (int it = 0; it < 32; ++it) {
        const int idx4 = it * 256 + tid;        // 0..8191
        const int r  = idx4 >> 6;
        const int c4 = (idx4 & 63) * 4;
        uint4 v = *(const uint4*)((const uint32_t*)g_kp + pbase + (size_t)r * NF + c4);
        *(uint4*)(KB + r*264 + c4) = v;
    }
    // ---- load v, convert to tf32 ----
#pragma unroll
    for (int it = 0; it < 8; ++it) {
        const int idx4 = it * 256 + tid;        // 0..2047
        const int s  = idx4 >> 4;
        const int d4 = (idx4 & 15) * 4;
        float4 v = *(const float4*)(g_qkv + (row0 + s) * QKVN + vcol + d4);
        uint4 u;
        u.x = f2tf32(v.x); u.y = f2tf32(v.y); u.z = f2tf32(v.z); u.w = f2tf32(v.w);
        *(uint4*)(VB + s*72 + d4) = u;
    }
    if (tid < NF) SK[tid] = g_ksum[(size_t)cid * NF + tid];
    __syncthreads();

    // ---- P1: ctx, warp w -> f rows [32w, 32w+32), mt(2) x nt(8 over d) ----
    {
        float acc[2][8][4];
#pragma unroll
        for (int mt = 0; mt < 2; mt++)
#pragma unroll
            for (int nt = 0; nt < 8; nt++)
#pragma unroll
                for (int c = 0; c < 4; c++) acc[mt][nt][c] = 0.f;

#pragma unroll 4
        for (int ks = 0; ks < 16; ++ks) {
            const int k0 = ks * 8;   // s index
            uint32_t af[2][4];
#pragma unroll
            for (int mt = 0; mt < 2; mt++) {
                const int fr = warp*32 + mt*16 + qr;
                const int i0 = (k0+qc)*264 + fr;
                const int i1 = (k0+qc+4)*264 + fr;
                af[mt][0] = KB[i0]; af[mt][1] = KB[i0+8];
                af[mt][2] = KB[i1]; af[mt][3] = KB[i1+8];
            }
#pragma unroll
            for (int nt = 0; nt < 8; nt++) {
                const int col = nt*8 + qr;
                const uint32_t b0 = VB[(k0+qc)*72 + col];
                const uint32_t b1 = VB[(k0+qc+4)*72 + col];
#pragma unroll
                for (int mt = 0; mt < 2; mt++)
                    mma_tf32(acc[mt][nt], af[mt][0], af[mt][1], af[mt][2], af[mt][3], b0, b1);
            }
        }
        __syncthreads();   // all P1 smem reads done before overwriting

        // store ctx (tf32) to CB [f][72]
#pragma unroll
        for (int mt = 0; mt < 2; mt++) {
            const int f0 = warp*32 + mt*16 + qr;
#pragma unroll
            for (int nt = 0; nt < 8; nt++) {
                const int col = nt*8 + 2*qc;
                uint2 u01 = make_uint2(f2tf32(acc[mt][nt][0]), f2tf32(acc[mt][nt][1]));
                uint2 u23 = make_uint2(f2tf32(acc[mt][nt][2]), f2tf32(acc[mt][nt][3]));
                *(uint2*)(CB + f0*72 + col)       = u01;
                *(uint2*)(CB + (f0+8)*72 + col)   = u23;
            }
        }
    }

    // ---- load q' into QB (parallel with ctx stores; disjoint regions) ----
#pragma unroll
    for (int it = 0; it < 32; ++it) {
        const int idx4 = it * 256 + tid;
        const int r  = idx4 >> 6;
        const int c4 = (idx4 & 63) * 4;
        uint4 v = *(const uint4*)((const uint32_t*)g_qp + pbase + (size_t)r * NF + c4);
        *(uint4*)(QB + r*264 + c4) = v;
    }
    __syncthreads();

    // ---- D[s] = q'[s] · ksum  (fp32), threads 0..127 ----
    if (tid < CSZ) {
        float s = 0.f;
        const uint32_t* qrow = QB + tid*264;
#pragma unroll 8
        for (int f = 0; f < NF; ++f)
            s = fmaf(__uint_as_float(qrow[f]), SK[f], s);
        DB[tid] = 1.0f / (s + 1e-4f);
    }

    // ---- P2: out = q' @ ctx, warps: 4 m-groups x 2 d-groups ----
    {
        const int mg = warp >> 1;     // 0..3
        const int ng = warp & 1;      // 0..1
        float acc[2][4][4];
#pragma unroll
        for (int mt = 0; mt < 2; mt++)
#pragma unroll
            for (int nt = 0; nt < 4; nt++)
#pragma unroll
                for (int c = 0; c < 4; c++) acc[mt][nt][c] = 0.f;

#pragma unroll 4
        for (int ks = 0; ks < 32; ++ks) {
            const int k0 = ks * 8;   // f index
            uint32_t af[2][4];
#pragma unroll
            for (int mt = 0; mt < 2; mt++) {
                const int row = mg*32 + mt*16 + qr;
                af[mt][0] = QB[row*264 + k0+qc];
                af[mt][1] = QB[(row+8)*264 + k0+qc];
                af[mt][2] = QB[row*264 + k0+qc+4];
                af[mt][3] = QB[(row+8)*264 + k0+qc+4];
            }
#pragma unroll
            for (int nt = 0; nt < 4; nt++) {
                const int col = ng*32 + nt*8 + qr;
                const uint32_t b0 = CB[(k0+qc)*72 + col];
                const uint32_t b1 = CB[(k0+qc+4)*72 + col];
#pragma unroll
                for (int mt = 0; mt < 2; mt++)
                    mma_tf32(acc[mt][nt], af[mt][0], af[mt][1], af[mt][2], af[mt][3], b0, b1);
            }
        }
        __syncthreads();   // DB visible

#pragma unroll
        for (int mt = 0; mt < 2; mt++) {
            const int r0 = mg*32 + mt*16 + qr;
            const float d0 = DB[r0];
            const float d1 = DB[r0 + 8];
#pragma unroll
            for (int nt = 0; nt < 4; nt++) {
                const int col = ng*32 + nt*8 + 2*qc;
                float* op0 = g_att + (row0 + r0)     * DIMM + h*DHD + col;
                float* op1 = g_att + (row0 + r0 + 8) * DIMM + h*DHD + col;
                *(float2*)op0 = make_float2(acc[mt][nt][0]*d0, acc[mt][nt][1]*d0);
                *(float2*)op1 = make_float2(acc[mt][nt][2]*d1, acc[mt][nt][3]*d1);
            }
        }
    }
}

// =====================================================================
// launch
// =====================================================================
extern "C" void kernel_launch(void* const* d_in, const int* in_sizes, int n_in,
                              void* d_out, int out_size)
{
    const float *x = nullptr, *wqkv = nullptr, *wout = nullptr,
                *bout = nullptr, *proj = nullptr;
    for (int i = 0; i < n_in; i++) {
        switch (in_sizes[i]) {
            case MTOK * DIMM:  x    = (const float*)d_in[i]; break;
            case QKVN * DIMM:  wqkv = (const float*)d_in[i]; break;
            case DIMM * DIMM:  wout = (const float*)d_in[i]; break;
            case DIMM:         bout = (const float*)d_in[i]; break;
            case NF * DHD:     proj = (const float*)d_in[i]; break;
        }
    }

    cudaFuncSetAttribute(feature_mma, cudaFuncAttributeMaxDynamicSharedMemorySize, FEAT_SMEM_BYTES);
    cudaFuncSetAttribute(ctx_out_mma, cudaFuncAttributeMaxDynamicSharedMemorySize, CO_SMEM_BYTES);

    float *qkvp = nullptr, *attp = nullptr;
    cudaGetSymbolAddress((void**)&qkvp, g_qkv);
    cudaGetSymbolAddress((void**)&attp, g_att);

    // 1) qkv = x @ w_qkv^T
    tgemm_nt<false><<<dim3(QKVN/128, MTOK/128), 256>>>(x, wqkv, nullptr, qkvp,
                                                       MTOK, QKVN, DIMM);
    // 2) q'/k' feature maps (3xTF32 tensor cores) + ksum
    feature_mma<<<dim3(NCHUNK, 2), 256, FEAT_SMEM_BYTES>>>(proj);
    // 3+4) fused ctx + out (tf32 tensor cores)
    ctx_out_mma<<<NCHUNK, 256, CO_SMEM_BYTES>>>();
    // 5) final = att @ w_out^T + b_out
    tgemm_nt<true><<<dim3(DIMM/128, MTOK/128), 256>>>(attp, wout, bout,
                                                      (float*)d_out,
                                                      MTOK, DIMM, DIMM);
}

// round 4
// speedup vs baseline: 1.9579x; 1.0776x over previous
#include <cuda_runtime.h>
#include <cstdint>

// ---------------- problem constants ----------------
#define NB   4
#define SEQ  4096
#define DIMM 512
#define NH   8
#define DHD  64
#define NF   256
#define CSZ  128
#define NCH  32
#define MTOK (NB*SEQ)            // 16384
#define QKVN (3*DIMM)            // 1536
#define NCHUNK (NB*NH*NCH)       // 1024

// ---------------- device scratch ----------------
__device__ float g_qkv [MTOK * QKVN];
__device__ float g_qp  [NB*NH*SEQ*NF];   // stored tf32-rounded
__device__ float g_kp  [NB*NH*SEQ*NF];   // stored tf32-rounded
__device__ float g_ksum[NCHUNK * NF];
__device__ float g_att [MTOK * DIMM];

__device__ __forceinline__ uint32_t f2tf32(float f) {
    uint32_t r;
    asm("cvt.rna.tf32.f32 %0, %1;" : "=r"(r) : "f"(f));
    return r;
}

__device__ __forceinline__ void mma_tf32(float acc[4],
                                         uint32_t a0, uint32_t a1, uint32_t a2, uint32_t a3,
                                         uint32_t b0, uint32_t b1)
{
    asm volatile(
        "mma.sync.aligned.m16n8k8.row.col.f32.tf32.tf32.f32 "
        "{%0,%1,%2,%3}, {%4,%5,%6,%7}, {%8,%9}, {%0,%1,%2,%3};"
        : "+f"(acc[0]), "+f"(acc[1]), "+f"(acc[2]), "+f"(acc[3])
        : "r"(a0), "r"(a1), "r"(a2), "r"(a3), "r"(b0), "r"(b1));
}

// =====================================================================
// TF32 tensor-core GEMM NT with packed-fragment smem.
//   C[m][n] = sum_k A[m][k]*B[n][k] (+bias[n])
// 128x128 tile, BK=16 (2 k-groups of 8), 256 threads (8 warps, 4m x 2n),
// warp tile 32(m) x 64(n).
//
// Packed layout (per buffer, per k-group kg):
//   A: [sub(8)][lane(32)] uint4  — lane L=(qr*4+qc) holds
//        {A[kg*8+qc][sub*16+qr], A[..][sub*16+qr+8],
//         A[kg*8+qc+4][sub*16+qr], A[..][sub*16+qr+8]}
//   B: [nsub(16)][lane(32)] uint2 — {B[kg*8+qc][nsub*8+qr], B[kg*8+qc+4][..]}
//   with lane-rotation swizzle: lane_stored = (qr<<2) | ((qc + (qr>>1) + 2*kg)&3)
//   (reader applies the same rotation -> STS scatter and LDS.128/64 reads
//    are both bank-conflict-free).
// =====================================================================
template<bool BIAS>
__global__ __launch_bounds__(256, 2)
void tgemm_nt(const float* __restrict__ A, const float* __restrict__ Bm,
              const float* __restrict__ bias, float* __restrict__ C,
              int M, int N, int K)
{
    __shared__ __align__(16) uint32_t Apk[2][2][8][128];    // [buf][kg][sub][lane*4+word]
    __shared__ __align__(16) uint32_t Bpk[2][2][16][64];    // [buf][kg][nsub][lane*2+word]

    const int tid  = threadIdx.x;
    const int lane = tid & 31;
    const int warp = tid >> 5;
    const int wsubA = (warp >> 1) * 2;    // A subtiles wsubA, wsubA+1 (32 rows)
    const int wsubB = (warp & 1)  * 8;    // B subtiles wsubB..wsubB+7 (64 cols)
    const int qr   = lane >> 2;
    const int qc   = lane & 3;

    const int bm = blockIdx.y * 128;
    const int bn = blockIdx.x * 128;

    // writer decomposition
    const int lm  = tid >> 2;             // 0..63 (row within half-tile)
    const int lk  = (tid & 3) * 4;        // k offset {0,4,8,12}
    const int wkg = lk >> 3;              // writer k-group (0/1)
    const int whi = (lk >> 2) & 1;        // writer hi (k>=4 within group)
    const int qrw   = lm & 7;
    const int half  = (lm >> 3) & 1;      // same for row lm and lm+64
    const int subA0 = lm >> 4;            // second rowset: +4
    const int nsub0 = lm >> 3;            // second rowset: +8
    const int wrot  = ((qrw >> 1) + 2 * wkg) & 3;
    const int wordA = whi * 2 + half;

    const float* Ap = A  + (size_t)(bm + lm) * K + lk;
    const float* Bp = Bm + (size_t)(bn + lm) * K + lk;

    float acc[2][8][4];
#pragma unroll
    for (int mt = 0; mt < 2; mt++)
#pragma unroll
        for (int nt = 0; nt < 8; nt++)
#pragma unroll
            for (int c = 0; c < 4; c++) acc[mt][nt][c] = 0.f;

    float4 pa0 = *(const float4*)Ap;
    float4 pa1 = *(const float4*)(Ap + (size_t)64 * K);
    float4 pb0 = *(const float4*)Bp;
    float4 pb1 = *(const float4*)(Bp + (size_t)64 * K);

    // stage a tile into buffer `bf`
    auto stage = [&](int bf, const float4& a0, const float4& a1,
                     const float4& b0, const float4& b1) {
        uint32_t* ad0 = &Apk[bf][wkg][subA0    ][0];
        uint32_t* ad1 = &Apk[bf][wkg][subA0 + 4][0];
        uint32_t* bd0 = &Bpk[bf][wkg][nsub0    ][0];
        uint32_t* bd1 = &Bpk[bf][wkg][nsub0 + 8][0];
        const float* av0 = &a0.x;
        const float* av1 = &a1.x;
        const float* bv0 = &b0.x;
        const float* bv1 = &b1.x;
#pragma unroll
        for (int j = 0; j < 4; ++j) {
            const int lp = ((qrw << 2) | ((j + wrot) & 3));
            ad0[lp*4 + wordA] = f2tf32(av0[j]);
            ad1[lp*4 + wordA] = f2tf32(av1[j]);
            bd0[lp*2 + whi]   = f2tf32(bv0[j]);
            bd1[lp*2 + whi]   = f2tf32(bv1[j]);
        }
    };

    stage(0, pa0, pa1, pb0, pb1);
    __syncthreads();

    const int KT = K >> 4;
    for (int kt = 0; kt < KT; ++kt) {
        const int buf = kt & 1;
        if (kt + 1 < KT) {
            const float* Ap2 = Ap + (kt + 1) * 16;
            const float* Bp2 = Bp + (kt + 1) * 16;
            pa0 = *(const float4*)Ap2;
            pa1 = *(const float4*)(Ap2 + (size_t)64 * K);
            pb0 = *(const float4*)Bp2;
            pb1 = *(const float4*)(Bp2 + (size_t)64 * K);
        }
#pragma unroll
        for (int kg = 0; kg < 2; ++kg) {
            const int rlane = ((qr << 2) | ((qc + (qr >> 1) + 2*kg) & 3));
            uint4 a0 = *(const uint4*)&Apk[buf][kg][wsubA    ][rlane*4];
            uint4 a1 = *(const uint4*)&Apk[buf][kg][wsubA + 1][rlane*4];
            uint2 bb[8];
#pragma unroll
            for (int nt = 0; nt < 8; nt++)
                bb[nt] = *(const uint2*)&Bpk[buf][kg][wsubB + nt][rlane*2];
#pragma unroll
            for (int nt = 0; nt < 8; nt++) {
                mma_tf32(acc[0][nt], a0.x, a0.y, a0.z, a0.w, bb[nt].x, bb[nt].y);
                mma_tf32(acc[1][nt], a1.x, a1.y, a1.z, a1.w, bb[nt].x, bb[nt].y);
            }
        }
        if (kt + 1 < KT) {
            stage(buf ^ 1, pa0, pa1, pb0, pb1);
            __syncthreads();
        }
    }

    // epilogue: c0/c1 at (row, 2qc/2qc+1), c2/c3 at (row+8, same)
#pragma unroll
    for (int mt = 0; mt < 2; mt++) {
        const int r0 = bm + (wsubA + mt) * 16 + qr;
#pragma unroll
        for (int nt = 0; nt < 8; nt++) {
            const int c0 = bn + (wsubB + nt) * 8 + 2*qc;
            float v0 = acc[mt][nt][0], v1 = acc[mt][nt][1];
            float v2 = acc[mt][nt][2], v3 = acc[mt][nt][3];
            if (BIAS) {
                const float b0 = __ldg(bias + c0), b1 = __ldg(bias + c0 + 1);
                v0 += b0; v1 += b1; v2 += b0; v3 += b1;
            }
            *(float2*)(C + (size_t)r0       * N + c0) = make_float2(v0, v1);
            *(float2*)(C + (size_t)(r0 + 8) * N + c0) = make_float2(v2, v3);
        }
    }
}

// =====================================================================
// Feature kernel, tensor-core 3xTF32 (unchanged from R3)
// =====================================================================
#define FEAT_SMEM_BYTES (51456 * 4)

__global__ __launch_bounds__(256, 1)
void feature_mma(const float* __restrict__ proj)
{
    extern __shared__ uint32_t smu[];
    uint32_t* AH = smu;
    uint32_t* AL = smu + 8704;
    uint32_t* PH = smu + 17408;
    uint32_t* PL = smu + 34304;
    float*    sm_e = (float*)(smu + 17408);     // alias (after MMA phase)
    float*    RMAX = (float*)(smu + 51200);

    const int cid = blockIdx.x;
    const int isK = blockIdx.y;
    const int b  = cid >> 8;
    const int h  = (cid >> 5) & 7;
    const int cc = cid & 31;
    const size_t row0   = (size_t)b * SEQ + (size_t)cc * CSZ;
    const int   colbase = isK * DIMM + h * DHD;
    const float scale   = isK ? 1.0f : 0.125f;
    const int tid  = threadIdx.x;
    const int lane = tid & 31;
    const int warp = tid >> 5;
    const int wgm  = warp >> 1;
    const int fg   = warp & 1;
    const int qr   = lane >> 2;
    const int qc   = lane & 3;

#pragma unroll
    for (int it = 0; it < 8; ++it) {
        const int idx4 = it * 256 + tid;
        const int s  = idx4 >> 4;
        const int d  = (idx4 & 15) * 4;
        float4 v = *(const float4*)(g_qkv + (row0 + s) * QKVN + colbase + d);
        float f0 = v.x * scale, f1 = v.y * scale, f2 = v.z * scale, f3 = v.w * scale;
        uint32_t h0 = f2tf32(f0), h1 = f2tf32(f1), h2 = f2tf32(f2), h3 = f2tf32(f3);
        AH[(d+0)*136 + s] = h0; AL[(d+0)*136 + s] = f2tf32(f0 - __uint_as_float(h0));
        AH[(d+1)*136 + s] = h1; AL[(d+1)*136 + s] = f2tf32(f1 - __uint_as_float(h1));
        AH[(d+2)*136 + s] = h2; AL[(d+2)*136 + s] = f2tf32(f2 - __uint_as_float(h2));
        AH[(d+3)*136 + s] = h3; AL[(d+3)*136 + s] = f2tf32(f3 - __uint_as_float(h3));
    }
#pragma unroll
    for (int it = 0; it < 16; ++it) {
        const int idx4 = it * 256 + tid;
        const int f  = idx4 >> 4;
        const int d  = (idx4 & 15) * 4;
        float4 v = *(const float4*)(proj + f * DHD + d);
        uint32_t h0 = f2tf32(v.x), h1 = f2tf32(v.y), h2 = f2tf32(v.z), h3 = f2tf32(v.w);
        PH[(d+0)*264 + f] = h0; PL[(d+0)*264 + f] = f2tf32(v.x - __uint_as_float(h0));
        PH[(d+1)*264 + f] = h1; PL[(d+1)*264 + f] = f2tf32(v.y - __uint_as_float(h1));
        PH[(d+2)*264 + f] = h2; PL[(d+2)*264 + f] = f2tf32(v.z - __uint_as_float(h2));
        PH[(d+3)*264 + f] = h3; PL[(d+3)*264 + f] = f2tf32(v.w - __uint_as_float(h3));
    }
    __syncthreads();

    float acc[2][16][4];
#pragma unroll
    for (int mt = 0; mt < 2; mt++)
#pragma unroll
        for (int nt = 0; nt < 16; nt++)
#pragma unroll
            for (int c = 0; c < 4; c++) acc[mt][nt][c] = 0.f;

#pragma unroll
    for (int ks = 0; ks < 8; ++ks) {
        const int k0 = ks * 8;
        uint32_t ah[2][4], al[2][4];
#pragma unroll
        for (int mt = 0; mt < 2; mt++) {
            const int row = wgm*32 + mt*16 + qr;
            const int i0 = (k0+qc)*136 + row;
            const int i1 = (k0+qc+4)*136 + row;
            ah[mt][0] = AH[i0]; ah[mt][1] = AH[i0+8];
            ah[mt][2] = AH[i1]; ah[mt][3] = AH[i1+8];
            al[mt][0] = AL[i0]; al[mt][1] = AL[i0+8];
            al[mt][2] = AL[i1]; al[mt][3] = AL[i1+8];
        }
#pragma unroll
        for (int nt = 0; nt < 16; nt++) {
            const int col = fg*128 + nt*8 + qr;
            const uint32_t bh0 = PH[(k0+qc)*264 + col];
            const uint32_t bh1 = PH[(k0+qc+4)*264 + col];
            const uint32_t bl0 = PL[(k0+qc)*264 + col];
            const uint32_t bl1 = PL[(k0+qc+4)*264 + col];
#pragma unroll
            for (int mt = 0; mt < 2; mt++) {
                mma_tf32(acc[mt][nt], ah[mt][0], ah[mt][1], ah[mt][2], ah[mt][3], bh0, bh1);
                mma_tf32(acc[mt][nt], ah[mt][0], ah[mt][1], ah[mt][2], ah[mt][3], bl0, bl1);
                mma_tf32(acc[mt][nt], al[mt][0], al[mt][1], al[mt][2], al[mt][3], bh0, bh1);
            }
        }
    }

    float mloc[2][2];
#pragma unroll
    for (int mt = 0; mt < 2; mt++)
#pragma unroll
        for (int hh = 0; hh < 2; hh++) {
            float m = -1e30f;
#pragma unroll
            for (int nt = 0; nt < 16; nt++) {
                m = fmaxf(m, acc[mt][nt][hh*2+0]);
                m = fmaxf(m, acc[mt][nt][hh*2+1]);
            }
            m = fmaxf(m, __shfl_xor_sync(0xffffffffu, m, 1));
            m = fmaxf(m, __shfl_xor_sync(0xffffffffu, m, 2));
            mloc[mt][hh] = m;
        }
    if (qc == 0) {
#pragma unroll
        for (int mt = 0; mt < 2; mt++)
#pragma unroll
            for (int hh = 0; hh < 2; hh++)
                RMAX[fg*128 + wgm*32 + mt*16 + hh*8 + qr] = mloc[mt][hh];
    }
    __syncthreads();

    float rm[2][2];
#pragma unroll
    for (int mt = 0; mt < 2; mt++)
#pragma unroll
        for (int hh = 0; hh < 2; hh++) {
            const int row = wgm*32 + mt*16 + hh*8 + qr;
            rm[mt][hh] = fmaxf(RMAX[row], RMAX[128 + row]);
        }

#pragma unroll
    for (int mt = 0; mt < 2; mt++)
#pragma unroll
        for (int hh = 0; hh < 2; hh++) {
            const int row = wgm*32 + mt*16 + hh*8 + qr;
#pragma unroll
            for (int nt = 0; nt < 16; nt++) {
                const int f = fg*128 + nt*8 + 2*qc;
                float e0 = __expf(acc[mt][nt][hh*2+0] - rm[mt][hh]);
                float e1 = __expf(acc[mt][nt][hh*2+1] - rm[mt][hh]);
                sm_e[row*260 + f]     = __uint_as_float(f2tf32(e0));
                sm_e[row*260 + f + 1] = __uint_as_float(f2tf32(e1));
            }
        }
    __syncthreads();

    float* outp = isK ? g_kp : g_qp;
    const size_t obase = ((size_t)(b*NH + h) * SEQ + (size_t)cc * CSZ) * NF;
#pragma unroll
    for (int it = 0; it < 32; ++it) {
        const int idx4 = it * 256 + tid;
        const int r  = idx4 >> 6;
        const int c4 = (idx4 & 63) * 4;
        float4 v;
        v.x = sm_e[r*260 + c4 + 0];
        v.y = sm_e[r*260 + c4 + 1];
        v.z = sm_e[r*260 + c4 + 2];
        v.w = sm_e[r*260 + c4 + 3];
        *(float4*)(outp + obase + (size_t)r * NF + c4) = v;
    }
    if (isK && tid < NF) {
        float s = 0.f;
#pragma unroll 8
        for (int r = 0; r < CSZ; ++r) s += sm_e[r*260 + tid];
        g_ksum[(size_t)cid * NF + tid] = s;
    }
}

// =====================================================================
// Fused ctx + out kernel (unchanged from R3)
// =====================================================================
#define CO_SMEM_BYTES (52608 * 4)

__global__ __launch_bounds__(256, 1)
void ctx_out_mma()
{
    extern __shared__ uint32_t smu[];
    uint32_t* KB = smu;
    uint32_t* VB = smu + 33792;
    uint32_t* CB = smu;
    uint32_t* QB = smu + 18432;
    float*    SK = (float*)(smu + 52224);
    float*    DB = (float*)(smu + 52480);

    const int cid = blockIdx.x;
    const int b  = cid >> 8;
    const int h  = (cid >> 5) & 7;
    const int cc = cid & 31;
    const size_t row0   = (size_t)b * SEQ + (size_t)cc * CSZ;
    const size_t pbase  = ((size_t)(b*NH + h) * SEQ + (size_t)cc * CSZ) * NF;
    const int vcol = 2 * DIMM + h * DHD;
    const int tid  = threadIdx.x;
    const int lane = tid & 31;
    const int warp = tid >> 5;
    const int qr   = lane >> 2;
    const int qc   = lane & 3;

#pragma unroll
    for (int it = 0; it < 32; ++it) {
        const int idx4 = it * 256 + tid;
        const int r  = idx4 >> 6;
        const int c4 = (idx4 & 63) * 4;
        uint4 v = *(const uint4*)((const uint32_t*)g_kp + pbase + (size_t)r * NF + c4);
        *(uint4*)(KB + r*264 + c4) = v;
    }
#pragma unroll
    for (int it = 0; it < 8; ++it) {
        const int idx4 = it * 256 + tid;
        const int s  = idx4 >> 4;
        const int d4 = (idx4 & 15) * 4;
        float4 v = *(const float4*)(g_qkv + (row0 + s) * QKVN + vcol + d4);
        uint4 u;
        u.x = f2tf32(v.x); u.y = f2tf32(v.y); u.z = f2tf32(v.z); u.w = f2tf32(v.w);
        *(uint4*)(VB + s*72 + d4) = u;
    }
    if (tid < NF) SK[tid] = g_ksum[(size_t)cid * NF + tid];
    __syncthreads();

    {
        float acc[2][8][4];
#pragma unroll
        for (int mt = 0; mt < 2; mt++)
#pragma unroll
            for (int nt = 0; nt < 8; nt++)
#pragma unroll
                for (int c = 0; c < 4; c++) acc[mt][nt][c] = 0.f;

#pragma unroll 4
        for (int ks = 0; ks < 16; ++ks) {
            const int k0 = ks * 8;
            uint32_t af[2][4];
#pragma unroll
            for (int mt = 0; mt < 2; mt++) {
                const int fr = warp*32 + mt*16 + qr;
                const int i0 = (k0+qc)*264 + fr;
                const int i1 = (k0+qc+4)*264 + fr;
                af[mt][0] = KB[i0]; af[mt][1] = KB[i0+8];
                af[mt][2] = KB[i1]; af[mt][3] = KB[i1+8];
            }
#pragma unroll
            for (int nt = 0; nt < 8; nt++) {
                const int col = nt*8 + qr;
                const uint32_t b0 = VB[(k0+qc)*72 + col];
                const uint32_t b1 = VB[(k0+qc+4)*72 + col];
#pragma unroll
                for (int mt = 0; mt < 2; mt++)
                    mma_tf32(acc[mt][nt], af[mt][0], af[mt][1], af[mt][2], af[mt][3], b0, b1);
            }
        }
        __syncthreads();

#pragma unroll
        for (int mt = 0; mt < 2; mt++) {
            const int f0 = warp*32 + mt*16 + qr;
#pragma unroll
            for (int nt = 0; nt < 8; nt++) {
                const int col = nt*8 + 2*qc;
                uint2 u01 = make_uint2(f2tf32(acc[mt][nt][0]), f2tf32(acc[mt][nt][1]));
                uint2 u23 = make_uint2(f2tf32(acc[mt][nt][2]), f2tf32(acc[mt][nt][3]));
                *(uint2*)(CB + f0*72 + col)       = u01;
                *(uint2*)(CB + (f0+8)*72 + col)   = u23;
            }
        }
    }

#pragma unroll
    for (int it = 0; it < 32; ++it) {
        const int idx4 = it * 256 + tid;
        const int r  = idx4 >> 6;
        const int c4 = (idx4 & 63) * 4;
        uint4 v = *(const uint4*)((const uint32_t*)g_qp + pbase + (size_t)r * NF + c4);
        *(uint4*)(QB + r*264 + c4) = v;
    }
    __syncthreads();

    if (tid < CSZ) {
        float s = 0.f;
        const uint32_t* qrow = QB + tid*264;
#pragma unroll 8
        for (int f = 0; f < NF; ++f)
            s = fmaf(__uint_as_float(qrow[f]), SK[f], s);
        DB[tid] = 1.0f / (s + 1e-4f);
    }

    {
        const int mg = warp >> 1;
        const int ng = warp & 1;
        float acc[2][4][4];
#pragma unroll
        for (int mt = 0; mt < 2; mt++)
#pragma unroll
            for (int nt = 0; nt < 4; nt++)
#pragma unroll
                for (int c = 0; c < 4; c++) acc[mt][nt][c] = 0.f;

#pragma unroll 4
        for (int ks = 0; ks < 32; ++ks) {
            const int k0 = ks * 8;
            uint32_t af[2][4];
#pragma unroll
            for (int mt = 0; mt < 2; mt++) {
                const int row = mg*32 + mt*16 + qr;
                af[mt][0] = QB[row*264 + k0+qc];
                af[mt][1] = QB[(row+8)*264 + k0+qc];
                af[mt][2] = QB[row*264 + k0+qc+4];
                af[mt][3] = QB[(row+8)*264 + k0+qc+4];
            }
#pragma unroll
            for (int nt = 0; nt < 4; nt++) {
                const int col = ng*32 + nt*8 + qr;
                const uint32_t b0 = CB[(k0+qc)*72 + col];
                const uint32_t b1 = CB[(k0+qc+4)*72 + col];
#pragma unroll
                for (int mt = 0; mt < 2; mt++)
                    mma_tf32(acc[mt][nt], af[mt][0], af[mt][1], af[mt][2], af[mt][3], b0, b1);
            }
        }
        __syncthreads();

#pragma unroll
        for (int mt = 0; mt < 2; mt++) {
            const int r0 = mg*32 + mt*16 + qr;
            const float d0 = DB[r0];
            const float d1 = DB[r0 + 8];
#pragma unroll
            for (int nt = 0; nt < 4; nt++) {
                const int col = ng*32 + nt*8 + 2*qc;
                float* op0 = g_att + (row0 + r0)     * DIMM + h*DHD + col;
                float* op1 = g_att + (row0 + r0 + 8) * DIMM + h*DHD + col;
                *(float2*)op0 = make_float2(acc[mt][nt][0]*d0, acc[mt][nt][1]*d0);
                *(float2*)op1 = make_float2(acc[mt][nt][2]*d1, acc[mt][nt][3]*d1);
            }
        }
    }
}

// =====================================================================
// launch
// =====================================================================
extern "C" void kernel_launch(void* const* d_in, const int* in_sizes, int n_in,
                              void* d_out, int out_size)
{
    const float *x = nullptr, *wqkv = nullptr, *wout = nullptr,
                *bout = nullptr, *proj = nullptr;
    for (int i = 0; i < n_in; i++) {
        switch (in_sizes[i]) {
            case MTOK * DIMM:  x    = (const float*)d_in[i]; break;
            case QKVN * DIMM:  wqkv = (const float*)d_in[i]; break;
            case DIMM * DIMM:  wout = (const float*)d_in[i]; break;
            case DIMM:         bout = (const float*)d_in[i]; break;
            case NF * DHD:     proj = (const float*)d_in[i]; break;
        }
    }

    cudaFuncSetAttribute(feature_mma, cudaFuncAttributeMaxDynamicSharedMemorySize, FEAT_SMEM_BYTES);
    cudaFuncSetAttribute(ctx_out_mma, cudaFuncAttributeMaxDynamicSharedMemorySize, CO_SMEM_BYTES);

    float *qkvp = nullptr, *attp = nullptr;
    cudaGetSymbolAddress((void**)&qkvp, g_qkv);
    cudaGetSymbolAddress((void**)&attp, g_att);

    // 1) qkv = x @ w_qkv^T  (packed-fragment tf32)
    tgemm_nt<false><<<dim3(QKVN/128, MTOK/128), 256>>>(x, wqkv, nullptr, qkvp,
                                                       MTOK, QKVN, DIMM);
    // 2) q'/k' feature maps (3xTF32) + ksum
    feature_mma<<<dim3(NCHUNK, 2), 256, FEAT_SMEM_BYTES>>>(proj);
    // 3+4) fused ctx + out
    ctx_out_mma<<<NCHUNK, 256, CO_SMEM_BYTES>>>();
    // 5) final = att @ w_out^T + b_out  (packed-fragment tf32)
    tgemm_nt<true><<<dim3(DIMM/128, MTOK/128), 256>>>(attp, wout, bout,
                                                      (float*)d_out,
                                                      MTOK, DIMM, DIMM);
}

// round 5
// speedup vs baseline: 2.7343x; 1.3966x over previous
#include <cuda_runtime.h>
#include <cstdint>

// ---------------- problem constants ----------------
#define NB   4
#define SEQ  4096
#define DIMM 512
#define NH   8
#define DHD  64
#define NF   256
#define CSZ  128
#define NCH  32
#define MTOK (NB*SEQ)            // 16384
#define QKVN (3*DIMM)            // 1536
#define NCHUNK (NB*NH*NCH)       // 1024

// ---------------- device scratch ----------------
__device__ float g_qkv [MTOK * QKVN];
__device__ float g_qp  [NB*NH*SEQ*NF];   // stored tf32-rounded
__device__ float g_kp  [NB*NH*SEQ*NF];   // stored tf32-rounded
__device__ float g_ksum[NCHUNK * NF];
__device__ float g_att [MTOK * DIMM];

__device__ __forceinline__ uint32_t f2tf32(float f) {
    uint32_t r;
    asm("cvt.rna.tf32.f32 %0, %1;" : "=r"(r) : "f"(f));
    return r;
}

__device__ __forceinline__ void mma_tf32(float acc[4],
                                         uint32_t a0, uint32_t a1, uint32_t a2, uint32_t a3,
                                         uint32_t b0, uint32_t b1)
{
    asm volatile(
        "mma.sync.aligned.m16n8k8.row.col.f32.tf32.tf32.f32 "
        "{%0,%1,%2,%3}, {%4,%5,%6,%7}, {%8,%9}, {%0,%1,%2,%3};"
        : "+f"(acc[0]), "+f"(acc[1]), "+f"(acc[2]), "+f"(acc[3])
        : "r"(a0), "r"(a1), "r"(a2), "r"(a3), "r"(b0), "r"(b1));
}

// =====================================================================
// TF32 tensor-core GEMM NT with packed-fragment smem (unchanged R4).
// =====================================================================
template<bool BIAS>
__global__ __launch_bounds__(256, 2)
void tgemm_nt(const float* __restrict__ A, const float* __restrict__ Bm,
              const float* __restrict__ bias, float* __restrict__ C,
              int M, int N, int K)
{
    __shared__ __align__(16) uint32_t Apk[2][2][8][128];
    __shared__ __align__(16) uint32_t Bpk[2][2][16][64];

    const int tid  = threadIdx.x;
    const int lane = tid & 31;
    const int warp = tid >> 5;
    const int wsubA = (warp >> 1) * 2;
    const int wsubB = (warp & 1)  * 8;
    const int qr   = lane >> 2;
    const int qc   = lane & 3;

    const int bm = blockIdx.y * 128;
    const int bn = blockIdx.x * 128;

    const int lm  = tid >> 2;
    const int lk  = (tid & 3) * 4;
    const int wkg = lk >> 3;
    const int whi = (lk >> 2) & 1;
    const int qrw   = lm & 7;
    const int half  = (lm >> 3) & 1;
    const int subA0 = lm >> 4;
    const int nsub0 = lm >> 3;
    const int wrot  = ((qrw >> 1) + 2 * wkg) & 3;
    const int wordA = whi * 2 + half;

    const float* Ap = A  + (size_t)(bm + lm) * K + lk;
    const float* Bp = Bm + (size_t)(bn + lm) * K + lk;

    float acc[2][8][4];
#pragma unroll
    for (int mt = 0; mt < 2; mt++)
#pragma unroll
        for (int nt = 0; nt < 8; nt++)
#pragma unroll
            for (int c = 0; c < 4; c++) acc[mt][nt][c] = 0.f;

    float4 pa0 = *(const float4*)Ap;
    float4 pa1 = *(const float4*)(Ap + (size_t)64 * K);
    float4 pb0 = *(const float4*)Bp;
    float4 pb1 = *(const float4*)(Bp + (size_t)64 * K);

    auto stage = [&](int bf, const float4& a0, const float4& a1,
                     const float4& b0, const float4& b1) {
        uint32_t* ad0 = &Apk[bf][wkg][subA0    ][0];
        uint32_t* ad1 = &Apk[bf][wkg][subA0 + 4][0];
        uint32_t* bd0 = &Bpk[bf][wkg][nsub0    ][0];
        uint32_t* bd1 = &Bpk[bf][wkg][nsub0 + 8][0];
        const float* av0 = &a0.x;
        const float* av1 = &a1.x;
        const float* bv0 = &b0.x;
        const float* bv1 = &b1.x;
#pragma unroll
        for (int j = 0; j < 4; ++j) {
            const int lp = ((qrw << 2) | ((j + wrot) & 3));
            ad0[lp*4 + wordA] = f2tf32(av0[j]);
            ad1[lp*4 + wordA] = f2tf32(av1[j]);
            bd0[lp*2 + whi]   = f2tf32(bv0[j]);
            bd1[lp*2 + whi]   = f2tf32(bv1[j]);
        }
    };

    stage(0, pa0, pa1, pb0, pb1);
    __syncthreads();

    const int KT = K >> 4;
    for (int kt = 0; kt < KT; ++kt) {
        const int buf = kt & 1;
        if (kt + 1 < KT) {
            const float* Ap2 = Ap + (kt + 1) * 16;
            const float* Bp2 = Bp + (kt + 1) * 16;
            pa0 = *(const float4*)Ap2;
            pa1 = *(const float4*)(Ap2 + (size_t)64 * K);
            pb0 = *(const float4*)Bp2;
            pb1 = *(const float4*)(Bp2 + (size_t)64 * K);
        }
#pragma unroll
        for (int kg = 0; kg < 2; ++kg) {
            const int rlane = ((qr << 2) | ((qc + (qr >> 1) + 2*kg) & 3));
            uint4 a0 = *(const uint4*)&Apk[buf][kg][wsubA    ][rlane*4];
            uint4 a1 = *(const uint4*)&Apk[buf][kg][wsubA + 1][rlane*4];
            uint2 bb[8];
#pragma unroll
            for (int nt = 0; nt < 8; nt++)
                bb[nt] = *(const uint2*)&Bpk[buf][kg][wsubB + nt][rlane*2];
#pragma unroll
            for (int nt = 0; nt < 8; nt++) {
                mma_tf32(acc[0][nt], a0.x, a0.y, a0.z, a0.w, bb[nt].x, bb[nt].y);
                mma_tf32(acc[1][nt], a1.x, a1.y, a1.z, a1.w, bb[nt].x, bb[nt].y);
            }
        }
        if (kt + 1 < KT) {
            stage(buf ^ 1, pa0, pa1, pb0, pb1);
            __syncthreads();
        }
    }

#pragma unroll
    for (int mt = 0; mt < 2; mt++) {
        const int r0 = bm + (wsubA + mt) * 16 + qr;
#pragma unroll
        for (int nt = 0; nt < 8; nt++) {
            const int c0 = bn + (wsubB + nt) * 8 + 2*qc;
            float v0 = acc[mt][nt][0], v1 = acc[mt][nt][1];
            float v2 = acc[mt][nt][2], v3 = acc[mt][nt][3];
            if (BIAS) {
                const float b0 = __ldg(bias + c0), b1 = __ldg(bias + c0 + 1);
                v0 += b0; v1 += b1; v2 += b0; v3 += b1;
            }
            *(float2*)(C + (size_t)r0       * N + c0) = make_float2(v0, v1);
            *(float2*)(C + (size_t)(r0 + 8) * N + c0) = make_float2(v2, v3);
        }
    }
}

// =====================================================================
// Feature kernel, single-pass TF32 with packed-fragment smem.
//   S = (t*scale) @ proj^T   [128 x 256 x 64]
//   out = exp(S - rowmax(S)) (tf32-rounded), ksum for k.
// 256 threads = 8 warps: wgm(4) x fg(2). Warp tile 32(s) x 128(f).
//
// Packed A: per ks (8): [sub(8)][lane(32)][word(4)], block stride 1028 u32.
// Packed P: per ks (8): [nsub(32)][lane(32)][word(2)], block stride 2052 u32.
// (+4 u32 pad per ks block -> writer STS <=2-way, reader LDS conflict-free)
// =====================================================================
#define APK_KS_STRIDE 1028          // 8*32*4 + 4
#define PPK_KS_STRIDE 2052          // 32*32*2 + 4
#define PPK_BASE      (8 * APK_KS_STRIDE)              // 8224
#define SME_SIZE      (CSZ * 260)                      // 33280 (aliases APK+PPK)
#define RMAX_BASE     SME_SIZE                         // 33280
#define FEAT_SMEM_BYTES ((SME_SIZE + 256) * 4)         // 134144

__global__ __launch_bounds__(256, 1)
void feature_mma(const float* __restrict__ proj)
{
    extern __shared__ uint32_t smu[];
    uint32_t* APK = smu;
    uint32_t* PPK = smu + PPK_BASE;
    float*    sm_e = (float*)smu;                 // alias (after MMA phase)
    float*    RMAX = (float*)(smu + RMAX_BASE);

    const int cid = blockIdx.x;
    const int isK = blockIdx.y;
    const int b  = cid >> 8;
    const int h  = (cid >> 5) & 7;
    const int cc = cid & 31;
    const size_t row0   = (size_t)b * SEQ + (size_t)cc * CSZ;
    const int   colbase = isK * DIMM + h * DHD;
    const float scale   = isK ? 1.0f : 0.125f;
    const int tid  = threadIdx.x;
    const int lane = tid & 31;
    const int warp = tid >> 5;
    const int wgm  = warp >> 1;     // 0..3  (s rows, 32 each)
    const int fg   = warp & 1;      // 0..1  (f cols, 128 each)
    const int qr   = lane >> 2;
    const int qc   = lane & 3;

    // ---- load t chunk [128 s][64 d] -> packed A fragments ----
#pragma unroll
    for (int it = 0; it < 8; ++it) {
        const int idx4 = it * 256 + tid;          // 0..2047
        const int s  = idx4 >> 4;
        const int d4 = (idx4 & 15) * 4;
        float4 v = *(const float4*)(g_qkv + (row0 + s) * QKVN + colbase + d4);
        const int ks   = d4 >> 3;
        const int hi   = (d4 >> 2) & 1;
        const int sub  = s >> 4;
        const int qrS  = s & 7;
        const int halfS= (s >> 3) & 1;
        const int word = hi * 2 + halfS;
        uint32_t* base = APK + ks * APK_KS_STRIDE + sub * 128 + (qrS << 4); // qrS*4 lanes *4 words
        base[0*4 + word] = f2tf32(v.x * scale);
        base[1*4 + word] = f2tf32(v.y * scale);
        base[2*4 + word] = f2tf32(v.z * scale);
        base[3*4 + word] = f2tf32(v.w * scale);
    }
    // ---- load proj [256 f][64 d] -> packed B fragments ----
#pragma unroll
    for (int it = 0; it < 16; ++it) {
        const int idx4 = it * 256 + tid;          // 0..4095
        const int f  = idx4 >> 4;
        const int d4 = (idx4 & 15) * 4;
        float4 v = *(const float4*)(proj + f * DHD + d4);
        const int ks   = d4 >> 3;
        const int hi   = (d4 >> 2) & 1;
        const int nsub = f >> 3;
        const int qrF  = f & 7;
        uint32_t* base = PPK + ks * PPK_KS_STRIDE + nsub * 64 + (qrF << 3);  // qrF*4 lanes *2 words
        base[0*2 + hi] = f2tf32(v.x);
        base[1*2 + hi] = f2tf32(v.y);
        base[2*2 + hi] = f2tf32(v.z);
        base[3*2 + hi] = f2tf32(v.w);
    }
    __syncthreads();

    float acc[2][16][4];
#pragma unroll
    for (int mt = 0; mt < 2; mt++)
#pragma unroll
        for (int nt = 0; nt < 16; nt++)
#pragma unroll
            for (int c = 0; c < 4; c++) acc[mt][nt][c] = 0.f;

    const int rl4 = lane * 4;
    const int rl2 = lane * 2;
#pragma unroll
    for (int ks = 0; ks < 8; ++ks) {
        const uint32_t* abase = APK + ks * APK_KS_STRIDE;
        const uint32_t* pbase = PPK + ks * PPK_KS_STRIDE;
        uint4 a0 = *(const uint4*)&abase[(wgm*2 + 0) * 128 + rl4];
        uint4 a1 = *(const uint4*)&abase[(wgm*2 + 1) * 128 + rl4];
#pragma unroll
        for (int nt = 0; nt < 16; nt++) {
            uint2 bb = *(const uint2*)&pbase[(fg*16 + nt) * 64 + rl2];
            mma_tf32(acc[0][nt], a0.x, a0.y, a0.z, a0.w, bb.x, bb.y);
            mma_tf32(acc[1][nt], a1.x, a1.y, a1.z, a1.w, bb.x, bb.y);
        }
    }

    // rowmax: per-thread partial, qc-shuffle, then combine 2 f-warps via smem
    float mloc[2][2];
#pragma unroll
    for (int mt = 0; mt < 2; mt++)
#pragma unroll
        for (int hh = 0; hh < 2; hh++) {
            float m = -1e30f;
#pragma unroll
            for (int nt = 0; nt < 16; nt++) {
                m = fmaxf(m, acc[mt][nt][hh*2+0]);
                m = fmaxf(m, acc[mt][nt][hh*2+1]);
            }
            m = fmaxf(m, __shfl_xor_sync(0xffffffffu, m, 1));
            m = fmaxf(m, __shfl_xor_sync(0xffffffffu, m, 2));
            mloc[mt][hh] = m;
        }
    if (qc == 0) {
#pragma unroll
        for (int mt = 0; mt < 2; mt++)
#pragma unroll
            for (int hh = 0; hh < 2; hh++)
                RMAX[fg*128 + wgm*32 + mt*16 + hh*8 + qr] = mloc[mt][hh];
    }
    __syncthreads();    // also fences mainloop smem reads before sm_e aliasing

    float rm[2][2];
#pragma unroll
    for (int mt = 0; mt < 2; mt++)
#pragma unroll
        for (int hh = 0; hh < 2; hh++) {
            const int row = wgm*32 + mt*16 + hh*8 + qr;
            rm[mt][hh] = fmaxf(RMAX[row], RMAX[128 + row]);
        }

    // exp + tf32-round, stage into sm_e[row][260]
#pragma unroll
    for (int mt = 0; mt < 2; mt++)
#pragma unroll
        for (int hh = 0; hh < 2; hh++) {
            const int row = wgm*32 + mt*16 + hh*8 + qr;
#pragma unroll
            for (int nt = 0; nt < 16; nt++) {
                const int f = fg*128 + nt*8 + 2*qc;
                float e0 = __expf(acc[mt][nt][hh*2+0] - rm[mt][hh]);
                float e1 = __expf(acc[mt][nt][hh*2+1] - rm[mt][hh]);
                sm_e[row*260 + f]     = __uint_as_float(f2tf32(e0));
                sm_e[row*260 + f + 1] = __uint_as_float(f2tf32(e1));
            }
        }
    __syncthreads();

    // coalesced global store
    float* outp = isK ? g_kp : g_qp;
    const size_t obase = ((size_t)(b*NH + h) * SEQ + (size_t)cc * CSZ) * NF;
#pragma unroll
    for (int it = 0; it < 32; ++it) {
        const int idx4 = it * 256 + tid;
        const int r  = idx4 >> 6;
        const int c4 = (idx4 & 63) * 4;
        float4 v;
        v.x = sm_e[r*260 + c4 + 0];
        v.y = sm_e[r*260 + c4 + 1];
        v.z = sm_e[r*260 + c4 + 2];
        v.w = sm_e[r*260 + c4 + 3];
        *(float4*)(outp + obase + (size_t)r * NF + c4) = v;
    }
    if (isK && tid < NF) {
        float s = 0.f;
#pragma unroll 8
        for (int r = 0; r < CSZ; ++r) s += sm_e[r*260 + tid];
        g_ksum[(size_t)cid * NF + tid] = s;
    }
}

// =====================================================================
// Fused ctx + out kernel (unchanged from R3/R4)
// =====================================================================
#define CO_SMEM_BYTES (52608 * 4)

__global__ __launch_bounds__(256, 1)
void ctx_out_mma()
{
    extern __shared__ uint32_t smu[];
    uint32_t* KB = smu;
    uint32_t* VB = smu + 33792;
    uint32_t* CB = smu;
    uint32_t* QB = smu + 18432;
    float*    SK = (float*)(smu + 52224);
    float*    DB = (float*)(smu + 52480);

    const int cid = blockIdx.x;
    const int b  = cid >> 8;
    const int h  = (cid >> 5) & 7;
    const int cc = cid & 31;
    const size_t row0   = (size_t)b * SEQ + (size_t)cc * CSZ;
    const size_t pbase  = ((size_t)(b*NH + h) * SEQ + (size_t)cc * CSZ) * NF;
    const int vcol = 2 * DIMM + h * DHD;
    const int tid  = threadIdx.x;
    const int lane = tid & 31;
    const int warp = tid >> 5;
    const int qr   = lane >> 2;
    const int qc   = lane & 3;

#pragma unroll
    for (int it = 0; it < 32; ++it) {
        const int idx4 = it * 256 + tid;
        const int r  = idx4 >> 6;
        const int c4 = (idx4 & 63) * 4;
        uint4 v = *(const uint4*)((const uint32_t*)g_kp + pbase + (size_t)r * NF + c4);
        *(uint4*)(KB + r*264 + c4) = v;
    }
#pragma unroll
    for (int it = 0; it < 8; ++it) {
        const int idx4 = it * 256 + tid;
        const int s  = idx4 >> 4;
        const int d4 = (idx4 & 15) * 4;
        float4 v = *(const float4*)(g_qkv + (row0 + s) * QKVN + vcol + d4);
        uint4 u;
        u.x = f2tf32(v.x); u.y = f2tf32(v.y); u.z = f2tf32(v.z); u.w = f2tf32(v.w);
        *(uint4*)(VB + s*72 + d4) = u;
    }
    if (tid < NF) SK[tid] = g_ksum[(size_t)cid * NF + tid];
    __syncthreads();

    {
        float acc[2][8][4];
#pragma unroll
        for (int mt = 0; mt < 2; mt++)
#pragma unroll
            for (int nt = 0; nt < 8; nt++)
#pragma unroll
                for (int c = 0; c < 4; c++) acc[mt][nt][c] = 0.f;

#pragma unroll 4
        for (int ks = 0; ks < 16; ++ks) {
            const int k0 = ks * 8;
            uint32_t af[2][4];
#pragma unroll
            for (int mt = 0; mt < 2; mt++) {
                const int fr = warp*32 + mt*16 + qr;
                const int i0 = (k0+qc)*264 + fr;
                const int i1 = (k0+qc+4)*264 + fr;
                af[mt][0] = KB[i0]; af[mt][1] = KB[i0+8];
                af[mt][2] = KB[i1]; af[mt][3] = KB[i1+8];
            }
#pragma unroll
            for (int nt = 0; nt < 8; nt++) {
                const int col = nt*8 + qr;
                const uint32_t b0 = VB[(k0+qc)*72 + col];
                const uint32_t b1 = VB[(k0+qc+4)*72 + col];
#pragma unroll
                for (int mt = 0; mt < 2; mt++)
                    mma_tf32(acc[mt][nt], af[mt][0], af[mt][1], af[mt][2], af[mt][3], b0, b1);
            }
        }
        __syncthreads();

#pragma unroll
        for (int mt = 0; mt < 2; mt++) {
            const int f0 = warp*32 + mt*16 + qr;
#pragma unroll
            for (int nt = 0; nt < 8; nt++) {
                const int col = nt*8 + 2*qc;
                uint2 u01 = make_uint2(f2tf32(acc[mt][nt][0]), f2tf32(acc[mt][nt][1]));
                uint2 u23 = make_uint2(f2tf32(acc[mt][nt][2]), f2tf32(acc[mt][nt][3]));
                *(uint2*)(CB + f0*72 + col)       = u01;
                *(uint2*)(CB + (f0+8)*72 + col)   = u23;
            }
        }
    }

#pragma unroll
    for (int it = 0; it < 32; ++it) {
        const int idx4 = it * 256 + tid;
        const int r  = idx4 >> 6;
        const int c4 = (idx4 & 63) * 4;
        uint4 v = *(const uint4*)((const uint32_t*)g_qp + pbase + (size_t)r * NF + c4);
        *(uint4*)(QB + r*264 + c4) = v;
    }
    __syncthreads();

    if (tid < CSZ) {
        float s = 0.f;
        const uint32_t* qrow = QB + tid*264;
#pragma unroll 8
        for (int f = 0; f < NF; ++f)
            s = fmaf(__uint_as_float(qrow[f]), SK[f], s);
        DB[tid] = 1.0f / (s + 1e-4f);
    }

    {
        const int mg = warp >> 1;
        const int ng = warp & 1;
        float acc[2][4][4];
#pragma unroll
        for (int mt = 0; mt < 2; mt++)
#pragma unroll
            for (int nt = 0; nt < 4; nt++)
#pragma unroll
                for (int c = 0; c < 4; c++) acc[mt][nt][c] = 0.f;

#pragma unroll 4
        for (int ks = 0; ks < 32; ++ks) {
            const int k0 = ks * 8;
            uint32_t af[2][4];
#pragma unroll
            for (int mt = 0; mt < 2; mt++) {
                const int row = mg*32 + mt*16 + qr;
                af[mt][0] = QB[row*264 + k0+qc];
                af[mt][1] = QB[(row+8)*264 + k0+qc];
                af[mt][2] = QB[row*264 + k0+qc+4];
                af[mt][3] = QB[(row+8)*264 + k0+qc+4];
            }
#pragma unroll
            for (int nt = 0; nt < 4; nt++) {
                const int col = ng*32 + nt*8 + qr;
                const uint32_t b0 = CB[(k0+qc)*72 + col];
                const uint32_t b1 = CB[(k0+qc+4)*72 + col];
#pragma unroll
                for (int mt = 0; mt < 2; mt++)
                    mma_tf32(acc[mt][nt], af[mt][0], af[mt][1], af[mt][2], af[mt][3], b0, b1);
            }
        }
        __syncthreads();

#pragma unroll
        for (int mt = 0; mt < 2; mt++) {
            const int r0 = mg*32 + mt*16 + qr;
            const float d0 = DB[r0];
            const float d1 = DB[r0 + 8];
#pragma unroll
            for (int nt = 0; nt < 4; nt++) {
                const int col = ng*32 + nt*8 + 2*qc;
                float* op0 = g_att + (row0 + r0)     * DIMM + h*DHD + col;
                float* op1 = g_att + (row0 + r0 + 8) * DIMM + h*DHD + col;
                *(float2*)op0 = make_float2(acc[mt][nt][0]*d0, acc[mt][nt][1]*d0);
                *(float2*)op1 = make_float2(acc[mt][nt][2]*d1, acc[mt][nt][3]*d1);
            }
        }
    }
}

// =====================================================================
// launch
// =====================================================================
extern "C" void kernel_launch(void* const* d_in, const int* in_sizes, int n_in,
                              void* d_out, int out_size)
{
    const float *x = nullptr, *wqkv = nullptr, *wout = nullptr,
                *bout = nullptr, *proj = nullptr;
    for (int i = 0; i < n_in; i++) {
        switch (in_sizes[i]) {
            case MTOK * DIMM:  x    = (const float*)d_in[i]; break;
            case QKVN * DIMM:  wqkv = (const float*)d_in[i]; break;
            case DIMM * DIMM:  wout = (const float*)d_in[i]; break;
            case DIMM:         bout = (const float*)d_in[i]; break;
            case NF * DHD:     proj = (const float*)d_in[i]; break;
        }
    }

    cudaFuncSetAttribute(feature_mma, cudaFuncAttributeMaxDynamicSharedMemorySize, FEAT_SMEM_BYTES);
    cudaFuncSetAttribute(ctx_out_mma, cudaFuncAttributeMaxDynamicSharedMemorySize, CO_SMEM_BYTES);

    float *qkvp = nullptr, *attp = nullptr;
    cudaGetSymbolAddress((void**)&qkvp, g_qkv);
    cudaGetSymbolAddress((void**)&attp, g_att);

    // 1) qkv = x @ w_qkv^T  (packed-fragment tf32)
    tgemm_nt<false><<<dim3(QKVN/128, MTOK/128), 256>>>(x, wqkv, nullptr, qkvp,
                                                       MTOK, QKVN, DIMM);
    // 2) q'/k' feature maps (single-pass tf32, packed fragments) + ksum
    feature_mma<<<dim3(NCHUNK, 2), 256, FEAT_SMEM_BYTES>>>(proj);
    // 3+4) fused ctx + out
    ctx_out_mma<<<NCHUNK, 256, CO_SMEM_BYTES>>>();
    // 5) final = att @ w_out^T + b_out  (packed-fragment tf32)
    tgemm_nt<true><<<dim3(DIMM/128, MTOK/128), 256>>>(attp, wout, bout,
                                                      (float*)d_out,
                                                      MTOK, DIMM, DIMM);
}

// round 6
// speedup vs baseline: 2.8674x; 1.0487x over previous
#include <cuda_runtime.h>
#include <cstdint>

// ---------------- problem constants ----------------
#define NB   4
#define SEQ  4096
#define DIMM 512
#define NH   8
#define DHD  64
#define NF   256
#define CSZ  128
#define NCH  32
#define MTOK (NB*SEQ)            // 16384
#define QKVN (3*DIMM)            // 1536
#define NCHUNK (NB*NH*NCH)       // 1024

// ---------------- device scratch ----------------
__device__ float g_qkv [MTOK * QKVN];
// q'/k' stored in fragment-packed per-chunk layouts (32768 u32 each chunk):
//  g_kp: [ks(16)][sub(16)][lane(32)][w(4)]  A-frags for P1 (m=f, k=s)
//  g_qp: [ks(32)][sub(8)][lane(32)][w(4)]   A-frags for P2 (m=s, k=f)
__device__ float g_qp  [NB*NH*SEQ*NF];
__device__ float g_kp  [NB*NH*SEQ*NF];
__device__ float g_ksum[NCHUNK * NF];
__device__ float g_att [MTOK * DIMM];

__device__ __forceinline__ uint32_t f2tf32(float f) {
    uint32_t r;
    asm("cvt.rna.tf32.f32 %0, %1;" : "=r"(r) : "f"(f));
    return r;
}

__device__ __forceinline__ void mma_tf32(float acc[4],
                                         uint32_t a0, uint32_t a1, uint32_t a2, uint32_t a3,
                                         uint32_t b0, uint32_t b1)
{
    asm volatile(
        "mma.sync.aligned.m16n8k8.row.col.f32.tf32.tf32.f32 "
        "{%0,%1,%2,%3}, {%4,%5,%6,%7}, {%8,%9}, {%0,%1,%2,%3};"
        : "+f"(acc[0]), "+f"(acc[1]), "+f"(acc[2]), "+f"(acc[3])
        : "r"(a0), "r"(a1), "r"(a2), "r"(a3), "r"(b0), "r"(b1));
}

// =====================================================================
// TF32 tensor-core GEMM NT with packed-fragment smem (unchanged; control)
// =====================================================================
template<bool BIAS>
__global__ __launch_bounds__(256, 2)
void tgemm_nt(const float* __restrict__ A, const float* __restrict__ Bm,
              const float* __restrict__ bias, float* __restrict__ C,
              int M, int N, int K)
{
    __shared__ __align__(16) uint32_t Apk[2][2][8][128];
    __shared__ __align__(16) uint32_t Bpk[2][2][16][64];

    const int tid  = threadIdx.x;
    const int lane = tid & 31;
    const int warp = tid >> 5;
    const int wsubA = (warp >> 1) * 2;
    const int wsubB = (warp & 1)  * 8;
    const int qr   = lane >> 2;
    const int qc   = lane & 3;

    const int bm = blockIdx.y * 128;
    const int bn = blockIdx.x * 128;

    const int lm  = tid >> 2;
    const int lk  = (tid & 3) * 4;
    const int wkg = lk >> 3;
    const int whi = (lk >> 2) & 1;
    const int qrw   = lm & 7;
    const int half  = (lm >> 3) & 1;
    const int subA0 = lm >> 4;
    const int nsub0 = lm >> 3;
    const int wrot  = ((qrw >> 1) + 2 * wkg) & 3;
    const int wordA = whi * 2 + half;

    const float* Ap = A  + (size_t)(bm + lm) * K + lk;
    const float* Bp = Bm + (size_t)(bn + lm) * K + lk;

    float acc[2][8][4];
#pragma unroll
    for (int mt = 0; mt < 2; mt++)
#pragma unroll
        for (int nt = 0; nt < 8; nt++)
#pragma unroll
            for (int c = 0; c < 4; c++) acc[mt][nt][c] = 0.f;

    float4 pa0 = *(const float4*)Ap;
    float4 pa1 = *(const float4*)(Ap + (size_t)64 * K);
    float4 pb0 = *(const float4*)Bp;
    float4 pb1 = *(const float4*)(Bp + (size_t)64 * K);

    auto stage = [&](int bf, const float4& a0, const float4& a1,
                     const float4& b0, const float4& b1) {
        uint32_t* ad0 = &Apk[bf][wkg][subA0    ][0];
        uint32_t* ad1 = &Apk[bf][wkg][subA0 + 4][0];
        uint32_t* bd0 = &Bpk[bf][wkg][nsub0    ][0];
        uint32_t* bd1 = &Bpk[bf][wkg][nsub0 + 8][0];
        const float* av0 = &a0.x;
        const float* av1 = &a1.x;
        const float* bv0 = &b0.x;
        const float* bv1 = &b1.x;
#pragma unroll
        for (int j = 0; j < 4; ++j) {
            const int lp = ((qrw << 2) | ((j + wrot) & 3));
            ad0[lp*4 + wordA] = f2tf32(av0[j]);
            ad1[lp*4 + wordA] = f2tf32(av1[j]);
            bd0[lp*2 + whi]   = f2tf32(bv0[j]);
            bd1[lp*2 + whi]   = f2tf32(bv1[j]);
        }
    };

    stage(0, pa0, pa1, pb0, pb1);
    __syncthreads();

    const int KT = K >> 4;
    for (int kt = 0; kt < KT; ++kt) {
        const int buf = kt & 1;
        if (kt + 1 < KT) {
            const float* Ap2 = Ap + (kt + 1) * 16;
            const float* Bp2 = Bp + (kt + 1) * 16;
            pa0 = *(const float4*)Ap2;
            pa1 = *(const float4*)(Ap2 + (size_t)64 * K);
            pb0 = *(const float4*)Bp2;
            pb1 = *(const float4*)(Bp2 + (size_t)64 * K);
        }
#pragma unroll
        for (int kg = 0; kg < 2; ++kg) {
            const int rlane = ((qr << 2) | ((qc + (qr >> 1) + 2*kg) & 3));
            uint4 a0 = *(const uint4*)&Apk[buf][kg][wsubA    ][rlane*4];
            uint4 a1 = *(const uint4*)&Apk[buf][kg][wsubA + 1][rlane*4];
            uint2 bb[8];
#pragma unroll
            for (int nt = 0; nt < 8; nt++)
                bb[nt] = *(const uint2*)&Bpk[buf][kg][wsubB + nt][rlane*2];
#pragma unroll
            for (int nt = 0; nt < 8; nt++) {
                mma_tf32(acc[0][nt], a0.x, a0.y, a0.z, a0.w, bb[nt].x, bb[nt].y);
                mma_tf32(acc[1][nt], a1.x, a1.y, a1.z, a1.w, bb[nt].x, bb[nt].y);
            }
        }
        if (kt + 1 < KT) {
            stage(buf ^ 1, pa0, pa1, pb0, pb1);
            __syncthreads();
        }
    }

#pragma unroll
    for (int mt = 0; mt < 2; mt++) {
        const int r0 = bm + (wsubA + mt) * 16 + qr;
#pragma unroll
        for (int nt = 0; nt < 8; nt++) {
            const int c0 = bn + (wsubB + nt) * 8 + 2*qc;
            float v0 = acc[mt][nt][0], v1 = acc[mt][nt][1];
            float v2 = acc[mt][nt][2], v3 = acc[mt][nt][3];
            if (BIAS) {
                const float b0 = __ldg(bias + c0), b1 = __ldg(bias + c0 + 1);
                v0 += b0; v1 += b1; v2 += b0; v3 += b1;
            }
            *(float2*)(C + (size_t)r0       * N + c0) = make_float2(v0, v1);
            *(float2*)(C + (size_t)(r0 + 8) * N + c0) = make_float2(v2, v3);
        }
    }
}

// =====================================================================
// Feature kernel, single-pass TF32, packed-fragment smem (R5 mainloop),
// NEW epilogue: stores q'/k' in fragment-packed GLOBAL layouts.
// sm_e stride: 264 for k' (banks 8qc+qr), 260 for q' (banks 4qr+qc).
// =====================================================================
#define APK_KS_STRIDE 1028
#define PPK_KS_STRIDE 2052
#define PPK_BASE      (8 * APK_KS_STRIDE)              // 8224
#define RMAX_BASE     33792                            // 128*264
#define FEAT_SMEM_BYTES ((33792 + 256) * 4)            // 136192

__global__ __launch_bounds__(256, 1)
void feature_mma(const float* __restrict__ proj)
{
    extern __shared__ uint32_t smu[];
    uint32_t* APK = smu;
    uint32_t* PPK = smu + PPK_BASE;
    float*    sm_e = (float*)smu;                 // alias (after MMA phase)
    float*    RMAX = (float*)(smu + RMAX_BASE);

    const int cid = blockIdx.x;
    const int isK = blockIdx.y;
    const int b  = cid >> 8;
    const int h  = (cid >> 5) & 7;
    const int cc = cid & 31;
    const size_t row0   = (size_t)b * SEQ + (size_t)cc * CSZ;
    const int   colbase = isK * DIMM + h * DHD;
    const float scale   = isK ? 1.0f : 0.125f;
    const int STR = isK ? 264 : 260;
    const int tid  = threadIdx.x;
    const int lane = tid & 31;
    const int warp = tid >> 5;
    const int wgm  = warp >> 1;
    const int fg   = warp & 1;
    const int qr   = lane >> 2;
    const int qc   = lane & 3;

    // ---- load t chunk [128 s][64 d] -> packed A fragments ----
#pragma unroll
    for (int it = 0; it < 8; ++it) {
        const int idx4 = it * 256 + tid;
        const int s  = idx4 >> 4;
        const int d4 = (idx4 & 15) * 4;
        float4 v = *(const float4*)(g_qkv + (row0 + s) * QKVN + colbase + d4);
        const int ks   = d4 >> 3;
        const int hi   = (d4 >> 2) & 1;
        const int sub  = s >> 4;
        const int qrS  = s & 7;
        const int halfS= (s >> 3) & 1;
        const int word = hi * 2 + halfS;
        uint32_t* base = APK + ks * APK_KS_STRIDE + sub * 128 + (qrS << 4);
        base[0*4 + word] = f2tf32(v.x * scale);
        base[1*4 + word] = f2tf32(v.y * scale);
        base[2*4 + word] = f2tf32(v.z * scale);
        base[3*4 + word] = f2tf32(v.w * scale);
    }
    // ---- load proj [256 f][64 d] -> packed B fragments ----
#pragma unroll
    for (int it = 0; it < 16; ++it) {
        const int idx4 = it * 256 + tid;
        const int f  = idx4 >> 4;
        const int d4 = (idx4 & 15) * 4;
        float4 v = *(const float4*)(proj + f * DHD + d4);
        const int ks   = d4 >> 3;
        const int hi   = (d4 >> 2) & 1;
        const int nsub = f >> 3;
        const int qrF  = f & 7;
        uint32_t* base = PPK + ks * PPK_KS_STRIDE + nsub * 64 + (qrF << 3);
        base[0*2 + hi] = f2tf32(v.x);
        base[1*2 + hi] = f2tf32(v.y);
        base[2*2 + hi] = f2tf32(v.z);
        base[3*2 + hi] = f2tf32(v.w);
    }
    __syncthreads();

    float acc[2][16][4];
#pragma unroll
    for (int mt = 0; mt < 2; mt++)
#pragma unroll
        for (int nt = 0; nt < 16; nt++)
#pragma unroll
            for (int c = 0; c < 4; c++) acc[mt][nt][c] = 0.f;

    const int rl4 = lane * 4;
    const int rl2 = lane * 2;
#pragma unroll
    for (int ks = 0; ks < 8; ++ks) {
        const uint32_t* abase = APK + ks * APK_KS_STRIDE;
        const uint32_t* pbase = PPK + ks * PPK_KS_STRIDE;
        uint4 a0 = *(const uint4*)&abase[(wgm*2 + 0) * 128 + rl4];
        uint4 a1 = *(const uint4*)&abase[(wgm*2 + 1) * 128 + rl4];
#pragma unroll
        for (int nt = 0; nt < 16; nt++) {
            uint2 bb = *(const uint2*)&pbase[(fg*16 + nt) * 64 + rl2];
            mma_tf32(acc[0][nt], a0.x, a0.y, a0.z, a0.w, bb.x, bb.y);
            mma_tf32(acc[1][nt], a1.x, a1.y, a1.z, a1.w, bb.x, bb.y);
        }
    }

    // rowmax
    float mloc[2][2];
#pragma unroll
    for (int mt = 0; mt < 2; mt++)
#pragma unroll
        for (int hh = 0; hh < 2; hh++) {
            float m = -1e30f;
#pragma unroll
            for (int nt = 0; nt < 16; nt++) {
                m = fmaxf(m, acc[mt][nt][hh*2+0]);
                m = fmaxf(m, acc[mt][nt][hh*2+1]);
            }
            m = fmaxf(m, __shfl_xor_sync(0xffffffffu, m, 1));
            m = fmaxf(m, __shfl_xor_sync(0xffffffffu, m, 2));
            mloc[mt][hh] = m;
        }
    if (qc == 0) {
#pragma unroll
        for (int mt = 0; mt < 2; mt++)
#pragma unroll
            for (int hh = 0; hh < 2; hh++)
                RMAX[fg*128 + wgm*32 + mt*16 + hh*8 + qr] = mloc[mt][hh];
    }
    __syncthreads();

    float rm[2][2];
#pragma unroll
    for (int mt = 0; mt < 2; mt++)
#pragma unroll
        for (int hh = 0; hh < 2; hh++) {
            const int row = wgm*32 + mt*16 + hh*8 + qr;
            rm[mt][hh] = fmaxf(RMAX[row], RMAX[128 + row]);
        }

    // exp + tf32-round, stage into sm_e[row][STR]
#pragma unroll
    for (int mt = 0; mt < 2; mt++)
#pragma unroll
        for (int hh = 0; hh < 2; hh++) {
            const int row = wgm*32 + mt*16 + hh*8 + qr;
#pragma unroll
            for (int nt = 0; nt < 16; nt++) {
                const int f = fg*128 + nt*8 + 2*qc;
                float e0 = __expf(acc[mt][nt][hh*2+0] - rm[mt][hh]);
                float e1 = __expf(acc[mt][nt][hh*2+1] - rm[mt][hh]);
                sm_e[row*STR + f]     = __uint_as_float(f2tf32(e0));
                sm_e[row*STR + f + 1] = __uint_as_float(f2tf32(e1));
            }
        }
    __syncthreads();

    if (isK) {
        // k' -> packed A-frags for P1 (m=f, k=s): [ks16][sub16][lane][w4]
        uint32_t* outp = (uint32_t*)g_kp + (size_t)cid * 32768;
#pragma unroll
        for (int it = 0; it < 32; ++it) {
            const int gid = it * 256 + tid;
            const int ln  = gid & 31;
            const int sub = (gid >> 5) & 15;
            const int ks  = gid >> 9;
            const int qc2 = ln & 3, qr2 = ln >> 2;
            const int s0 = ks*8 + qc2, f0 = sub*16 + qr2;
            uint4 u;
            u.x = __float_as_uint(sm_e[s0*264 + f0]);
            u.y = __float_as_uint(sm_e[s0*264 + f0 + 8]);
            u.z = __float_as_uint(sm_e[(s0+4)*264 + f0]);
            u.w = __float_as_uint(sm_e[(s0+4)*264 + f0 + 8]);
            *(uint4*)(outp + (size_t)gid * 4) = u;
        }
        // ksum
        float s = 0.f;
#pragma unroll 8
        for (int r = 0; r < CSZ; ++r) s += sm_e[r*264 + tid];
        g_ksum[(size_t)cid * NF + tid] = s;
    } else {
        // q' -> packed A-frags for P2 (m=s, k=f): [ks32][sub8][lane][w4]
        uint32_t* outp = (uint32_t*)g_qp + (size_t)cid * 32768;
#pragma unroll
        for (int it = 0; it < 32; ++it) {
            const int gid = it * 256 + tid;
            const int ln  = gid & 31;
            const int sub = (gid >> 5) & 7;
            const int ks  = gid >> 8;
            const int qc2 = ln & 3, qr2 = ln >> 2;
            const int r0 = sub*16 + qr2, f0 = ks*8 + qc2;
            uint4 u;
            u.x = __float_as_uint(sm_e[r0*260 + f0]);
            u.y = __float_as_uint(sm_e[(r0+8)*260 + f0]);
            u.z = __float_as_uint(sm_e[r0*260 + f0 + 4]);
            u.w = __float_as_uint(sm_e[(r0+8)*260 + f0 + 4]);
            *(uint4*)(outp + (size_t)gid * 4) = u;
        }
    }
}

// =====================================================================
// Fused ctx + out kernel v2 — all operands fragment-packed.
// P1: ctx[f][d] = sum_s k'[s][f] v[s][d]   (A=k' packed, B=v packed)
// P2: out[s][d] = (q' @ ctx) * Dinv ; D folded in as extra MMA vs ksum.
// smem (u32): KPs@0(32768) | VBp@32768(4096) | vpl@36864(9216)
//   then CBp@0(16384, alias) | QBs@16384(32768) | SKu@49152(256)
// =====================================================================
#define CO_SMEM_BYTES (49408 * 4)     // 197632

__global__ __launch_bounds__(256, 1)
void ctx_out_mma()
{
    extern __shared__ uint32_t smu[];
    uint32_t* KPs = smu;
    uint32_t* VBp = smu + 32768;
    float*    vpl = (float*)(smu + 36864);
    uint32_t* CBp = smu;
    uint32_t* QBs = smu + 16384;
    uint32_t* SKu = smu + 49152;

    const int cid = blockIdx.x;
    const int b  = cid >> 8;
    const int h  = (cid >> 5) & 7;
    const int cc = cid & 31;
    const size_t row0 = (size_t)b * SEQ + (size_t)cc * CSZ;
    const int vcol = 2 * DIMM + h * DHD;
    const int tid  = threadIdx.x;
    const int lane = tid & 31;
    const int warp = tid >> 5;
    const int qr   = lane >> 2;
    const int qc   = lane & 3;

    // ---- load packed k' (straight copy) ----
    {
        const uint4* src = (const uint4*)((const float*)g_kp + (size_t)cid * 32768);
        uint4* dst = (uint4*)KPs;
#pragma unroll
        for (int it = 0; it < 32; ++it)
            dst[it*256 + tid] = src[it*256 + tid];
    }
    // ---- load v into plain tile [s][72] ----
#pragma unroll
    for (int it = 0; it < 8; ++it) {
        const int idx4 = it * 256 + tid;
        const int s  = idx4 >> 4;
        const int d4 = (idx4 & 15) * 4;
        *(float4*)(vpl + s*72 + d4) =
            *(const float4*)(g_qkv + (row0 + s) * QKVN + vcol + d4);
    }
    SKu[tid] = f2tf32(g_ksum[(size_t)cid * NF + tid]);
    __syncthreads();

    // ---- pack v into B-frags [ks16][nsub8][lane][w2] ----
#pragma unroll
    for (int it = 0; it < 16; ++it) {
        const int wid2 = it * 256 + tid;       // 0..4095
        const int ln   = wid2 & 31;
        const int nsub = (wid2 >> 5) & 7;
        const int ks   = wid2 >> 8;
        const int qc2 = ln & 3, qr2 = ln >> 2;
        const int s0 = ks*8 + qc2, d0 = nsub*8 + qr2;
        uint2 u;
        u.x = f2tf32(vpl[s0*72 + d0]);
        u.y = f2tf32(vpl[(s0+4)*72 + d0]);
        *(uint2*)(VBp + wid2*2) = u;
    }
    __syncthreads();

    // ---- P1: ctx (warp w -> f subs {2w,2w+1}) ----
    float acc[2][8][4];
#pragma unroll
    for (int mt = 0; mt < 2; mt++)
#pragma unroll
        for (int nt = 0; nt < 8; nt++)
#pragma unroll
            for (int c = 0; c < 4; c++) acc[mt][nt][c] = 0.f;

#pragma unroll 4
    for (int ks = 0; ks < 16; ++ks) {
        const uint32_t* ab = KPs + ks*2048;
        uint4 a0 = *(const uint4*)(ab + (warp*2 + 0)*128 + lane*4);
        uint4 a1 = *(const uint4*)(ab + (warp*2 + 1)*128 + lane*4);
#pragma unroll
        for (int nt = 0; nt < 8; nt++) {
            uint2 bb = *(const uint2*)(VBp + ks*512 + nt*64 + lane*2);
            mma_tf32(acc[0][nt], a0.x, a0.y, a0.z, a0.w, bb.x, bb.y);
            mma_tf32(acc[1][nt], a1.x, a1.y, a1.z, a1.w, bb.x, bb.y);
        }
    }
    __syncthreads();   // KPs reads done before CBp alias-write

    // ---- scatter ctx -> B-frags for P2: [ks32][nsub8][lane][w2] ----
#pragma unroll
    for (int mt = 0; mt < 2; mt++)
#pragma unroll
        for (int nt = 0; nt < 8; nt++)
#pragma unroll
            for (int c = 0; c < 4; c++) {
                const int f = warp*32 + mt*16 + qr + ((c & 2) << 2);
                const int d = nt*8 + 2*qc + (c & 1);
                CBp[(f>>3)*512 + (d>>3)*64 + ((d&7)*4 + (f&3))*2 + ((f>>2)&1)]
                    = f2tf32(acc[mt][nt][c]);
            }

    // ---- load packed q' (straight copy) ----
    {
        const uint4* src = (const uint4*)((const float*)g_qp + (size_t)cid * 32768);
        uint4* dst = (uint4*)QBs;
#pragma unroll
        for (int it = 0; it < 32; ++it)
            dst[it*256 + tid] = src[it*256 + tid];
    }
    __syncthreads();

    // ---- P2: out + D (warps: mg(4) x ng(2)) ----
    const int mg = warp >> 1;
    const int ng = warp & 1;
    float acc2[2][4][4];
    float accD[2][4];
#pragma unroll
    for (int mt = 0; mt < 2; mt++) {
#pragma unroll
        for (int c = 0; c < 4; c++) accD[mt][c] = 0.f;
#pragma unroll
        for (int nt = 0; nt < 4; nt++)
#pragma unroll
            for (int c = 0; c < 4; c++) acc2[mt][nt][c] = 0.f;
    }

#pragma unroll 4
    for (int ks = 0; ks < 32; ++ks) {
        const uint32_t* qb = QBs + ks*1024;
        uint4 a0 = *(const uint4*)(qb + (mg*2 + 0)*128 + lane*4);
        uint4 a1 = *(const uint4*)(qb + (mg*2 + 1)*128 + lane*4);
        const uint32_t sb0 = SKu[ks*8 + qc];
        const uint32_t sb1 = SKu[ks*8 + qc + 4];
#pragma unroll
        for (int nt = 0; nt < 4; nt++) {
            uint2 bb = *(const uint2*)(CBp + ks*512 + (ng*4 + nt)*64 + lane*2);
            mma_tf32(acc2[0][nt], a0.x, a0.y, a0.z, a0.w, bb.x, bb.y);
            mma_tf32(acc2[1][nt], a1.x, a1.y, a1.z, a1.w, bb.x, bb.y);
        }
        mma_tf32(accD[0], a0.x, a0.y, a0.z, a0.w, sb0, sb1);
        mma_tf32(accD[1], a1.x, a1.y, a1.z, a1.w, sb0, sb1);
    }

    // ---- normalize + store ----
#pragma unroll
    for (int mt = 0; mt < 2; mt++) {
        const int r0 = mg*32 + mt*16 + qr;
        const float d0 = 1.0f / (accD[mt][0] + 1e-4f);
        const float d1 = 1.0f / (accD[mt][2] + 1e-4f);
#pragma unroll
        for (int nt = 0; nt < 4; nt++) {
            const int col = (ng*4 + nt)*8 + 2*qc;
            float* op0 = g_att + (row0 + r0)     * DIMM + h*DHD + col;
            float* op1 = g_att + (row0 + r0 + 8) * DIMM + h*DHD + col;
            *(float2*)op0 = make_float2(acc2[mt][nt][0]*d0, acc2[mt][nt][1]*d0);
            *(float2*)op1 = make_float2(acc2[mt][nt][2]*d1, acc2[mt][nt][3]*d1);
        }
    }
}

// =====================================================================
// launch
// =====================================================================
extern "C" void kernel_launch(void* const* d_in, const int* in_sizes, int n_in,
                              void* d_out, int out_size)
{
    const float *x = nullptr, *wqkv = nullptr, *wout = nullptr,
                *bout = nullptr, *proj = nullptr;
    for (int i = 0; i < n_in; i++) {
        switch (in_sizes[i]) {
            case MTOK * DIMM:  x    = (const float*)d_in[i]; break;
            case QKVN * DIMM:  wqkv = (const float*)d_in[i]; break;
            case DIMM * DIMM:  wout = (const float*)d_in[i]; break;
            case DIMM:         bout = (const float*)d_in[i]; break;
            case NF * DHD:     proj = (const float*)d_in[i]; break;
        }
    }

    cudaFuncSetAttribute(feature_mma, cudaFuncAttributeMaxDynamicSharedMemorySize, FEAT_SMEM_BYTES);
    cudaFuncSetAttribute(ctx_out_mma, cudaFuncAttributeMaxDynamicSharedMemorySize, CO_SMEM_BYTES);

    float *qkvp = nullptr, *attp = nullptr;
    cudaGetSymbolAddress((void**)&qkvp, g_qkv);
    cudaGetSymbolAddress((void**)&attp, g_att);

    // 1) qkv = x @ w_qkv^T
    tgemm_nt<false><<<dim3(QKVN/128, MTOK/128), 256>>>(x, wqkv, nullptr, qkvp,
                                                       MTOK, QKVN, DIMM);
    // 2) q'/k' feature maps -> fragment-packed global layouts (+ksum)
    feature_mma<<<dim3(NCHUNK, 2), 256, FEAT_SMEM_BYTES>>>(proj);
    // 3+4) fused ctx + out, fully packed operands
    ctx_out_mma<<<NCHUNK, 256, CO_SMEM_BYTES>>>();
    // 5) final = att @ w_out^T + b_out
    tgemm_nt<true><<<dim3(DIMM/128, MTOK/128), 256>>>(attp, wout, bout,
                                                      (float*)d_out,
                                                      MTOK, DIMM, DIMM);
}

// round 8
// speedup vs baseline: 2.9175x; 1.0175x over previous
#include <cuda_runtime.h>
#include <cstdint>

// ---------------- problem constants ----------------
#define NB   4
#define SEQ  4096
#define DIMM 512
#define NH   8
#define DHD  64
#define NF   256
#define CSZ  128
#define NCH  32
#define MTOK (NB*SEQ)            // 16384
#define QKVN (3*DIMM)            // 1536
#define NCHUNK (NB*NH*NCH)       // 1024

// ---------------- device scratch ----------------
__device__ float g_qkv [MTOK * QKVN];
// q'/k' fragment-packed per-chunk (32768 u32 each chunk) — see feature_mma
__device__ float g_qp  [NB*NH*SEQ*NF];
__device__ float g_kp  [NB*NH*SEQ*NF];
__device__ float g_ksum[NCHUNK * NF];
__device__ float g_att [MTOK * DIMM];    // tf32-rounded at source
// tf32-pre-rounded copies of GEMM operands
__device__ float g_xr  [MTOK * DIMM];
__device__ float g_wqr [QKVN * DIMM];
__device__ float g_wor [DIMM * DIMM];

__device__ __forceinline__ uint32_t f2tf32(float f) {
    uint32_t r;
    asm("cvt.rna.tf32.f32 %0, %1;" : "=r"(r) : "f"(f));
    return r;
}

__device__ __forceinline__ void mma_tf32(float acc[4],
                                         uint32_t a0, uint32_t a1, uint32_t a2, uint32_t a3,
                                         uint32_t b0, uint32_t b1)
{
    asm volatile(
        "mma.sync.aligned.m16n8k8.row.col.f32.tf32.tf32.f32 "
        "{%0,%1,%2,%3}, {%4,%5,%6,%7}, {%8,%9}, {%0,%1,%2,%3};"
        : "+f"(acc[0]), "+f"(acc[1]), "+f"(acc[2]), "+f"(acc[3])
        : "r"(a0), "r"(a1), "r"(a2), "r"(a3), "r"(b0), "r"(b1));
}

// =====================================================================
// cvt_tf32: elementwise tf32 rounding pass (bandwidth-bound, tiny)
// =====================================================================
__global__ void cvt_tf32(const float4* __restrict__ src, float4* __restrict__ dst, int n4)
{
    int i = blockIdx.x * blockDim.x + threadIdx.x;
    if (i >= n4) return;
    float4 v = src[i];
    dst[i] = make_float4(__uint_as_float(f2tf32(v.x)),
                         __uint_as_float(f2tf32(v.y)),
                         __uint_as_float(f2tf32(v.z)),
                         __uint_as_float(f2tf32(v.w)));
}

// =====================================================================
// TF32 GEMM NT, tile 128(m) x 256(n), BK=16, 256 threads (8 warps, 2x4),
// warp tile 64x64 (4 msubs x 8 nsubs), packed-fragment smem, dbl-buffered.
// Inputs pre-rounded to tf32 -> staging is a pure bit copy.
// smem (u32): A frags [buf2][kg2][sub8][lane32][w4]  = 4096
//             B frags @4096 [buf2][kg2][nsub32][lane32][w2] = 8192
// total 12288 u32 = 49152 B
// =====================================================================
#define TG_SMEM_BYTES 49152

template<bool BIAS>
__global__ __launch_bounds__(256, 1)
void tgemm_nt(const float* __restrict__ A, const float* __restrict__ Bm,
              const float* __restrict__ bias, float* __restrict__ C,
              int M, int N, int K)
{
    extern __shared__ uint32_t smg[];

    const int tid  = threadIdx.x;
    const int lane = tid & 31;
    const int warp = tid >> 5;
    const int mg   = warp >> 2;          // 0..1 : m 64 each
    const int ng   = warp & 3;           // 0..3 : n 64 each
    const int qr   = lane >> 2;
    const int qc   = lane & 3;

    const int bm = blockIdx.y * 128;
    const int bn = blockIdx.x * 256;

    // writer decomposition
    const int lm   = tid >> 2;           // 0..63
    const int lk   = (tid & 3) * 4;      // {0,4,8,12}
    const int wkg  = lk >> 3;
    const int whi  = (lk >> 2) & 1;
    const int qrw  = lm & 7;
    const int half = (lm >> 3) & 1;
    const int subA0  = lm >> 4;          // 0..3 (+4 for rowset2)
    const int nsubB0 = lm >> 3;          // 0..7 (+8/+16/+24)
    const int wrot  = ((qrw >> 1) + 2 * wkg) & 3;
    const int wordA = whi * 2 + half;

    const uint32_t* Ap = (const uint32_t*)A  + (size_t)(bm + lm) * K + lk;
    const uint32_t* Bp = (const uint32_t*)Bm + (size_t)(bn + lm) * K + lk;

    float acc[4][8][4];
#pragma unroll
    for (int i = 0; i < 4; i++)
#pragma unroll
        for (int nt = 0; nt < 8; nt++)
#pragma unroll
            for (int c = 0; c < 4; c++) acc[i][nt][c] = 0.f;

    uint4 pa0, pa1, pb0, pb1, pb2, pb3;
    pa0 = *(const uint4*)Ap;
    pa1 = *(const uint4*)(Ap + (size_t)64  * K);
    pb0 = *(const uint4*)Bp;
    pb1 = *(const uint4*)(Bp + (size_t)64  * K);
    pb2 = *(const uint4*)(Bp + (size_t)128 * K);
    pb3 = *(const uint4*)(Bp + (size_t)192 * K);

    auto stage = [&](int bf) {
        uint32_t* ab = smg + ((bf*2 + wkg) * 8) * 128;
        uint32_t* bb = smg + 4096 + ((bf*2 + wkg) * 32) * 64;
        const uint32_t* av0 = &pa0.x;
        const uint32_t* av1 = &pa1.x;
        const uint32_t* bv0 = &pb0.x;
        const uint32_t* bv1 = &pb1.x;
        const uint32_t* bv2 = &pb2.x;
        const uint32_t* bv3 = &pb3.x;
#pragma unroll
        for (int j = 0; j < 4; ++j) {
            const int lp = ((qrw << 2) | ((j + wrot) & 3));
            ab[(subA0    ) * 128 + lp*4 + wordA] = av0[j];
            ab[(subA0 + 4) * 128 + lp*4 + wordA] = av1[j];
            bb[(nsubB0     ) * 64 + lp*2 + whi] = bv0[j];
            bb[(nsubB0 +  8) * 64 + lp*2 + whi] = bv1[j];
            bb[(nsubB0 + 16) * 64 + lp*2 + whi] = bv2[j];
            bb[(nsubB0 + 24) * 64 + lp*2 + whi] = bv3[j];
        }
    };

    stage(0);
    __syncthreads();

    const int KT = K >> 4;
    for (int kt = 0; kt < KT; ++kt) {
        const int buf = kt & 1;
        if (kt + 1 < KT) {
            const uint32_t* Ap2 = Ap + (kt + 1) * 16;
            const uint32_t* Bp2 = Bp + (kt + 1) * 16;
            pa0 = *(const uint4*)Ap2;
            pa1 = *(const uint4*)(Ap2 + (size_t)64  * K);
            pb0 = *(const uint4*)Bp2;
            pb1 = *(const uint4*)(Bp2 + (size_t)64  * K);
            pb2 = *(const uint4*)(Bp2 + (size_t)128 * K);
            pb3 = *(const uint4*)(Bp2 + (size_t)192 * K);
        }
#pragma unroll
        for (int kg = 0; kg < 2; ++kg) {
            const int rlane = ((qr << 2) | ((qc + (qr >> 1) + 2*kg) & 3));
            const uint32_t* ab = smg + ((buf*2 + kg) * 8) * 128;
            const uint32_t* bb = smg + 4096 + ((buf*2 + kg) * 32) * 64;
            uint4 a[4];
#pragma unroll
            for (int i = 0; i < 4; i++)
                a[i] = *(const uint4*)&ab[(mg*4 + i) * 128 + rlane*4];
            uint2 bf[8];
#pragma unroll
            for (int nt = 0; nt < 8; nt++)
                bf[nt] = *(const uint2*)&bb[(ng*8 + nt) * 64 + rlane*2];
#pragma unroll
            for (int i = 0; i < 4; i++)
#pragma unroll
                for (int nt = 0; nt < 8; nt++)
                    mma_tf32(acc[i][nt], a[i].x, a[i].y, a[i].z, a[i].w,
                             bf[nt].x, bf[nt].y);
        }
        if (kt + 1 < KT) {
            stage(buf ^ 1);
            __syncthreads();
        }
    }

    // epilogue
#pragma unroll
    for (int i = 0; i < 4; i++) {
        const int r0 = bm + (mg*4 + i) * 16 + qr;
#pragma unroll
        for (int nt = 0; nt < 8; nt++) {
            const int c0 = bn + (ng*8 + nt) * 8 + 2*qc;
            float v0 = acc[i][nt][0], v1 = acc[i][nt][1];
            float v2 = acc[i][nt][2], v3 = acc[i][nt][3];
            if (BIAS) {
                const float b0 = __ldg(bias + c0), b1 = __ldg(bias + c0 + 1);
                v0 += b0; v1 += b1; v2 += b0; v3 += b1;
            }
            *(float2*)(C + (size_t)r0       * N + c0) = make_float2(v0, v1);
            *(float2*)(C + (size_t)(r0 + 8) * N + c0) = make_float2(v2, v3);
        }
    }
}

// =====================================================================
// Feature kernel (unchanged from R6): single-pass tf32 mma,
// emits fragment-packed q'/k' + ksum.
// =====================================================================
#define APK_KS_STRIDE 1028
#define PPK_KS_STRIDE 2052
#define PPK_BASE      (8 * APK_KS_STRIDE)
#define RMAX_BASE     33792
#define FEAT_SMEM_BYTES ((33792 + 256) * 4)

__global__ __launch_bounds__(256, 1)
void feature_mma(const float* __restrict__ proj)
{
    extern __shared__ uint32_t smu[];
    uint32_t* APK = smu;
    uint32_t* PPK = smu + PPK_BASE;
    float*    sm_e = (float*)smu;
    float*    RMAX = (float*)(smu + RMAX_BASE);

    const int cid = blockIdx.x;
    const int isK = blockIdx.y;
    const int b  = cid >> 8;
    const int h  = (cid >> 5) & 7;
    const int cc = cid & 31;
    const size_t row0   = (size_t)b * SEQ + (size_t)cc * CSZ;
    const int   colbase = isK * DIMM + h * DHD;
    const float scale   = isK ? 1.0f : 0.125f;
    const int STR = isK ? 264 : 260;
    const int tid  = threadIdx.x;
    const int lane = tid & 31;
    const int warp = tid >> 5;
    const int wgm  = warp >> 1;
    const int fg   = warp & 1;
    const int qr   = lane >> 2;
    const int qc   = lane & 3;

#pragma unroll
    for (int it = 0; it < 8; ++it) {
        const int idx4 = it * 256 + tid;
        const int s  = idx4 >> 4;
        const int d4 = (idx4 & 15) * 4;
        float4 v = *(const float4*)(g_qkv + (row0 + s) * QKVN + colbase + d4);
        const int ks   = d4 >> 3;
        const int hi   = (d4 >> 2) & 1;
        const int sub  = s >> 4;
        const int qrS  = s & 7;
        const int halfS= (s >> 3) & 1;
        const int word = hi * 2 + halfS;
        uint32_t* base = APK + ks * APK_KS_STRIDE + sub * 128 + (qrS << 4);
        base[0*4 + word] = f2tf32(v.x * scale);
        base[1*4 + word] = f2tf32(v.y * scale);
        base[2*4 + word] = f2tf32(v.z * scale);
        base[3*4 + word] = f2tf32(v.w * scale);
    }
#pragma unroll
    for (int it = 0; it < 16; ++it) {
        const int idx4 = it * 256 + tid;
        const int f  = idx4 >> 4;
        const int d4 = (idx4 & 15) * 4;
        float4 v = *(const float4*)(proj + f * DHD + d4);
        const int ks   = d4 >> 3;
        const int hi   = (d4 >> 2) & 1;
        const int nsub = f >> 3;
        const int qrF  = f & 7;
        uint32_t* base = PPK + ks * PPK_KS_STRIDE + nsub * 64 + (qrF << 3);
        base[0*2 + hi] = f2tf32(v.x);
        base[1*2 + hi] = f2tf32(v.y);
        base[2*2 + hi] = f2tf32(v.z);
        base[3*2 + hi] = f2tf32(v.w);
    }
    __syncthreads();

    float acc[2][16][4];
#pragma unroll
    for (int mt = 0; mt < 2; mt++)
#pragma unroll
        for (int nt = 0; nt < 16; nt++)
#pragma unroll
            for (int c = 0; c < 4; c++) acc[mt][nt][c] = 0.f;

    const int rl4 = lane * 4;
    const int rl2 = lane * 2;
#pragma unroll
    for (int ks = 0; ks < 8; ++ks) {
        const uint32_t* abase = APK + ks * APK_KS_STRIDE;
        const uint32_t* pbase = PPK + ks * PPK_KS_STRIDE;
        uint4 a0 = *(const uint4*)&abase[(wgm*2 + 0) * 128 + rl4];
        uint4 a1 = *(const uint4*)&abase[(wgm*2 + 1) * 128 + rl4];
#pragma unroll
        for (int nt = 0; nt < 16; nt++) {
            uint2 bb = *(const uint2*)&pbase[(fg*16 + nt) * 64 + rl2];
            mma_tf32(acc[0][nt], a0.x, a0.y, a0.z, a0.w, bb.x, bb.y);
            mma_tf32(acc[1][nt], a1.x, a1.y, a1.z, a1.w, bb.x, bb.y);
        }
    }

    float mloc[2][2];
#pragma unroll
    for (int mt = 0; mt < 2; mt++)
#pragma unroll
        for (int hh = 0; hh < 2; hh++) {
            float m = -1e30f;
#pragma unroll
            for (int nt = 0; nt < 16; nt++) {
                m = fmaxf(m, acc[mt][nt][hh*2+0]);
                m = fmaxf(m, acc[mt][nt][hh*2+1]);
            }
            m = fmaxf(m, __shfl_xor_sync(0xffffffffu, m, 1));
            m = fmaxf(m, __shfl_xor_sync(0xffffffffu, m, 2));
            mloc[mt][hh] = m;
        }
    if (qc == 0) {
#pragma unroll
        for (int mt = 0; mt < 2; mt++)
#pragma unroll
            for (int hh = 0; hh < 2; hh++)
                RMAX[fg*128 + wgm*32 + mt*16 + hh*8 + qr] = mloc[mt][hh];
    }
    __syncthreads();

    float rm[2][2];
#pragma unroll
    for (int mt = 0; mt < 2; mt++)
#pragma unroll
        for (int hh = 0; hh < 2; hh++) {
            const int row = wgm*32 + mt*16 + hh*8 + qr;
            rm[mt][hh] = fmaxf(RMAX[row], RMAX[128 + row]);
        }

#pragma unroll
    for (int mt = 0; mt < 2; mt++)
#pragma unroll
        for (int hh = 0; hh < 2; hh++) {
            const int row = wgm*32 + mt*16 + hh*8 + qr;
#pragma unroll
            for (int nt = 0; nt < 16; nt++) {
                const int f = fg*128 + nt*8 + 2*qc;
                float e0 = __expf(acc[mt][nt][hh*2+0] - rm[mt][hh]);
                float e1 = __expf(acc[mt][nt][hh*2+1] - rm[mt][hh]);
                sm_e[row*STR + f]     = __uint_as_float(f2tf32(e0));
                sm_e[row*STR + f + 1] = __uint_as_float(f2tf32(e1));
            }
        }
    __syncthreads();

    if (isK) {
        uint32_t* outp = (uint32_t*)g_kp + (size_t)cid * 32768;
#pragma unroll
        for (int it = 0; it < 32; ++it) {
            const int gid = it * 256 + tid;
            const int ln  = gid & 31;
            const int sub = (gid >> 5) & 15;
            const int ks  = gid >> 9;
            const int qc2 = ln & 3, qr2 = ln >> 2;
            const int s0 = ks*8 + qc2, f0 = sub*16 + qr2;
            uint4 u;
            u.x = __float_as_uint(sm_e[s0*264 + f0]);
            u.y = __float_as_uint(sm_e[s0*264 + f0 + 8]);
            u.z = __float_as_uint(sm_e[(s0+4)*264 + f0]);
            u.w = __float_as_uint(sm_e[(s0+4)*264 + f0 + 8]);
            *(uint4*)(outp + (size_t)gid * 4) = u;
        }
        float s = 0.f;
#pragma unroll 8
        for (int r = 0; r < CSZ; ++r) s += sm_e[r*264 + tid];
        g_ksum[(size_t)cid * NF + tid] = s;
    } else {
        uint32_t* outp = (uint32_t*)g_qp + (size_t)cid * 32768;
#pragma unroll
        for (int it = 0; it < 32; ++it) {
            const int gid = it * 256 + tid;
            const int ln  = gid & 31;
            const int sub = (gid >> 5) & 7;
            const int ks  = gid >> 8;
            const int qc2 = ln & 3, qr2 = ln >> 2;
            const int r0 = sub*16 + qr2, f0 = ks*8 + qc2;
            uint4 u;
            u.x = __float_as_uint(sm_e[r0*260 + f0]);
            u.y = __float_as_uint(sm_e[(r0+8)*260 + f0]);
            u.z = __float_as_uint(sm_e[r0*260 + f0 + 4]);
            u.w = __float_as_uint(sm_e[(r0+8)*260 + f0 + 4]);
            *(uint4*)(outp + (size_t)gid * 4) = u;
        }
    }
}

// =====================================================================
// Fused ctx + out kernel (R6 structure), epilogue rounds att to tf32.
// =====================================================================
#define CO_SMEM_BYTES (49408 * 4)

__global__ __launch_bounds__(256, 1)
void ctx_out_mma()
{
    extern __shared__ uint32_t smu[];
    uint32_t* KPs = smu;
    uint32_t* VBp = smu + 32768;
    float*    vpl = (float*)(smu + 36864);
    uint32_t* CBp = smu;
    uint32_t* QBs = smu + 16384;
    uint32_t* SKu = smu + 49152;

    const int cid = blockIdx.x;
    const int b  = cid >> 8;
    const int h  = (cid >> 5) & 7;
    const int cc = cid & 31;
    const size_t row0 = (size_t)b * SEQ + (size_t)cc * CSZ;
    const int vcol = 2 * DIMM + h * DHD;
    const int tid  = threadIdx.x;
    const int lane = tid & 31;
    const int warp = tid >> 5;
    const int qr   = lane >> 2;
    const int qc   = lane & 3;

    {
        const uint4* src = (const uint4*)((const float*)g_kp + (size_t)cid * 32768);
        uint4* dst = (uint4*)KPs;
#pragma unroll
        for (int it = 0; it < 32; ++it)
            dst[it*256 + tid] = src[it*256 + tid];
    }
#pragma unroll
    for (int it = 0; it < 8; ++it) {
        const int idx4 = it * 256 + tid;
        const int s  = idx4 >> 4;
        const int d4 = (idx4 & 15) * 4;
        *(float4*)(vpl + s*72 + d4) =
            *(const float4*)(g_qkv + (row0 + s) * QKVN + vcol + d4);
    }
    SKu[tid] = f2tf32(g_ksum[(size_t)cid * NF + tid]);
    __syncthreads();

#pragma unroll
    for (int it = 0; it < 16; ++it) {
        const int wid2 = it * 256 + tid;
        const int ln   = wid2 & 31;
        const int nsub = (wid2 >> 5) & 7;
        const int ks   = wid2 >> 8;
        const int qc2 = ln & 3, qr2 = ln >> 2;
        const int s0 = ks*8 + qc2, d0 = nsub*8 + qr2;
        uint2 u;
        u.x = f2tf32(vpl[s0*72 + d0]);
        u.y = f2tf32(vpl[(s0+4)*72 + d0]);
        *(uint2*)(VBp + wid2*2) = u;
    }
    __syncthreads();

    float acc[2][8][4];
#pragma unroll
    for (int mt = 0; mt < 2; mt++)
#pragma unroll
        for (int nt = 0; nt < 8; nt++)
#pragma unroll
            for (int c = 0; c < 4; c++) acc[mt][nt][c] = 0.f;

#pragma unroll 4
    for (int ks = 0; ks < 16; ++ks) {
        const uint32_t* ab = KPs + ks*2048;
        uint4 a0 = *(const uint4*)(ab + (warp*2 + 0)*128 + lane*4);
        uint4 a1 = *(const uint4*)(ab + (warp*2 + 1)*128 + lane*4);
#pragma unroll
        for (int nt = 0; nt < 8; nt++) {
            uint2 bb = *(const uint2*)(VBp + ks*512 + nt*64 + lane*2);
            mma_tf32(acc[0][nt], a0.x, a0.y, a0.z, a0.w, bb.x, bb.y);
            mma_tf32(acc[1][nt], a1.x, a1.y, a1.z, a1.w, bb.x, bb.y);
        }
    }
    __syncthreads();

#pragma unroll
    for (int mt = 0; mt < 2; mt++)
#pragma unroll
        for (int nt = 0; nt < 8; nt++)
#pragma unroll
            for (int c = 0; c < 4; c++) {
                const int f = warp*32 + mt*16 + qr + ((c & 2) << 2);
                const int d = nt*8 + 2*qc + (c & 1);
                CBp[(f>>3)*512 + (d>>3)*64 + ((d&7)*4 + (f&3))*2 + ((f>>2)&1)]
                    = f2tf32(acc[mt][nt][c]);
            }

    {
        const uint4* src = (const uint4*)((const float*)g_qp + (size_t)cid * 32768);
        uint4* dst = (uint4*)QBs;
#pragma unroll
        for (int it = 0; it < 32; ++it)
            dst[it*256 + tid] = src[it*256 + tid];
    }
    __syncthreads();

    const int mg = warp >> 1;
    const int ng = warp & 1;
    float acc2[2][4][4];
    float accD[2][4];
#pragma unroll
    for (int mt = 0; mt < 2; mt++) {
#pragma unroll
        for (int c = 0; c < 4; c++) accD[mt][c] = 0.f;
#pragma unroll
        for (int nt = 0; nt < 4; nt++)
#pragma unroll
            for (int c = 0; c < 4; c++) acc2[mt][nt][c] = 0.f;
    }

#pragma unroll 4
    for (int ks = 0; ks < 32; ++ks) {
        const uint32_t* qb = QBs + ks*1024;
        uint4 a0 = *(const uint4*)(qb + (mg*2 + 0)*128 + lane*4);
        uint4 a1 = *(const uint4*)(qb + (mg*2 + 1)*128 + lane*4);
        const uint32_t sb0 = SKu[ks*8 + qc];
        const uint32_t sb1 = SKu[ks*8 + qc + 4];
#pragma unroll
        for (int nt = 0; nt < 4; nt++) {
            uint2 bb = *(const uint2*)(CBp + ks*512 + (ng*4 + nt)*64 + lane*2);
            mma_tf32(acc2[0][nt], a0.x, a0.y, a0.z, a0.w, bb.x, bb.y);
            mma_tf32(acc2[1][nt], a1.x, a1.y, a1.z, a1.w, bb.x, bb.y);
        }
        mma_tf32(accD[0], a0.x, a0.y, a0.z, a0.w, sb0, sb1);
        mma_tf32(accD[1], a1.x, a1.y, a1.z, a1.w, sb0, sb1);
    }

#pragma unroll
    for (int mt = 0; mt < 2; mt++) {
        const int r0 = mg*32 + mt*16 + qr;
        const float d0 = 1.0f / (accD[mt][0] + 1e-4f);
        const float d1 = 1.0f / (accD[mt][2] + 1e-4f);
#pragma unroll
        for (int nt = 0; nt < 4; nt++) {
            const int col = (ng*4 + nt)*8 + 2*qc;
            float* op0 = g_att + (row0 + r0)     * DIMM + h*DHD + col;
            float* op1 = g_att + (row0 + r0 + 8) * DIMM + h*DHD + col;
            *(float2*)op0 = make_float2(
                __uint_as_float(f2tf32(acc2[mt][nt][0]*d0)),
                __uint_as_float(f2tf32(acc2[mt][nt][1]*d0)));
            *(float2*)op1 = make_float2(
                __uint_as_float(f2tf32(acc2[mt][nt][2]*d1)),
                __uint_as_float(f2tf32(acc2[mt][nt][3]*d1)));
        }
    }
}

// =====================================================================
// launch
// =====================================================================
extern "C" void kernel_launch(void* const* d_in, const int* in_sizes, int n_in,
                              void* d_out, int out_size)
{
    const float *x = nullptr, *wqkv = nullptr, *wout = nullptr,
                *bout = nullptr, *proj = nullptr;
    for (int i = 0; i < n_in; i++) {
        switch (in_sizes[i]) {
            case MTOK * DIMM:  x    = (const float*)d_in[i]; break;
            case QKVN * DIMM:  wqkv = (const float*)d_in[i]; break;
            case DIMM * DIMM:  wout = (const float*)d_in[i]; break;
            case DIMM:         bout = (const float*)d_in[i]; break;
            case NF * DHD:     proj = (const float*)d_in[i]; break;
        }
    }

    cudaFuncSetAttribute(feature_mma, cudaFuncAttributeMaxDynamicSharedMemorySize, FEAT_SMEM_BYTES);
    cudaFuncSetAttribute(ctx_out_mma, cudaFuncAttributeMaxDynamicSharedMemorySize, CO_SMEM_BYTES);
    cudaFuncSetAttribute(tgemm_nt<false>, cudaFuncAttributeMaxDynamicSharedMemorySize, TG_SMEM_BYTES);
    cudaFuncSetAttribute(tgemm_nt<true>,  cudaFuncAttributeMaxDynamicSharedMemorySize, TG_SMEM_BYTES);

    float *qkvp = nullptr, *attp = nullptr, *xr = nullptr, *wqr = nullptr, *wor = nullptr;
    cudaGetSymbolAddress((void**)&qkvp, g_qkv);
    cudaGetSymbolAddress((void**)&attp, g_att);
    cudaGetSymbolAddress((void**)&xr,   g_xr);
    cudaGetSymbolAddress((void**)&wqr,  g_wqr);
    cudaGetSymbolAddress((void**)&wor,  g_wor);

    // 0) pre-round GEMM operands to tf32
    cvt_tf32<<<(MTOK*DIMM/4 + 255)/256, 256>>>((const float4*)x,    (float4*)xr,  MTOK*DIMM/4);
    cvt_tf32<<<(QKVN*DIMM/4 + 255)/256, 256>>>((const float4*)wqkv, (float4*)wqr, QKVN*DIMM/4);
    cvt_tf32<<<(DIMM*DIMM/4 + 255)/256, 256>>>((const float4*)wout, (float4*)wor, DIMM*DIMM/4);

    // 1) qkv = x @ w_qkv^T   (tile 128x256)
    tgemm_nt<false><<<dim3(QKVN/256, MTOK/128), 256, TG_SMEM_BYTES>>>(
        xr, wqr, nullptr, qkvp, MTOK, QKVN, DIMM);
    // 2) q'/k' feature maps -> fragment-packed layouts (+ksum)
    feature_mma<<<dim3(NCHUNK, 2), 256, FEAT_SMEM_BYTES>>>(proj);
    // 3+4) fused ctx + out -> att (tf32-rounded)
    ctx_out_mma<<<NCHUNK, 256, CO_SMEM_BYTES>>>();
    // 5) final = att @ w_out^T + b_out   (tile 128x256)
    tgemm_nt<true><<<dim3(DIMM/256, MTOK/128), 256, TG_SMEM_BYTES>>>(
        attp, wor, bout, (float*)d_out, MTOK, DIMM, DIMM);
}

// round 9
// speedup vs baseline: 3.1457x; 1.0782x over previous
#include <cuda_runtime.h>
#include <cstdint>

// ---------------- problem constants ----------------
#define NB   4
#define SEQ  4096
#define DIMM 512
#define NH   8
#define DHD  64
#define NF   256
#define CSZ  128
#define NCH  32
#define MTOK (NB*SEQ)            // 16384
#define QKVN (3*DIMM)            // 1536
#define NCHUNK (NB*NH*NCH)       // 1024

// ---------------- device scratch ----------------
__device__ float g_qkv [MTOK * QKVN];
// q'/k' fragment-packed per-chunk (32768 u32 each chunk)
__device__ float g_qp  [NB*NH*SEQ*NF];
__device__ float g_kp  [NB*NH*SEQ*NF];
__device__ float g_ksum[NCHUNK * NF];
// GEMM operands in fragment-packed tf32 global layouts
__device__ uint32_t g_att [MTOK * DIMM];   // packed A for GEMM2 (written by ctx_out)
__device__ uint32_t g_xr  [MTOK * DIMM];   // packed A for GEMM1
__device__ uint32_t g_wqr [QKVN * DIMM];   // packed B for GEMM1
__device__ uint32_t g_wor [DIMM * DIMM];   // packed B for GEMM2

__device__ __forceinline__ uint32_t f2tf32(float f) {
    uint32_t r;
    asm("cvt.rna.tf32.f32 %0, %1;" : "=r"(r) : "f"(f));
    return r;
}

__device__ __forceinline__ void mma_tf32(float acc[4],
                                         uint32_t a0, uint32_t a1, uint32_t a2, uint32_t a3,
                                         uint32_t b0, uint32_t b1)
{
    asm volatile(
        "mma.sync.aligned.m16n8k8.row.col.f32.tf32.tf32.f32 "
        "{%0,%1,%2,%3}, {%4,%5,%6,%7}, {%8,%9}, {%0,%1,%2,%3};"
        : "+f"(acc[0]), "+f"(acc[1]), "+f"(acc[2]), "+f"(acc[3])
        : "r"(a0), "r"(a1), "r"(a2), "r"(a3), "r"(b0), "r"(b1));
}

// =====================================================================
// Pack kernels: fp32 [rows][K] -> tf32 fragment-packed layouts (K=512).
// A: [tile128][kt32][kg2][sub8][lane32][w4]   (uint4 per thread)
// B: [tile256][kt32][kg2][nsub32][lane32][w2] (uint2 per thread)
// =====================================================================
__global__ void pack_A_tf32(const float* __restrict__ src, uint32_t* __restrict__ dst, int n4)
{
    int gid = blockIdx.x * blockDim.x + threadIdx.x;
    if (gid >= n4) return;
    const int lane = gid & 31, sub = (gid >> 5) & 7, kg = (gid >> 8) & 1;
    const int kt = (gid >> 9) & 31, tile = gid >> 14;
    const int qr = lane >> 2, qc = lane & 3;
    const int row = tile*128 + sub*16 + qr;
    const int col = kt*16 + kg*8 + qc;
    const float* s0 = src + (size_t)row * 512 + col;
    uint4 u;
    u.x = f2tf32(s0[0]);
    u.y = f2tf32(s0[8*512]);
    u.z = f2tf32(s0[4]);
    u.w = f2tf32(s0[8*512 + 4]);
    *(uint4*)(dst + (size_t)gid * 4) = u;
}

__global__ void pack_B_tf32(const float* __restrict__ src, uint32_t* __restrict__ dst, int n2)
{
    int gid = blockIdx.x * blockDim.x + threadIdx.x;
    if (gid >= n2) return;
    const int lane = gid & 31, nsub = (gid >> 5) & 31, kg = (gid >> 10) & 1;
    const int kt = (gid >> 11) & 31, tile = gid >> 16;
    const int qr = lane >> 2, qc = lane & 3;
    const int row = tile*256 + nsub*8 + qr;
    const int col = kt*16 + kg*8 + qc;
    const float* s0 = src + (size_t)row * 512 + col;
    uint2 u;
    u.x = f2tf32(s0[0]);
    u.y = f2tf32(s0[4]);
    *(uint2*)(dst + (size_t)gid * 2) = u;
}

// =====================================================================
// TF32 GEMM NT on pre-packed operands, tile 128(m) x 256(n), BK=16,
// 256 threads (8 warps, 2x4), warp tile 64x64, cp.async 4-stage pipeline.
// smem: 4 stages x (A 2048 u32 + B 4096 u32) = 24576 u32 = 98304 B.
// =====================================================================
#define TG_SMEM_BYTES 98304

template<bool BIAS>
__global__ __launch_bounds__(256, 1)
void tgemm_nt(const uint32_t* __restrict__ Apk, const uint32_t* __restrict__ Bpk,
              const float* __restrict__ bias, float* __restrict__ C,
              int M, int N, int K)
{
    extern __shared__ uint32_t smg[];
    const uint32_t smb = (uint32_t)__cvta_generic_to_shared(smg);

    const int tid  = threadIdx.x;
    const int lane = tid & 31;
    const int warp = tid >> 5;
    const int mg   = warp >> 2;          // 0..1 : m 64 each
    const int ng   = warp & 3;           // 0..3 : n 64 each
    const int qr   = lane >> 2;
    const int qc   = lane & 3;

    const int KT = K >> 4;
    const size_t aBase = (size_t)blockIdx.y * KT * 2048;
    const size_t bBase = (size_t)blockIdx.x * KT * 4096;
    const int bm = blockIdx.y * 128;
    const int bn = blockIdx.x * 256;

    auto issue = [&](int kt, int s) {
        const uint32_t sb = smb + s * 6144 * 4;
        const uint32_t* gA = Apk + aBase + (size_t)kt * 2048;
#pragma unroll
        for (int i = 0; i < 2; ++i) {
            const int j = tid + i * 256;
            asm volatile("cp.async.cg.shared.global [%0], [%1], 16;"
                         :: "r"(sb + j * 16), "l"(gA + j * 4) : "memory");
        }
        const uint32_t* gB = Bpk + bBase + (size_t)kt * 4096;
#pragma unroll
        for (int i = 0; i < 4; ++i) {
            const int j = tid + i * 256;
            asm volatile("cp.async.cg.shared.global [%0], [%1], 16;"
                         :: "r"(sb + 8192 + j * 16), "l"(gB + j * 4) : "memory");
        }
    };

    float acc[4][8][4];
#pragma unroll
    for (int i = 0; i < 4; i++)
#pragma unroll
        for (int nt = 0; nt < 8; nt++)
#pragma unroll
            for (int c = 0; c < 4; c++) acc[i][nt][c] = 0.f;

    // prologue: 3 stages in flight
#pragma unroll
    for (int s = 0; s < 3; ++s) {
        issue(s, s);
        asm volatile("cp.async.commit_group;" ::: "memory");
    }

    for (int kt = 0; kt < KT; ++kt) {
        asm volatile("cp.async.wait_group 2;" ::: "memory");
        __syncthreads();
        const uint32_t* st = smg + (kt & 3) * 6144;
#pragma unroll
        for (int kg = 0; kg < 2; ++kg) {
            const uint32_t* ab = st + kg * 1024;
            const uint32_t* bb = st + 2048 + kg * 2048;
            uint4 a[4];
#pragma unroll
            for (int i = 0; i < 4; i++)
                a[i] = *(const uint4*)&ab[(mg*4 + i) * 128 + lane*4];
            uint2 bf[8];
#pragma unroll
            for (int nt = 0; nt < 8; nt++)
                bf[nt] = *(const uint2*)&bb[(ng*8 + nt) * 64 + lane*2];
#pragma unroll
            for (int i = 0; i < 4; i++)
#pragma unroll
                for (int nt = 0; nt < 8; nt++)
                    mma_tf32(acc[i][nt], a[i].x, a[i].y, a[i].z, a[i].w,
                             bf[nt].x, bf[nt].y);
        }
        const int nkt = kt + 3;
        if (nkt < KT) issue(nkt, nkt & 3);
        asm volatile("cp.async.commit_group;" ::: "memory");
    }

    // epilogue
#pragma unroll
    for (int i = 0; i < 4; i++) {
        const int r0 = bm + (mg*4 + i) * 16 + qr;
#pragma unroll
        for (int nt = 0; nt < 8; nt++) {
            const int c0 = bn + (ng*8 + nt) * 8 + 2*qc;
            float v0 = acc[i][nt][0], v1 = acc[i][nt][1];
            float v2 = acc[i][nt][2], v3 = acc[i][nt][3];
            if (BIAS) {
                const float b0 = __ldg(bias + c0), b1 = __ldg(bias + c0 + 1);
                v0 += b0; v1 += b1; v2 += b0; v3 += b1;
            }
            *(float2*)(C + (size_t)r0       * N + c0) = make_float2(v0, v1);
            *(float2*)(C + (size_t)(r0 + 8) * N + c0) = make_float2(v2, v3);
        }
    }
}

// =====================================================================
// Feature kernel (unchanged): single-pass tf32 mma,
// emits fragment-packed q'/k' + ksum.
// =====================================================================
#define APK_KS_STRIDE 1028
#define PPK_KS_STRIDE 2052
#define PPK_BASE      (8 * APK_KS_STRIDE)
#define RMAX_BASE     33792
#define FEAT_SMEM_BYTES ((33792 + 256) * 4)

__global__ __launch_bounds__(256, 1)
void feature_mma(const float* __restrict__ proj)
{
    extern __shared__ uint32_t smu[];
    uint32_t* APK = smu;
    uint32_t* PPK = smu + PPK_BASE;
    float*    sm_e = (float*)smu;
    float*    RMAX = (float*)(smu + RMAX_BASE);

    const int cid = blockIdx.x;
    const int isK = blockIdx.y;
    const int b  = cid >> 8;
    const int h  = (cid >> 5) & 7;
    const int cc = cid & 31;
    const size_t row0   = (size_t)b * SEQ + (size_t)cc * CSZ;
    const int   colbase = isK * DIMM + h * DHD;
    const float scale   = isK ? 1.0f : 0.125f;
    const int STR = isK ? 264 : 260;
    const int tid  = threadIdx.x;
    const int lane = tid & 31;
    const int warp = tid >> 5;
    const int wgm  = warp >> 1;
    const int fg   = warp & 1;
    const int qr   = lane >> 2;
    const int qc   = lane & 3;

#pragma unroll
    for (int it = 0; it < 8; ++it) {
        const int idx4 = it * 256 + tid;
        const int s  = idx4 >> 4;
        const int d4 = (idx4 & 15) * 4;
        float4 v = *(const float4*)(g_qkv + (row0 + s) * QKVN + colbase + d4);
        const int ks   = d4 >> 3;
        const int hi   = (d4 >> 2) & 1;
        const int sub  = s >> 4;
        const int qrS  = s & 7;
        const int halfS= (s >> 3) & 1;
        const int word = hi * 2 + halfS;
        uint32_t* base = APK + ks * APK_KS_STRIDE + sub * 128 + (qrS << 4);
        base[0*4 + word] = f2tf32(v.x * scale);
        base[1*4 + word] = f2tf32(v.y * scale);
        base[2*4 + word] = f2tf32(v.z * scale);
        base[3*4 + word] = f2tf32(v.w * scale);
    }
#pragma unroll
    for (int it = 0; it < 16; ++it) {
        const int idx4 = it * 256 + tid;
        const int f  = idx4 >> 4;
        const int d4 = (idx4 & 15) * 4;
        float4 v = *(const float4*)(proj + f * DHD + d4);
        const int ks   = d4 >> 3;
        const int hi   = (d4 >> 2) & 1;
        const int nsub = f >> 3;
        const int qrF  = f & 7;
        uint32_t* base = PPK + ks * PPK_KS_STRIDE + nsub * 64 + (qrF << 3);
        base[0*2 + hi] = f2tf32(v.x);
        base[1*2 + hi] = f2tf32(v.y);
        base[2*2 + hi] = f2tf32(v.z);
        base[3*2 + hi] = f2tf32(v.w);
    }
    __syncthreads();

    float acc[2][16][4];
#pragma unroll
    for (int mt = 0; mt < 2; mt++)
#pragma unroll
        for (int nt = 0; nt < 16; nt++)
#pragma unroll
            for (int c = 0; c < 4; c++) acc[mt][nt][c] = 0.f;

    const int rl4 = lane * 4;
    const int rl2 = lane * 2;
#pragma unroll
    for (int ks = 0; ks < 8; ++ks) {
        const uint32_t* abase = APK + ks * APK_KS_STRIDE;
        const uint32_t* pbase = PPK + ks * PPK_KS_STRIDE;
        uint4 a0 = *(const uint4*)&abase[(wgm*2 + 0) * 128 + rl4];
        uint4 a1 = *(const uint4*)&abase[(wgm*2 + 1) * 128 + rl4];
#pragma unroll
        for (int nt = 0; nt < 16; nt++) {
            uint2 bb = *(const uint2*)&pbase[(fg*16 + nt) * 64 + rl2];
            mma_tf32(acc[0][nt], a0.x, a0.y, a0.z, a0.w, bb.x, bb.y);
            mma_tf32(acc[1][nt], a1.x, a1.y, a1.z, a1.w, bb.x, bb.y);
        }
    }

    float mloc[2][2];
#pragma unroll
    for (int mt = 0; mt < 2; mt++)
#pragma unroll
        for (int hh = 0; hh < 2; hh++) {
            float m = -1e30f;
#pragma unroll
            for (int nt = 0; nt < 16; nt++) {
                m = fmaxf(m, acc[mt][nt][hh*2+0]);
                m = fmaxf(m, acc[mt][nt][hh*2+1]);
            }
            m = fmaxf(m, __shfl_xor_sync(0xffffffffu, m, 1));
            m = fmaxf(m, __shfl_xor_sync(0xffffffffu, m, 2));
            mloc[mt][hh] = m;
        }
    if (qc == 0) {
#pragma unroll
        for (int mt = 0; mt < 2; mt++)
#pragma unroll
            for (int hh = 0; hh < 2; hh++)
                RMAX[fg*128 + wgm*32 + mt*16 + hh*8 + qr] = mloc[mt][hh];
    }
    __syncthreads();

    float rm[2][2];
#pragma unroll
    for (int mt = 0; mt < 2; mt++)
#pragma unroll
        for (int hh = 0; hh < 2; hh++) {
            const int row = wgm*32 + mt*16 + hh*8 + qr;
            rm[mt][hh] = fmaxf(RMAX[row], RMAX[128 + row]);
        }

#pragma unroll
    for (int mt = 0; mt < 2; mt++)
#pragma unroll
        for (int hh = 0; hh < 2; hh++) {
            const int row = wgm*32 + mt*16 + hh*8 + qr;
#pragma unroll
            for (int nt = 0; nt < 16; nt++) {
                const int f = fg*128 + nt*8 + 2*qc;
                float e0 = __expf(acc[mt][nt][hh*2+0] - rm[mt][hh]);
                float e1 = __expf(acc[mt][nt][hh*2+1] - rm[mt][hh]);
                sm_e[row*STR + f]     = __uint_as_float(f2tf32(e0));
                sm_e[row*STR + f + 1] = __uint_as_float(f2tf32(e1));
            }
        }
    __syncthreads();

    if (isK) {
        uint32_t* outp = (uint32_t*)g_kp + (size_t)cid * 32768;
#pragma unroll
        for (int it = 0; it < 32; ++it) {
            const int gid = it * 256 + tid;
            const int ln  = gid & 31;
            const int sub = (gid >> 5) & 15;
            const int ks  = gid >> 9;
            const int qc2 = ln & 3, qr2 = ln >> 2;
            const int s0 = ks*8 + qc2, f0 = sub*16 + qr2;
            uint4 u;
            u.x = __float_as_uint(sm_e[s0*264 + f0]);
            u.y = __float_as_uint(sm_e[s0*264 + f0 + 8]);
            u.z = __float_as_uint(sm_e[(s0+4)*264 + f0]);
            u.w = __float_as_uint(sm_e[(s0+4)*264 + f0 + 8]);
            *(uint4*)(outp + (size_t)gid * 4) = u;
        }
        float s = 0.f;
#pragma unroll 8
        for (int r = 0; r < CSZ; ++r) s += sm_e[r*264 + tid];
        g_ksum[(size_t)cid * NF + tid] = s;
    } else {
        uint32_t* outp = (uint32_t*)g_qp + (size_t)cid * 32768;
#pragma unroll
        for (int it = 0; it < 32; ++it) {
            const int gid = it * 256 + tid;
            const int ln  = gid & 31;
            const int sub = (gid >> 5) & 7;
            const int ks  = gid >> 8;
            const int qc2 = ln & 3, qr2 = ln >> 2;
            const int r0 = sub*16 + qr2, f0 = ks*8 + qc2;
            uint4 u;
            u.x = __float_as_uint(sm_e[r0*260 + f0]);
            u.y = __float_as_uint(sm_e[(r0+8)*260 + f0]);
            u.z = __float_as_uint(sm_e[r0*260 + f0 + 4]);
            u.w = __float_as_uint(sm_e[(r0+8)*260 + f0 + 4]);
            *(uint4*)(outp + (size_t)gid * 4) = u;
        }
    }
}

// =====================================================================
// Fused ctx + out kernel — epilogue stores att in fragment-packed
// global layout (smem scatter -> coalesced copy).
// =====================================================================
#define CO_SMEM_BYTES (49408 * 4)

__global__ __launch_bounds__(256, 1)
void ctx_out_mma()
{
    extern __shared__ uint32_t smu[];
    uint32_t* KPs = smu;
    uint32_t* VBp = smu + 32768;
    float*    vpl = (float*)(smu + 36864);
    uint32_t* CBp = smu;
    uint32_t* QBs = smu + 16384;
    uint32_t* SKu = smu + 49152;
    uint32_t* ATs = smu;                 // packed att staging (8192 u32, alias)

    const int cid = blockIdx.x;
    const int b  = cid >> 8;
    const int h  = (cid >> 5) & 7;
    const int cc = cid & 31;
    const size_t row0 = (size_t)b * SEQ + (size_t)cc * CSZ;
    const int vcol = 2 * DIMM + h * DHD;
    const int tid  = threadIdx.x;
    const int lane = tid & 31;
    const int warp = tid >> 5;
    const int qr   = lane >> 2;
    const int qc   = lane & 3;

    {
        const uint4* src = (const uint4*)((const float*)g_kp + (size_t)cid * 32768);
        uint4* dst = (uint4*)KPs;
#pragma unroll
        for (int it = 0; it < 32; ++it)
            dst[it*256 + tid] = src[it*256 + tid];
    }
#pragma unroll
    for (int it = 0; it < 8; ++it) {
        const int idx4 = it * 256 + tid;
        const int s  = idx4 >> 4;
        const int d4 = (idx4 & 15) * 4;
        *(float4*)(vpl + s*72 + d4) =
            *(const float4*)(g_qkv + (row0 + s) * QKVN + vcol + d4);
    }
    SKu[tid] = f2tf32(g_ksum[(size_t)cid * NF + tid]);
    __syncthreads();

#pragma unroll
    for (int it = 0; it < 16; ++it) {
        const int wid2 = it * 256 + tid;
        const int ln   = wid2 & 31;
        const int nsub = (wid2 >> 5) & 7;
        const int ks   = wid2 >> 8;
        const int qc2 = ln & 3, qr2 = ln >> 2;
        const int s0 = ks*8 + qc2, d0 = nsub*8 + qr2;
        uint2 u;
        u.x = f2tf32(vpl[s0*72 + d0]);
        u.y = f2tf32(vpl[(s0+4)*72 + d0]);
        *(uint2*)(VBp + wid2*2) = u;
    }
    __syncthreads();

    float acc[2][8][4];
#pragma unroll
    for (int mt = 0; mt < 2; mt++)
#pragma unroll
        for (int nt = 0; nt < 8; nt++)
#pragma unroll
            for (int c = 0; c < 4; c++) acc[mt][nt][c] = 0.f;

#pragma unroll 4
    for (int ks = 0; ks < 16; ++ks) {
        const uint32_t* ab = KPs + ks*2048;
        uint4 a0 = *(const uint4*)(ab + (warp*2 + 0)*128 + lane*4);
        uint4 a1 = *(const uint4*)(ab + (warp*2 + 1)*128 + lane*4);
#pragma unroll
        for (int nt = 0; nt < 8; nt++) {
            uint2 bb = *(const uint2*)(VBp + ks*512 + nt*64 + lane*2);
            mma_tf32(acc[0][nt], a0.x, a0.y, a0.z, a0.w, bb.x, bb.y);
            mma_tf32(acc[1][nt], a1.x, a1.y, a1.z, a1.w, bb.x, bb.y);
        }
    }
    __syncthreads();

#pragma unroll
    for (int mt = 0; mt < 2; mt++)
#pragma unroll
        for (int nt = 0; nt < 8; nt++)
#pragma unroll
            for (int c = 0; c < 4; c++) {
                const int f = warp*32 + mt*16 + qr + ((c & 2) << 2);
                const int d = nt*8 + 2*qc + (c & 1);
                CBp[(f>>3)*512 + (d>>3)*64 + ((d&7)*4 + (f&3))*2 + ((f>>2)&1)]
                    = f2tf32(acc[mt][nt][c]);
            }

    {
        const uint4* src = (const uint4*)((const float*)g_qp + (size_t)cid * 32768);
        uint4* dst = (uint4*)QBs;
#pragma unroll
        for (int it = 0; it < 32; ++it)
            dst[it*256 + tid] = src[it*256 + tid];
    }
    __syncthreads();

    const int mg = warp >> 1;
    const int ng = warp & 1;
    float acc2[2][4][4];
    float accD[2][4];
#pragma unroll
    for (int mt = 0; mt < 2; mt++) {
#pragma unroll
        for (int c = 0; c < 4; c++) accD[mt][c] = 0.f;
#pragma unroll
        for (int nt = 0; nt < 4; nt++)
#pragma unroll
            for (int c = 0; c < 4; c++) acc2[mt][nt][c] = 0.f;
    }

#pragma unroll 4
    for (int ks = 0; ks < 32; ++ks) {
        const uint32_t* qb = QBs + ks*1024;
        uint4 a0 = *(const uint4*)(qb + (mg*2 + 0)*128 + lane*4);
        uint4 a1 = *(const uint4*)(qb + (mg*2 + 1)*128 + lane*4);
        const uint32_t sb0 = SKu[ks*8 + qc];
        const uint32_t sb1 = SKu[ks*8 + qc + 4];
#pragma unroll
        for (int nt = 0; nt < 4; nt++) {
            uint2 bb = *(const uint2*)(CBp + ks*512 + (ng*4 + nt)*64 + lane*2);
            mma_tf32(acc2[0][nt], a0.x, a0.y, a0.z, a0.w, bb.x, bb.y);
            mma_tf32(acc2[1][nt], a1.x, a1.y, a1.z, a1.w, bb.x, bb.y);
        }
        mma_tf32(accD[0], a0.x, a0.y, a0.z, a0.w, sb0, sb1);
        mma_tf32(accD[1], a1.x, a1.y, a1.z, a1.w, sb0, sb1);
    }
    __syncthreads();    // CBp reads done; ATs alias-write next

    // scatter packed att fragments into smem
#pragma unroll
    for (int mt = 0; mt < 2; mt++) {
        const float d0 = 1.0f / (accD[mt][0] + 1e-4f);
        const float d1 = 1.0f / (accD[mt][2] + 1e-4f);
#pragma unroll
        for (int nt = 0; nt < 4; nt++) {
#pragma unroll
            for (int c = 0; c < 4; c++) {
                const int r   = mg*32 + mt*16 + qr + (c & 2) * 4;   // +8 if c>=2
                const int col = (ng*4 + nt)*8 + 2*qc + (c & 1);
                const float dinv = (c & 2) ? d1 : d0;
                const int idx = (col>>4)*2048 + ((col>>3)&1)*1024 + (r>>4)*128
                              + ((r&7)*4 + (col&3))*4 + ((col>>2)&1)*2 + ((r>>3)&1);
                ATs[idx] = f2tf32(acc2[mt][nt][c] * dinv);
            }
        }
    }
    __syncthreads();

    // coalesced copy: per-chunk packed span = 8192 u32 at tile*65536 + h*8192
    {
        const int tile = b*32 + cc;
        uint4* gdst = (uint4*)(g_att + (size_t)tile * 65536 + (size_t)h * 8192);
        const uint4* ssrc = (const uint4*)ATs;
#pragma unroll
        for (int i = 0; i < 8; ++i)
            gdst[i*256 + tid] = ssrc[i*256 + tid];
    }
}

// =====================================================================
// launch
// =====================================================================
extern "C" void kernel_launch(void* const* d_in, const int* in_sizes, int n_in,
                              void* d_out, int out_size)
{
    const float *x = nullptr, *wqkv = nullptr, *wout = nullptr,
                *bout = nullptr, *proj = nullptr;
    for (int i = 0; i < n_in; i++) {
        switch (in_sizes[i]) {
            case MTOK * DIMM:  x    = (const float*)d_in[i]; break;
            case QKVN * DIMM:  wqkv = (const float*)d_in[i]; break;
            case DIMM * DIMM:  wout = (const float*)d_in[i]; break;
            case DIMM:         bout = (const float*)d_in[i]; break;
            case NF * DHD:     proj = (const float*)d_in[i]; break;
        }
    }

    cudaFuncSetAttribute(feature_mma, cudaFuncAttributeMaxDynamicSharedMemorySize, FEAT_SMEM_BYTES);
    cudaFuncSetAttribute(ctx_out_mma, cudaFuncAttributeMaxDynamicSharedMemorySize, CO_SMEM_BYTES);
    cudaFuncSetAttribute(tgemm_nt<false>, cudaFuncAttributeMaxDynamicSharedMemorySize, TG_SMEM_BYTES);
    cudaFuncSetAttribute(tgemm_nt<true>,  cudaFuncAttributeMaxDynamicSharedMemorySize, TG_SMEM_BYTES);

    float *qkvp = nullptr;
    uint32_t *attp = nullptr, *xr = nullptr, *wqr = nullptr, *wor = nullptr;
    cudaGetSymbolAddress((void**)&qkvp, g_qkv);
    cudaGetSymbolAddress((void**)&attp, g_att);
    cudaGetSymbolAddress((void**)&xr,   g_xr);
    cudaGetSymbolAddress((void**)&wqr,  g_wqr);
    cudaGetSymbolAddress((void**)&wor,  g_wor);

    // 0) pack GEMM operands into tf32 fragment layouts
    pack_A_tf32<<<(MTOK*DIMM/4 + 255)/256, 256>>>(x,    xr,  MTOK*DIMM/4);
    pack_B_tf32<<<(QKVN*DIMM/2 + 255)/256, 256>>>(wqkv, wqr, QKVN*DIMM/2);
    pack_B_tf32<<<(DIMM*DIMM/2 + 255)/256, 256>>>(wout, wor, DIMM*DIMM/2);

    // 1) qkv = x @ w_qkv^T   (cp.async pipelined, packed operands)
    tgemm_nt<false><<<dim3(QKVN/256, MTOK/128), 256, TG_SMEM_BYTES>>>(
        xr, wqr, nullptr, qkvp, MTOK, QKVN, DIMM);
    // 2) q'/k' feature maps -> fragment-packed layouts (+ksum)
    feature_mma<<<dim3(NCHUNK, 2), 256, FEAT_SMEM_BYTES>>>(proj);
    // 3+4) fused ctx + out -> att (packed tf32)
    ctx_out_mma<<<NCHUNK, 256, CO_SMEM_BYTES>>>();
    // 5) final = att @ w_out^T + b_out
    tgemm_nt<true><<<dim3(DIMM/256, MTOK/128), 256, TG_SMEM_BYTES>>>(
        g_att ? attp : attp, wor, bout, (float*)d_out, MTOK, DIMM, DIMM);
}

// round 10
// speedup vs baseline: 3.2536x; 1.0343x over previous
#include <cuda_runtime.h>
#include <cstdint>

// ---------------- problem constants ----------------
#define NB   4
#define SEQ  4096
#define DIMM 512
#define NH   8
#define DHD  64
#define NF   256
#define CSZ  128
#define NCH  32
#define MTOK (NB*SEQ)            // 16384
#define QKVN (3*DIMM)            // 1536
#define NCHUNK (NB*NH*NCH)       // 1024

// ---------------- device scratch ----------------
__device__ float g_qkv [MTOK * QKVN];
// q'/k' fragment-packed per-chunk (32768 u32 each chunk)
__device__ float g_qp  [NB*NH*SEQ*NF];
__device__ float g_kp  [NB*NH*SEQ*NF];
__device__ float g_ksum[NCHUNK * NF];
// GEMM operands in fragment-packed tf32 global layouts
__device__ uint32_t g_att [MTOK * DIMM];   // packed A for GEMM2 (written by ctx_out)
__device__ uint32_t g_xr  [MTOK * DIMM];   // packed A for GEMM1
__device__ uint32_t g_wqr [QKVN * DIMM];   // packed B for GEMM1
__device__ uint32_t g_wor [DIMM * DIMM];   // packed B for GEMM2

__device__ __forceinline__ uint32_t f2tf32(float f) {
    uint32_t r;
    asm("cvt.rna.tf32.f32 %0, %1;" : "=r"(r) : "f"(f));
    return r;
}

__device__ __forceinline__ void mma_tf32(float acc[4],
                                         uint32_t a0, uint32_t a1, uint32_t a2, uint32_t a3,
                                         uint32_t b0, uint32_t b1)
{
    asm volatile(
        "mma.sync.aligned.m16n8k8.row.col.f32.tf32.tf32.f32 "
        "{%0,%1,%2,%3}, {%4,%5,%6,%7}, {%8,%9}, {%0,%1,%2,%3};"
        : "+f"(acc[0]), "+f"(acc[1]), "+f"(acc[2]), "+f"(acc[3])
        : "r"(a0), "r"(a1), "r"(a2), "r"(a3), "r"(b0), "r"(b1));
}

// =====================================================================
// Pack kernels: fp32 [rows][K] -> tf32 fragment-packed layouts (K=512).
// A: [tile128][kt32][kg2][sub8][lane32][w4]    (uint4 per thread)
// B: [tile128][kt32][kg2][nsub16][lane32][w2]  (uint2 per thread)
// =====================================================================
__global__ void pack_A_tf32(const float* __restrict__ src, uint32_t* __restrict__ dst, int n4)
{
    int gid = blockIdx.x * blockDim.x + threadIdx.x;
    if (gid >= n4) return;
    const int lane = gid & 31, sub = (gid >> 5) & 7, kg = (gid >> 8) & 1;
    const int kt = (gid >> 9) & 31, tile = gid >> 14;
    const int qr = lane >> 2, qc = lane & 3;
    const int row = tile*128 + sub*16 + qr;
    const int col = kt*16 + kg*8 + qc;
    const float* s0 = src + (size_t)row * 512 + col;
    uint4 u;
    u.x = f2tf32(s0[0]);
    u.y = f2tf32(s0[8*512]);
    u.z = f2tf32(s0[4]);
    u.w = f2tf32(s0[8*512 + 4]);
    *(uint4*)(dst + (size_t)gid * 4) = u;
}

__global__ void pack_B_tf32(const float* __restrict__ src, uint32_t* __restrict__ dst, int n2)
{
    int gid = blockIdx.x * blockDim.x + threadIdx.x;
    if (gid >= n2) return;
    const int lane = gid & 31, nsub = (gid >> 5) & 15, kg = (gid >> 9) & 1;
    const int kt = (gid >> 10) & 31, tile = gid >> 15;
    const int qr = lane >> 2, qc = lane & 3;
    const int row = tile*128 + nsub*8 + qr;
    const int col = kt*16 + kg*8 + qc;
    const float* s0 = src + (size_t)row * 512 + col;
    uint2 u;
    u.x = f2tf32(s0[0]);
    u.y = f2tf32(s0[4]);
    *(uint2*)(dst + (size_t)gid * 2) = u;
}

// =====================================================================
// TF32 GEMM NT on pre-packed operands, tile 128(m) x 128(n), BK=16,
// 256 threads (8 warps, 4m x 2n), warp tile 32x64, cp.async 4-stage
// pipeline, 2 CTAs/SM.
// smem: 4 stages x (A 2048 u32 + B 2048 u32) = 16384 u32 = 65536 B.
// =====================================================================
#define TG_SMEM_BYTES 65536

template<bool BIAS>
__global__ __launch_bounds__(256, 2)
void tgemm_nt(const uint32_t* __restrict__ Apk, const uint32_t* __restrict__ Bpk,
              const float* __restrict__ bias, float* __restrict__ C,
              int M, int N, int K)
{
    extern __shared__ uint32_t smg[];
    const uint32_t smb = (uint32_t)__cvta_generic_to_shared(smg);

    const int tid  = threadIdx.x;
    const int lane = tid & 31;
    const int warp = tid >> 5;
    const int mg   = warp >> 1;          // 0..3 : m 32 each
    const int ng   = warp & 1;           // 0..1 : n 64 each
    const int qr   = lane >> 2;
    const int qc   = lane & 3;

    const int KT = K >> 4;
    const size_t aBase = (size_t)blockIdx.y * KT * 2048;
    const size_t bBase = (size_t)blockIdx.x * KT * 2048;
    const int bm = blockIdx.y * 128;
    const int bn = blockIdx.x * 128;

    auto issue = [&](int kt, int s) {
        const uint32_t sb = smb + s * 4096 * 4;
        const uint32_t* gA = Apk + aBase + (size_t)kt * 2048;
        const uint32_t* gB = Bpk + bBase + (size_t)kt * 2048;
#pragma unroll
        for (int i = 0; i < 2; ++i) {
            const int j = tid + i * 256;
            asm volatile("cp.async.cg.shared.global [%0], [%1], 16;"
                         :: "r"(sb + j * 16), "l"(gA + j * 4) : "memory");
            asm volatile("cp.async.cg.shared.global [%0], [%1], 16;"
                         :: "r"(sb + 8192 + j * 16), "l"(gB + j * 4) : "memory");
        }
    };

    float acc[2][8][4];
#pragma unroll
    for (int i = 0; i < 2; i++)
#pragma unroll
        for (int nt = 0; nt < 8; nt++)
#pragma unroll
            for (int c = 0; c < 4; c++) acc[i][nt][c] = 0.f;

    // prologue: 3 stages in flight
#pragma unroll
    for (int s = 0; s < 3; ++s) {
        issue(s, s);
        asm volatile("cp.async.commit_group;" ::: "memory");
    }

    for (int kt = 0; kt < KT; ++kt) {
        asm volatile("cp.async.wait_group 2;" ::: "memory");
        __syncthreads();
        const uint32_t* st = smg + (kt & 3) * 4096;
#pragma unroll
        for (int kg = 0; kg < 2; ++kg) {
            const uint32_t* ab = st + kg * 1024;
            const uint32_t* bb = st + 2048 + kg * 1024;
            uint4 a[2];
#pragma unroll
            for (int i = 0; i < 2; i++)
                a[i] = *(const uint4*)&ab[(mg*2 + i) * 128 + lane*4];
            uint2 bf[8];
#pragma unroll
            for (int nt = 0; nt < 8; nt++)
                bf[nt] = *(const uint2*)&bb[(ng*8 + nt) * 64 + lane*2];
#pragma unroll
            for (int i = 0; i < 2; i++)
#pragma unroll
                for (int nt = 0; nt < 8; nt++)
                    mma_tf32(acc[i][nt], a[i].x, a[i].y, a[i].z, a[i].w,
                             bf[nt].x, bf[nt].y);
        }
        const int nkt = kt + 3;
        if (nkt < KT) issue(nkt, nkt & 3);
        asm volatile("cp.async.commit_group;" ::: "memory");
    }

    // epilogue
#pragma unroll
    for (int i = 0; i < 2; i++) {
        const int r0 = bm + (mg*2 + i) * 16 + qr;
#pragma unroll
        for (int nt = 0; nt < 8; nt++) {
            const int c0 = bn + (ng*8 + nt) * 8 + 2*qc;
            float v0 = acc[i][nt][0], v1 = acc[i][nt][1];
            float v2 = acc[i][nt][2], v3 = acc[i][nt][3];
            if (BIAS) {
                const float b0 = __ldg(bias + c0), b1 = __ldg(bias + c0 + 1);
                v0 += b0; v1 += b1; v2 += b0; v3 += b1;
            }
            *(float2*)(C + (size_t)r0       * N + c0) = make_float2(v0, v1);
            *(float2*)(C + (size_t)(r0 + 8) * N + c0) = make_float2(v2, v3);
        }
    }
}

// =====================================================================
// Feature kernel (unchanged): single-pass tf32 mma,
// emits fragment-packed q'/k' + ksum.
// =====================================================================
#define APK_KS_STRIDE 1028
#define PPK_KS_STRIDE 2052
#define PPK_BASE      (8 * APK_KS_STRIDE)
#define RMAX_BASE     33792
#define FEAT_SMEM_BYTES ((33792 + 256) * 4)

__global__ __launch_bounds__(256, 1)
void feature_mma(const float* __restrict__ proj)
{
    extern __shared__ uint32_t smu[];
    uint32_t* APK = smu;
    uint32_t* PPK = smu + PPK_BASE;
    float*    sm_e = (float*)smu;
    float*    RMAX = (float*)(smu + RMAX_BASE);

    const int cid = blockIdx.x;
    const int isK = blockIdx.y;
    const int b  = cid >> 8;
    const int h  = (cid >> 5) & 7;
    const int cc = cid & 31;
    const size_t row0   = (size_t)b * SEQ + (size_t)cc * CSZ;
    const int   colbase = isK * DIMM + h * DHD;
    const float scale   = isK ? 1.0f : 0.125f;
    const int STR = isK ? 264 : 260;
    const int tid  = threadIdx.x;
    const int lane = tid & 31;
    const int warp = tid >> 5;
    const int wgm  = warp >> 1;
    const int fg   = warp & 1;
    const int qr   = lane >> 2;
    const int qc   = lane & 3;

#pragma unroll
    for (int it = 0; it < 8; ++it) {
        const int idx4 = it * 256 + tid;
        const int s  = idx4 >> 4;
        const int d4 = (idx4 & 15) * 4;
        float4 v = *(const float4*)(g_qkv + (row0 + s) * QKVN + colbase + d4);
        const int ks   = d4 >> 3;
        const int hi   = (d4 >> 2) & 1;
        const int sub  = s >> 4;
        const int qrS  = s & 7;
        const int halfS= (s >> 3) & 1;
        const int word = hi * 2 + halfS;
        uint32_t* base = APK + ks * APK_KS_STRIDE + sub * 128 + (qrS << 4);
        base[0*4 + word] = f2tf32(v.x * scale);
        base[1*4 + word] = f2tf32(v.y * scale);
        base[2*4 + word] = f2tf32(v.z * scale);
        base[3*4 + word] = f2tf32(v.w * scale);
    }
#pragma unroll
    for (int it = 0; it < 16; ++it) {
        const int idx4 = it * 256 + tid;
        const int f  = idx4 >> 4;
        const int d4 = (idx4 & 15) * 4;
        float4 v = *(const float4*)(proj + f * DHD + d4);
        const int ks   = d4 >> 3;
        const int hi   = (d4 >> 2) & 1;
        const int nsub = f >> 3;
        const int qrF  = f & 7;
        uint32_t* base = PPK + ks * PPK_KS_STRIDE + nsub * 64 + (qrF << 3);
        base[0*2 + hi] = f2tf32(v.x);
        base[1*2 + hi] = f2tf32(v.y);
        base[2*2 + hi] = f2tf32(v.z);
        base[3*2 + hi] = f2tf32(v.w);
    }
    __syncthreads();

    float acc[2][16][4];
#pragma unroll
    for (int mt = 0; mt < 2; mt++)
#pragma unroll
        for (int nt = 0; nt < 16; nt++)
#pragma unroll
            for (int c = 0; c < 4; c++) acc[mt][nt][c] = 0.f;

    const int rl4 = lane * 4;
    const int rl2 = lane * 2;
#pragma unroll
    for (int ks = 0; ks < 8; ++ks) {
        const uint32_t* abase = APK + ks * APK_KS_STRIDE;
        const uint32_t* pbase = PPK + ks * PPK_KS_STRIDE;
        uint4 a0 = *(const uint4*)&abase[(wgm*2 + 0) * 128 + rl4];
        uint4 a1 = *(const uint4*)&abase[(wgm*2 + 1) * 128 + rl4];
#pragma unroll
        for (int nt = 0; nt < 16; nt++) {
            uint2 bb = *(const uint2*)&pbase[(fg*16 + nt) * 64 + rl2];
            mma_tf32(acc[0][nt], a0.x, a0.y, a0.z, a0.w, bb.x, bb.y);
            mma_tf32(acc[1][nt], a1.x, a1.y, a1.z, a1.w, bb.x, bb.y);
        }
    }

    float mloc[2][2];
#pragma unroll
    for (int mt = 0; mt < 2; mt++)
#pragma unroll
        for (int hh = 0; hh < 2; hh++) {
            float m = -1e30f;
#pragma unroll
            for (int nt = 0; nt < 16; nt++) {
                m = fmaxf(m, acc[mt][nt][hh*2+0]);
                m = fmaxf(m, acc[mt][nt][hh*2+1]);
            }
            m = fmaxf(m, __shfl_xor_sync(0xffffffffu, m, 1));
            m = fmaxf(m, __shfl_xor_sync(0xffffffffu, m, 2));
            mloc[mt][hh] = m;
        }
    if (qc == 0) {
#pragma unroll
        for (int mt = 0; mt < 2; mt++)
#pragma unroll
            for (int hh = 0; hh < 2; hh++)
                RMAX[fg*128 + wgm*32 + mt*16 + hh*8 + qr] = mloc[mt][hh];
    }
    __syncthreads();

    float rm[2][2];
#pragma unroll
    for (int mt = 0; mt < 2; mt++)
#pragma unroll
        for (int hh = 0; hh < 2; hh++) {
            const int row = wgm*32 + mt*16 + hh*8 + qr;
            rm[mt][hh] = fmaxf(RMAX[row], RMAX[128 + row]);
        }

#pragma unroll
    for (int mt = 0; mt < 2; mt++)
#pragma unroll
        for (int hh = 0; hh < 2; hh++) {
            const int row = wgm*32 + mt*16 + hh*8 + qr;
#pragma unroll
            for (int nt = 0; nt < 16; nt++) {
                const int f = fg*128 + nt*8 + 2*qc;
                float e0 = __expf(acc[mt][nt][hh*2+0] - rm[mt][hh]);
                float e1 = __expf(acc[mt][nt][hh*2+1] - rm[mt][hh]);
                sm_e[row*STR + f]     = __uint_as_float(f2tf32(e0));
                sm_e[row*STR + f + 1] = __uint_as_float(f2tf32(e1));
            }
        }
    __syncthreads();

    if (isK) {
        uint32_t* outp = (uint32_t*)g_kp + (size_t)cid * 32768;
#pragma unroll
        for (int it = 0; it < 32; ++it) {
            const int gid = it * 256 + tid;
            const int ln  = gid & 31;
            const int sub = (gid >> 5) & 15;
            const int ks  = gid >> 9;
            const int qc2 = ln & 3, qr2 = ln >> 2;
            const int s0 = ks*8 + qc2, f0 = sub*16 + qr2;
            uint4 u;
            u.x = __float_as_uint(sm_e[s0*264 + f0]);
            u.y = __float_as_uint(sm_e[s0*264 + f0 + 8]);
            u.z = __float_as_uint(sm_e[(s0+4)*264 + f0]);
            u.w = __float_as_uint(sm_e[(s0+4)*264 + f0 + 8]);
            *(uint4*)(outp + (size_t)gid * 4) = u;
        }
        float s = 0.f;
#pragma unroll 8
        for (int r = 0; r < CSZ; ++r) s += sm_e[r*264 + tid];
        g_ksum[(size_t)cid * NF + tid] = s;
    } else {
        uint32_t* outp = (uint32_t*)g_qp + (size_t)cid * 32768;
#pragma unroll
        for (int it = 0; it < 32; ++it) {
            const int gid = it * 256 + tid;
            const int ln  = gid & 31;
            const int sub = (gid >> 5) & 7;
            const int ks  = gid >> 8;
            const int qc2 = ln & 3, qr2 = ln >> 2;
            const int r0 = sub*16 + qr2, f0 = ks*8 + qc2;
            uint4 u;
            u.x = __float_as_uint(sm_e[r0*260 + f0]);
            u.y = __float_as_uint(sm_e[(r0+8)*260 + f0]);
            u.z = __float_as_uint(sm_e[r0*260 + f0 + 4]);
            u.w = __float_as_uint(sm_e[(r0+8)*260 + f0 + 4]);
            *(uint4*)(outp + (size_t)gid * 4) = u;
        }
    }
}

// =====================================================================
// Fused ctx + out kernel (unchanged from R9) — emits packed att.
// =====================================================================
#define CO_SMEM_BYTES (49408 * 4)

__global__ __launch_bounds__(256, 1)
void ctx_out_mma()
{
    extern __shared__ uint32_t smu[];
    uint32_t* KPs = smu;
    uint32_t* VBp = smu + 32768;
    float*    vpl = (float*)(smu + 36864);
    uint32_t* CBp = smu;
    uint32_t* QBs = smu + 16384;
    uint32_t* SKu = smu + 49152;
    uint32_t* ATs = smu;                 // packed att staging (8192 u32, alias)

    const int cid = blockIdx.x;
    const int b  = cid >> 8;
    const int h  = (cid >> 5) & 7;
    const int cc = cid & 31;
    const size_t row0 = (size_t)b * SEQ + (size_t)cc * CSZ;
    const int vcol = 2 * DIMM + h * DHD;
    const int tid  = threadIdx.x;
    const int lane = tid & 31;
    const int warp = tid >> 5;
    const int qr   = lane >> 2;
    const int qc   = lane & 3;

    {
        const uint4* src = (const uint4*)((const float*)g_kp + (size_t)cid * 32768);
        uint4* dst = (uint4*)KPs;
#pragma unroll
        for (int it = 0; it < 32; ++it)
            dst[it*256 + tid] = src[it*256 + tid];
    }
#pragma unroll
    for (int it = 0; it < 8; ++it) {
        const int idx4 = it * 256 + tid;
        const int s  = idx4 >> 4;
        const int d4 = (idx4 & 15) * 4;
        *(float4*)(vpl + s*72 + d4) =
            *(const float4*)(g_qkv + (row0 + s) * QKVN + vcol + d4);
    }
    SKu[tid] = f2tf32(g_ksum[(size_t)cid * NF + tid]);
    __syncthreads();

#pragma unroll
    for (int it = 0; it < 16; ++it) {
        const int wid2 = it * 256 + tid;
        const int ln   = wid2 & 31;
        const int nsub = (wid2 >> 5) & 7;
        const int ks   = wid2 >> 8;
        const int qc2 = ln & 3, qr2 = ln >> 2;
        const int s0 = ks*8 + qc2, d0 = nsub*8 + qr2;
        uint2 u;
        u.x = f2tf32(vpl[s0*72 + d0]);
        u.y = f2tf32(vpl[(s0+4)*72 + d0]);
        *(uint2*)(VBp + wid2*2) = u;
    }
    __syncthreads();

    float acc[2][8][4];
#pragma unroll
    for (int mt = 0; mt < 2; mt++)
#pragma unroll
        for (int nt = 0; nt < 8; nt++)
#pragma unroll
            for (int c = 0; c < 4; c++) acc[mt][nt][c] = 0.f;

#pragma unroll 4
    for (int ks = 0; ks < 16; ++ks) {
        const uint32_t* ab = KPs + ks*2048;
        uint4 a0 = *(const uint4*)(ab + (warp*2 + 0)*128 + lane*4);
        uint4 a1 = *(const uint4*)(ab + (warp*2 + 1)*128 + lane*4);
#pragma unroll
        for (int nt = 0; nt < 8; nt++) {
            uint2 bb = *(const uint2*)(VBp + ks*512 + nt*64 + lane*2);
            mma_tf32(acc[0][nt], a0.x, a0.y, a0.z, a0.w, bb.x, bb.y);
            mma_tf32(acc[1][nt], a1.x, a1.y, a1.z, a1.w, bb.x, bb.y);
        }
    }
    __syncthreads();

#pragma unroll
    for (int mt = 0; mt < 2; mt++)
#pragma unroll
        for (int nt = 0; nt < 8; nt++)
#pragma unroll
            for (int c = 0; c < 4; c++) {
                const int f = warp*32 + mt*16 + qr + ((c & 2) << 2);
                const int d = nt*8 + 2*qc + (c & 1);
                CBp[(f>>3)*512 + (d>>3)*64 + ((d&7)*4 + (f&3))*2 + ((f>>2)&1)]
                    = f2tf32(acc[mt][nt][c]);
            }

    {
        const uint4* src = (const uint4*)((const float*)g_qp + (size_t)cid * 32768);
        uint4* dst = (uint4*)QBs;
#pragma unroll
        for (int it = 0; it < 32; ++it)
            dst[it*256 + tid] = src[it*256 + tid];
    }
    __syncthreads();

    const int mg = warp >> 1;
    const int ng = warp & 1;
    float acc2[2][4][4];
    float accD[2][4];
#pragma unroll
    for (int mt = 0; mt < 2; mt++) {
#pragma unroll
        for (int c = 0; c < 4; c++) accD[mt][c] = 0.f;
#pragma unroll
        for (int nt = 0; nt < 4; nt++)
#pragma unroll
            for (int c = 0; c < 4; c++) acc2[mt][nt][c] = 0.f;
    }

#pragma unroll 4
    for (int ks = 0; ks < 32; ++ks) {
        const uint32_t* qb = QBs + ks*1024;
        uint4 a0 = *(const uint4*)(qb + (mg*2 + 0)*128 + lane*4);
        uint4 a1 = *(const uint4*)(qb + (mg*2 + 1)*128 + lane*4);
        const uint32_t sb0 = SKu[ks*8 + qc];
        const uint32_t sb1 = SKu[ks*8 + qc + 4];
#pragma unroll
        for (int nt = 0; nt < 4; nt++) {
            uint2 bb = *(const uint2*)(CBp + ks*512 + (ng*4 + nt)*64 + lane*2);
            mma_tf32(acc2[0][nt], a0.x, a0.y, a0.z, a0.w, bb.x, bb.y);
            mma_tf32(acc2[1][nt], a1.x, a1.y, a1.z, a1.w, bb.x, bb.y);
        }
        mma_tf32(accD[0], a0.x, a0.y, a0.z, a0.w, sb0, sb1);
        mma_tf32(accD[1], a1.x, a1.y, a1.z, a1.w, sb0, sb1);
    }
    __syncthreads();    // CBp reads done; ATs alias-write next

    // scatter packed att fragments into smem
#pragma unroll
    for (int mt = 0; mt < 2; mt++) {
        const float d0 = 1.0f / (accD[mt][0] + 1e-4f);
        const float d1 = 1.0f / (accD[mt][2] + 1e-4f);
#pragma unroll
        for (int nt = 0; nt < 4; nt++) {
#pragma unroll
            for (int c = 0; c < 4; c++) {
                const int r   = mg*32 + mt*16 + qr + (c & 2) * 4;   // +8 if c>=2
                const int col = (ng*4 + nt)*8 + 2*qc + (c & 1);
                const float dinv = (c & 2) ? d1 : d0;
                const int idx = (col>>4)*2048 + ((col>>3)&1)*1024 + (r>>4)*128
                              + ((r&7)*4 + (col&3))*4 + ((col>>2)&1)*2 + ((r>>3)&1);
                ATs[idx] = f2tf32(acc2[mt][nt][c] * dinv);
            }
        }
    }
    __syncthreads();

    // coalesced copy: per-chunk packed span = 8192 u32 at tile*65536 + h*8192
    {
        const int tile = b*32 + cc;
        uint4* gdst = (uint4*)(g_att + (size_t)tile * 65536 + (size_t)h * 8192);
        const uint4* ssrc = (const uint4*)ATs;
#pragma unroll
        for (int i = 0; i < 8; ++i)
            gdst[i*256 + tid] = ssrc[i*256 + tid];
    }
}

// =====================================================================
// launch
// =====================================================================
extern "C" void kernel_launch(void* const* d_in, const int* in_sizes, int n_in,
                              void* d_out, int out_size)
{
    const float *x = nullptr, *wqkv = nullptr, *wout = nullptr,
                *bout = nullptr, *proj = nullptr;
    for (int i = 0; i < n_in; i++) {
        switch (in_sizes[i]) {
            case MTOK * DIMM:  x    = (const float*)d_in[i]; break;
            case QKVN * DIMM:  wqkv = (const float*)d_in[i]; break;
            case DIMM * DIMM:  wout = (const float*)d_in[i]; break;
            case DIMM:         bout = (const float*)d_in[i]; break;
            case NF * DHD:     proj = (const float*)d_in[i]; break;
        }
    }

    cudaFuncSetAttribute(feature_mma, cudaFuncAttributeMaxDynamicSharedMemorySize, FEAT_SMEM_BYTES);
    cudaFuncSetAttribute(ctx_out_mma, cudaFuncAttributeMaxDynamicSharedMemorySize, CO_SMEM_BYTES);
    cudaFuncSetAttribute(tgemm_nt<false>, cudaFuncAttributeMaxDynamicSharedMemorySize, TG_SMEM_BYTES);
    cudaFuncSetAttribute(tgemm_nt<true>,  cudaFuncAttributeMaxDynamicSharedMemorySize, TG_SMEM_BYTES);

    float *qkvp = nullptr;
    uint32_t *attp = nullptr, *xr = nullptr, *wqr = nullptr, *wor = nullptr;
    cudaGetSymbolAddress((void**)&qkvp, g_qkv);
    cudaGetSymbolAddress((void**)&attp, g_att);
    cudaGetSymbolAddress((void**)&xr,   g_xr);
    cudaGetSymbolAddress((void**)&wqr,  g_wqr);
    cudaGetSymbolAddress((void**)&wor,  g_wor);

    // 0) pack GEMM operands into tf32 fragment layouts
    pack_A_tf32<<<(MTOK*DIMM/4 + 255)/256, 256>>>(x,    xr,  MTOK*DIMM/4);
    pack_B_tf32<<<(QKVN*DIMM/2 + 255)/256, 256>>>(wqkv, wqr, QKVN*DIMM/2);
    pack_B_tf32<<<(DIMM*DIMM/2 + 255)/256, 256>>>(wout, wor, DIMM*DIMM/2);

    // 1) qkv = x @ w_qkv^T   (128x128, 2 CTAs/SM, cp.async)
    tgemm_nt<false><<<dim3(QKVN/128, MTOK/128), 256, TG_SMEM_BYTES>>>(
        xr, wqr, nullptr, qkvp, MTOK, QKVN, DIMM);
    // 2) q'/k' feature maps -> fragment-packed layouts (+ksum)
    feature_mma<<<dim3(NCHUNK, 2), 256, FEAT_SMEM_BYTES>>>(proj);
    // 3+4) fused ctx + out -> att (packed tf32)
    ctx_out_mma<<<NCHUNK, 256, CO_SMEM_BYTES>>>();
    // 5) final = att @ w_out^T + b_out
    tgemm_nt<true><<<dim3(DIMM/128, MTOK/128), 256, TG_SMEM_BYTES>>>(
        attp, wor, bout, (float*)d_out, MTOK, DIMM, DIMM);
}

// round 12
// speedup vs baseline: 3.5833x; 1.1014x over previous
#include <cuda_runtime.h>
#include <cstdint>

// ---------------- problem constants ----------------
#define NB   4
#define SEQ  4096
#define DIMM 512
#define NH   8
#define DHD  64
#define NF   256
#define CSZ  128
#define NCH  32
#define MTOK (NB*SEQ)            // 16384
#define QKVN (3*DIMM)            // 1536
#define NCHUNK (NB*NH*NCH)       // 1024

// ---------------- device scratch ----------------
__device__ float g_qkv  [MTOK * QKVN];
// q'/k' fragment-packed per-chunk (32768 u32 each chunk)
__device__ float g_qp   [NB*NH*SEQ*NF];
__device__ float g_kp   [NB*NH*SEQ*NF];
__device__ float g_ksumP[2 * NCHUNK * NF];     // [half][chunk][f] partials
// GEMM operands in fragment-packed tf32 global layouts
__device__ uint32_t g_att [MTOK * DIMM];   // packed A for GEMM2 (written by ctx_out)
__device__ uint32_t g_xr  [MTOK * DIMM];   // packed A for GEMM1
__device__ uint32_t g_wqr [QKVN * DIMM];   // packed B for GEMM1
__device__ uint32_t g_wor [DIMM * DIMM];   // packed B for GEMM2

__device__ __forceinline__ uint32_t f2tf32(float f) {
    uint32_t r;
    asm("cvt.rna.tf32.f32 %0, %1;" : "=r"(r) : "f"(f));
    return r;
}

__device__ __forceinline__ void mma_tf32(float acc[4],
                                         uint32_t a0, uint32_t a1, uint32_t a2, uint32_t a3,
                                         uint32_t b0, uint32_t b1)
{
    asm volatile(
        "mma.sync.aligned.m16n8k8.row.col.f32.tf32.tf32.f32 "
        "{%0,%1,%2,%3}, {%4,%5,%6,%7}, {%8,%9}, {%0,%1,%2,%3};"
        : "+f"(acc[0]), "+f"(acc[1]), "+f"(acc[2]), "+f"(acc[3])
        : "r"(a0), "r"(a1), "r"(a2), "r"(a3), "r"(b0), "r"(b1));
}

// =====================================================================
// Pack kernels (unchanged)
// =====================================================================
__global__ void pack_A_tf32(const float* __restrict__ src, uint32_t* __restrict__ dst, int n4)
{
    int gid = blockIdx.x * blockDim.x + threadIdx.x;
    if (gid >= n4) return;
    const int lane = gid & 31, sub = (gid >> 5) & 7, kg = (gid >> 8) & 1;
    const int kt = (gid >> 9) & 31, tile = gid >> 14;
    const int qr = lane >> 2, qc = lane & 3;
    const int row = tile*128 + sub*16 + qr;
    const int col = kt*16 + kg*8 + qc;
    const float* s0 = src + (size_t)row * 512 + col;
    uint4 u;
    u.x = f2tf32(s0[0]);
    u.y = f2tf32(s0[8*512]);
    u.z = f2tf32(s0[4]);
    u.w = f2tf32(s0[8*512 + 4]);
    *(uint4*)(dst + (size_t)gid * 4) = u;
}

__global__ void pack_B_tf32(const float* __restrict__ src, uint32_t* __restrict__ dst, int n2)
{
    int gid = blockIdx.x * blockDim.x + threadIdx.x;
    if (gid >= n2) return;
    const int lane = gid & 31, nsub = (gid >> 5) & 15, kg = (gid >> 9) & 1;
    const int kt = (gid >> 10) & 31, tile = gid >> 15;
    const int qr = lane >> 2, qc = lane & 3;
    const int row = tile*128 + nsub*8 + qr;
    const int col = kt*16 + kg*8 + qc;
    const float* s0 = src + (size_t)row * 512 + col;
    uint2 u;
    u.x = f2tf32(s0[0]);
    u.y = f2tf32(s0[4]);
    *(uint2*)(dst + (size_t)gid * 2) = u;
}

// =====================================================================
// TF32 GEMM NT (unchanged): 128x128, cp.async, 2 CTAs/SM.
// =====================================================================
#define TG_SMEM_BYTES 65536

template<bool BIAS>
__global__ __launch_bounds__(256, 2)
void tgemm_nt(const uint32_t* __restrict__ Apk, const uint32_t* __restrict__ Bpk,
              const float* __restrict__ bias, float* __restrict__ C,
              int M, int N, int K)
{
    extern __shared__ uint32_t smg[];
    const uint32_t smb = (uint32_t)__cvta_generic_to_shared(smg);

    const int tid  = threadIdx.x;
    const int lane = tid & 31;
    const int warp = tid >> 5;
    const int mg   = warp >> 1;
    const int ng   = warp & 1;
    const int qr   = lane >> 2;
    const int qc   = lane & 3;

    const int KT = K >> 4;
    const size_t aBase = (size_t)blockIdx.y * KT * 2048;
    const size_t bBase = (size_t)blockIdx.x * KT * 2048;
    const int bm = blockIdx.y * 128;
    const int bn = blockIdx.x * 128;

    auto issue = [&](int kt, int s) {
        const uint32_t sb = smb + s * 4096 * 4;
        const uint32_t* gA = Apk + aBase + (size_t)kt * 2048;
        const uint32_t* gB = Bpk + bBase + (size_t)kt * 2048;
#pragma unroll
        for (int i = 0; i < 2; ++i) {
            const int j = tid + i * 256;
            asm volatile("cp.async.cg.shared.global [%0], [%1], 16;"
                         :: "r"(sb + j * 16), "l"(gA + j * 4) : "memory");
            asm volatile("cp.async.cg.shared.global [%0], [%1], 16;"
                         :: "r"(sb + 8192 + j * 16), "l"(gB + j * 4) : "memory");
        }
    };

    float acc[2][8][4];
#pragma unroll
    for (int i = 0; i < 2; i++)
#pragma unroll
        for (int nt = 0; nt < 8; nt++)
#pragma unroll
            for (int c = 0; c < 4; c++) acc[i][nt][c] = 0.f;

#pragma unroll
    for (int s = 0; s < 3; ++s) {
        issue(s, s);
        asm volatile("cp.async.commit_group;" ::: "memory");
    }

    for (int kt = 0; kt < KT; ++kt) {
        asm volatile("cp.async.wait_group 2;" ::: "memory");
        __syncthreads();
        const uint32_t* st = smg + (kt & 3) * 4096;
#pragma unroll
        for (int kg = 0; kg < 2; ++kg) {
            const uint32_t* ab = st + kg * 1024;
            const uint32_t* bb = st + 2048 + kg * 1024;
            uint4 a[2];
#pragma unroll
            for (int i = 0; i < 2; i++)
                a[i] = *(const uint4*)&ab[(mg*2 + i) * 128 + lane*4];
            uint2 bf[8];
#pragma unroll
            for (int nt = 0; nt < 8; nt++)
                bf[nt] = *(const uint2*)&bb[(ng*8 + nt) * 64 + lane*2];
#pragma unroll
            for (int i = 0; i < 2; i++)
#pragma unroll
                for (int nt = 0; nt < 8; nt++)
                    mma_tf32(acc[i][nt], a[i].x, a[i].y, a[i].z, a[i].w,
                             bf[nt].x, bf[nt].y);
        }
        const int nkt = kt + 3;
        if (nkt < KT) issue(nkt, nkt & 3);
        asm volatile("cp.async.commit_group;" ::: "memory");
    }

#pragma unroll
    for (int i = 0; i < 2; i++) {
        const int r0 = bm + (mg*2 + i) * 16 + qr;
#pragma unroll
        for (int nt = 0; nt < 8; nt++) {
            const int c0 = bn + (ng*8 + nt) * 8 + 2*qc;
            float v0 = acc[i][nt][0], v1 = acc[i][nt][1];
            float v2 = acc[i][nt][2], v3 = acc[i][nt][3];
            if (BIAS) {
                const float b0 = __ldg(bias + c0), b1 = __ldg(bias + c0 + 1);
                v0 += b0; v1 += b1; v2 += b0; v3 += b1;
            }
            *(float2*)(C + (size_t)r0       * N + c0) = make_float2(v0, v1);
            *(float2*)(C + (size_t)(r0 + 8) * N + c0) = make_float2(v2, v3);
        }
    }
}

// =====================================================================
// Feature kernel, half-chunk blocks (64 s-rows), 2 CTAs/SM.
// grid = (NCHUNK, 4): y = half*2 + isK.
// smem (u32): APK 8*516=4128 | PPK @4128 8*2052=16416 -> 20544
//             sm_e aliases base (64*264=16896 <= 20544)
//             RMAX @20544: 256 -> total 20800 u32 = 83200 B
// =====================================================================
#define FAPK_STRIDE 516
#define FPPK_STRIDE 2052
#define FPPK_BASE   4128
#define FRMAX_BASE  20544
#define FEAT_SMEM_BYTES (20800 * 4)

__global__ __launch_bounds__(256, 2)
void feature_mma(const float* __restrict__ proj)
{
    extern __shared__ uint32_t smu[];
    uint32_t* APK = smu;
    uint32_t* PPK = smu + FPPK_BASE;
    float*    sm_e = (float*)smu;
    float*    RMAX = (float*)(smu + FRMAX_BASE);

    const int cid  = blockIdx.x;
    const int isK  = blockIdx.y & 1;
    const int half = blockIdx.y >> 1;
    const int b  = cid >> 8;
    const int h  = (cid >> 5) & 7;
    const int cc = cid & 31;
    const size_t row0h  = (size_t)b * SEQ + (size_t)cc * CSZ + half * 64;
    const int   colbase = isK * DIMM + h * DHD;
    const float scale   = isK ? 1.0f : 0.125f;
    const int STR = isK ? 264 : 260;
    const int tid  = threadIdx.x;
    const int lane = tid & 31;
    const int warp = tid >> 5;
    const int wgm  = warp >> 2;     // 0..1 : 32 s-rows each
    const int fg   = warp & 3;      // 0..3 : 64 f each
    const int qr   = lane >> 2;
    const int qc   = lane & 3;

    // ---- load t half-chunk [64 s][64 d] -> packed A fragments ----
#pragma unroll
    for (int it = 0; it < 4; ++it) {
        const int idx4 = it * 256 + tid;          // 0..1023
        const int s  = idx4 >> 4;                 // 0..63
        const int d4 = (idx4 & 15) * 4;
        float4 v = *(const float4*)(g_qkv + (row0h + s) * QKVN + colbase + d4);
        const int ks   = d4 >> 3;
        const int hi   = (d4 >> 2) & 1;
        const int sub  = s >> 4;                  // 0..3
        const int qrS  = s & 7;
        const int halfS= (s >> 3) & 1;
        const int word = hi * 2 + halfS;
        uint32_t* base = APK + ks * FAPK_STRIDE + sub * 128 + (qrS << 4);
        base[0*4 + word] = f2tf32(v.x * scale);
        base[1*4 + word] = f2tf32(v.y * scale);
        base[2*4 + word] = f2tf32(v.z * scale);
        base[3*4 + word] = f2tf32(v.w * scale);
    }
    // ---- load proj [256 f][64 d] -> packed B fragments ----
#pragma unroll
    for (int it = 0; it < 16; ++it) {
        const int idx4 = it * 256 + tid;
        const int f  = idx4 >> 4;
        const int d4 = (idx4 & 15) * 4;
        float4 v = *(const float4*)(proj + f * DHD + d4);
        const int ks   = d4 >> 3;
        const int hi   = (d4 >> 2) & 1;
        const int nsub = f >> 3;
        const int qrF  = f & 7;
        uint32_t* base = PPK + ks * FPPK_STRIDE + nsub * 64 + (qrF << 3);
        base[0*2 + hi] = f2tf32(v.x);
        base[1*2 + hi] = f2tf32(v.y);
        base[2*2 + hi] = f2tf32(v.z);
        base[3*2 + hi] = f2tf32(v.w);
    }
    __syncthreads();

    float acc[2][8][4];
#pragma unroll
    for (int mt = 0; mt < 2; mt++)
#pragma unroll
        for (int nt = 0; nt < 8; nt++)
#pragma unroll
            for (int c = 0; c < 4; c++) acc[mt][nt][c] = 0.f;

    const int rl4 = lane * 4;
    const int rl2 = lane * 2;
#pragma unroll
    for (int ks = 0; ks < 8; ++ks) {
        const uint32_t* abase = APK + ks * FAPK_STRIDE;
        const uint32_t* pbase = PPK + ks * FPPK_STRIDE;
        uint4 a0 = *(const uint4*)&abase[(wgm*2 + 0) * 128 + rl4];
        uint4 a1 = *(const uint4*)&abase[(wgm*2 + 1) * 128 + rl4];
#pragma unroll
        for (int nt = 0; nt < 8; nt++) {
            uint2 bb = *(const uint2*)&pbase[(fg*8 + nt) * 64 + rl2];
            mma_tf32(acc[0][nt], a0.x, a0.y, a0.z, a0.w, bb.x, bb.y);
            mma_tf32(acc[1][nt], a1.x, a1.y, a1.z, a1.w, bb.x, bb.y);
        }
    }

    // rowmax: per-thread partial, qc-shuffle, 4 f-warps via smem
    float mloc[2][2];
#pragma unroll
    for (int mt = 0; mt < 2; mt++)
#pragma unroll
        for (int hh = 0; hh < 2; hh++) {
            float m = -1e30f;
#pragma unroll
            for (int nt = 0; nt < 8; nt++) {
                m = fmaxf(m, acc[mt][nt][hh*2+0]);
                m = fmaxf(m, acc[mt][nt][hh*2+1]);
            }
            m = fmaxf(m, __shfl_xor_sync(0xffffffffu, m, 1));
            m = fmaxf(m, __shfl_xor_sync(0xffffffffu, m, 2));
            mloc[mt][hh] = m;
        }
    if (qc == 0) {
#pragma unroll
        for (int mt = 0; mt < 2; mt++)
#pragma unroll
            for (int hh = 0; hh < 2; hh++)
                RMAX[fg*64 + wgm*32 + mt*16 + hh*8 + qr] = mloc[mt][hh];
    }
    __syncthreads();

    float rm[2][2];
#pragma unroll
    for (int mt = 0; mt < 2; mt++)
#pragma unroll
        for (int hh = 0; hh < 2; hh++) {
            const int row = wgm*32 + mt*16 + hh*8 + qr;
            float m = fmaxf(RMAX[row], RMAX[64 + row]);
            m = fmaxf(m, RMAX[128 + row]);
            rm[mt][hh] = fmaxf(m, RMAX[192 + row]);
        }

    // exp + tf32-round, stage into sm_e[row_local][STR]
#pragma unroll
    for (int mt = 0; mt < 2; mt++)
#pragma unroll
        for (int hh = 0; hh < 2; hh++) {
            const int row = wgm*32 + mt*16 + hh*8 + qr;
#pragma unroll
            for (int nt = 0; nt < 8; nt++) {
                const int f = fg*64 + nt*8 + 2*qc;
                float e0 = __expf(acc[mt][nt][hh*2+0] - rm[mt][hh]);
                float e1 = __expf(acc[mt][nt][hh*2+1] - rm[mt][hh]);
                sm_e[row*STR + f]     = __uint_as_float(f2tf32(e0));
                sm_e[row*STR + f + 1] = __uint_as_float(f2tf32(e1));
            }
        }
    __syncthreads();

    if (isK) {
        // k' half -> packed A-frags [ks16][sub16][lane][w4], ks in [8h, 8h+8)
        uint32_t* outp = (uint32_t*)g_kp + (size_t)cid * 32768;
#pragma unroll
        for (int it = 0; it < 16; ++it) {
            const int gid = it * 256 + tid;       // 0..4095
            const int ln  = gid & 31;
            const int sub = (gid >> 5) & 15;
            const int ksl = gid >> 9;             // 0..7
            const int ks  = half*8 + ksl;
            const int qc2 = ln & 3, qr2 = ln >> 2;
            const int s0l = ksl*8 + qc2;          // local row
            const int f0  = sub*16 + qr2;
            uint4 u;
            u.x = __float_as_uint(sm_e[s0l*264 + f0]);
            u.y = __float_as_uint(sm_e[s0l*264 + f0 + 8]);
            u.z = __float_as_uint(sm_e[(s0l+4)*264 + f0]);
            u.w = __float_as_uint(sm_e[(s0l+4)*264 + f0 + 8]);
            *(uint4*)(outp + (size_t)(ks*2048 + sub*128 + ln*4)) = u;
        }
        // ksum partial over the 64 local rows
        float s = 0.f;
#pragma unroll 8
        for (int r = 0; r < 64; ++r) s += sm_e[r*264 + tid];
        g_ksumP[((size_t)half * NCHUNK + cid) * NF + tid] = s;
    } else {
        // q' half -> packed A-frags [ks32][sub8][lane][w4], sub in [4h, 4h+4)
        uint32_t* outp = (uint32_t*)g_qp + (size_t)cid * 32768;
#pragma unroll
        for (int it = 0; it < 16; ++it) {
            const int gid = it * 256 + tid;       // 0..4095
            const int ln  = gid & 31;
            const int subl = (gid >> 5) & 3;      // 0..3
            const int ks  = gid >> 7;             // 0..31
            const int sub = half*4 + subl;
            const int qc2 = ln & 3, qr2 = ln >> 2;
            const int r0l = subl*16 + qr2;        // local row
            const int f0  = ks*8 + qc2;
            uint4 u;
            u.x = __float_as_uint(sm_e[r0l*260 + f0]);
            u.y = __float_as_uint(sm_e[(r0l+8)*260 + f0]);
            u.z = __float_as_uint(sm_e[r0l*260 + f0 + 4]);
            u.w = __float_as_uint(sm_e[(r0l+8)*260 + f0 + 4]);
            *(uint4*)(outp + (size_t)(ks*1024 + sub*128 + ln*4)) = u;
        }
    }
}

// =====================================================================
// Fused ctx + out kernel v3 (FIXED smem map) — k'/q' A-frags direct
// from gmem; 2 CTAs/SM.
// smem (u32): region0 @0: max(vpl 9216, CBp 16384, ATs 8192) = 16384
//             VBp @16384: 8192  (FULL size — was the R11 overflow)
//             SKu @24576: 256 -> total 24832 u32 = 99328 B
// =====================================================================
#define CO_SMEM_BYTES (24832 * 4)

__global__ __launch_bounds__(256, 2)
void ctx_out_mma()
{
    extern __shared__ uint32_t smu[];
    float*    vpl = (float*)smu;           // [128][72] staging (aliases CBp)
    uint32_t* CBp = smu;                   // [ks32][nsub8][lane][w2]
    uint32_t* ATs = smu;                   // packed att staging (aliases CBp)
    uint32_t* VBp = smu + 16384;           // [ks16][nsub8][lane][w2] = 8192 u32
    uint32_t* SKu = smu + 24576;

    const int cid = blockIdx.x;
    const int b  = cid >> 8;
    const int h  = (cid >> 5) & 7;
    const int cc = cid & 31;
    const size_t row0 = (size_t)b * SEQ + (size_t)cc * CSZ;
    const int vcol = 2 * DIMM + h * DHD;
    const int tid  = threadIdx.x;
    const int lane = tid & 31;
    const int warp = tid >> 5;
    const int qr   = lane >> 2;
    const int qc   = lane & 3;

    const uint32_t* kbase = (const uint32_t*)g_kp + (size_t)cid * 32768;
    const uint32_t* qbase = (const uint32_t*)g_qp + (size_t)cid * 32768;

    // ---- load v into plain tile [s][72] (aliases CBp; dead before CBp write) ----
#pragma unroll
    for (int it = 0; it < 8; ++it) {
        const int idx4 = it * 256 + tid;
        const int s  = idx4 >> 4;
        const int d4 = (idx4 & 15) * 4;
        *(float4*)(vpl + s*72 + d4) =
            *(const float4*)(g_qkv + (row0 + s) * QKVN + vcol + d4);
    }
    if (tid < NF)
        SKu[tid] = f2tf32(g_ksumP[(size_t)cid * NF + tid] +
                          g_ksumP[((size_t)NCHUNK + cid) * NF + tid]);
    __syncthreads();

    // ---- pack v into B-frags [ks16][nsub8][lane][w2] ----
#pragma unroll
    for (int it = 0; it < 16; ++it) {
        const int wid2 = it * 256 + tid;       // 0..4095
        const int ln   = wid2 & 31;
        const int nsub = (wid2 >> 5) & 7;
        const int ks   = wid2 >> 8;
        const int qc2 = ln & 3, qr2 = ln >> 2;
        const int s0 = ks*8 + qc2, d0 = nsub*8 + qr2;
        uint2 u;
        u.x = f2tf32(vpl[s0*72 + d0]);
        u.y = f2tf32(vpl[(s0+4)*72 + d0]);
        *(uint2*)(VBp + wid2*2) = u;
    }
    __syncthreads();

    // ---- P1: ctx[f][d], warp w -> f subs {2w,2w+1}; k' A-frags from gmem ----
    float acc[2][8][4];
#pragma unroll
    for (int mt = 0; mt < 2; mt++)
#pragma unroll
        for (int nt = 0; nt < 8; nt++)
#pragma unroll
            for (int c = 0; c < 4; c++) acc[mt][nt][c] = 0.f;

#pragma unroll 4
    for (int ks = 0; ks < 16; ++ks) {
        uint4 a0 = *(const uint4*)(kbase + ks*2048 + (warp*2 + 0)*128 + lane*4);
        uint4 a1 = *(const uint4*)(kbase + ks*2048 + (warp*2 + 1)*128 + lane*4);
#pragma unroll
        for (int nt = 0; nt < 8; nt++) {
            uint2 bb = *(const uint2*)(VBp + ks*512 + nt*64 + lane*2);
            mma_tf32(acc[0][nt], a0.x, a0.y, a0.z, a0.w, bb.x, bb.y);
            mma_tf32(acc[1][nt], a1.x, a1.y, a1.z, a1.w, bb.x, bb.y);
        }
    }
    __syncthreads();   // vpl reads long done; CBp alias-write next

    // ---- scatter ctx -> B-frags for P2: [ks32][nsub8][lane][w2] ----
#pragma unroll
    for (int mt = 0; mt < 2; mt++)
#pragma unroll
        for (int nt = 0; nt < 8; nt++)
#pragma unroll
            for (int c = 0; c < 4; c++) {
                const int f = warp*32 + mt*16 + qr + ((c & 2) << 2);
                const int d = nt*8 + 2*qc + (c & 1);
                CBp[(f>>3)*512 + (d>>3)*64 + ((d&7)*4 + (f&3))*2 + ((f>>2)&1)]
                    = f2tf32(acc[mt][nt][c]);
            }
    __syncthreads();

    // ---- P2: out + D, warp tile 16(s) x 64(d); q' A-frags from gmem ----
    float acc2[8][4];
    float accD[4];
#pragma unroll
    for (int c = 0; c < 4; c++) accD[c] = 0.f;
#pragma unroll
    for (int nt = 0; nt < 8; nt++)
#pragma unroll
        for (int c = 0; c < 4; c++) acc2[nt][c] = 0.f;

#pragma unroll 4
    for (int ks = 0; ks < 32; ++ks) {
        uint4 a0 = *(const uint4*)(qbase + ks*1024 + warp*128 + lane*4);
        const uint32_t sb0 = SKu[ks*8 + qc];
        const uint32_t sb1 = SKu[ks*8 + qc + 4];
#pragma unroll
        for (int nt = 0; nt < 8; nt++) {
            uint2 bb = *(const uint2*)(CBp + ks*512 + nt*64 + lane*2);
            mma_tf32(acc2[nt], a0.x, a0.y, a0.z, a0.w, bb.x, bb.y);
        }
        mma_tf32(accD, a0.x, a0.y, a0.z, a0.w, sb0, sb1);
    }
    __syncthreads();    // CBp reads done; ATs alias-write next

    // ---- scatter packed att fragments into smem ----
    {
        const float d0 = 1.0f / (accD[0] + 1e-4f);
        const float d1 = 1.0f / (accD[2] + 1e-4f);
#pragma unroll
        for (int nt = 0; nt < 8; nt++) {
#pragma unroll
            for (int c = 0; c < 4; c++) {
                const int r   = warp*16 + qr + (c & 2) * 4;   // +8 if c>=2
                const int col = nt*8 + 2*qc + (c & 1);
                const float dinv = (c & 2) ? d1 : d0;
                const int idx = (col>>4)*2048 + ((col>>3)&1)*1024 + (r>>4)*128
                              + ((r&7)*4 + (col&3))*4 + ((col>>2)&1)*2 + ((r>>3)&1);
                ATs[idx] = f2tf32(acc2[nt][c] * dinv);
            }
        }
    }
    __syncthreads();

    // ---- coalesced copy: packed span at tile*65536 + h*8192 ----
    {
        const int tile = b*32 + cc;
        uint4* gdst = (uint4*)(g_att + (size_t)tile * 65536 + (size_t)h * 8192);
        const uint4* ssrc = (const uint4*)ATs;
#pragma unroll
        for (int i = 0; i < 8; ++i)
            gdst[i*256 + tid] = ssrc[i*256 + tid];
    }
}

// =====================================================================
// launch
// =====================================================================
extern "C" void kernel_launch(void* const* d_in, const int* in_sizes, int n_in,
                              void* d_out, int out_size)
{
    const float *x = nullptr, *wqkv = nullptr, *wout = nullptr,
                *bout = nullptr, *proj = nullptr;
    for (int i = 0; i < n_in; i++) {
        switch (in_sizes[i]) {
            case MTOK * DIMM:  x    = (const float*)d_in[i]; break;
            case QKVN * DIMM:  wqkv = (const float*)d_in[i]; break;
            case DIMM * DIMM:  wout = (const float*)d_in[i]; break;
            case DIMM:         bout = (const float*)d_in[i]; break;
            case NF * DHD:     proj = (const float*)d_in[i]; break;
        }
    }

    cudaFuncSetAttribute(feature_mma, cudaFuncAttributeMaxDynamicSharedMemorySize, FEAT_SMEM_BYTES);
    cudaFuncSetAttribute(ctx_out_mma, cudaFuncAttributeMaxDynamicSharedMemorySize, CO_SMEM_BYTES);
    cudaFuncSetAttribute(tgemm_nt<false>, cudaFuncAttributeMaxDynamicSharedMemorySize, TG_SMEM_BYTES);
    cudaFuncSetAttribute(tgemm_nt<true>,  cudaFuncAttributeMaxDynamicSharedMemorySize, TG_SMEM_BYTES);

    float *qkvp = nullptr;
    uint32_t *attp = nullptr, *xr = nullptr, *wqr = nullptr, *wor = nullptr;
    cudaGetSymbolAddress((void**)&qkvp, g_qkv);
    cudaGetSymbolAddress((void**)&attp, g_att);
    cudaGetSymbolAddress((void**)&xr,   g_xr);
    cudaGetSymbolAddress((void**)&wqr,  g_wqr);
    cudaGetSymbolAddress((void**)&wor,  g_wor);

    // 0) pack GEMM operands into tf32 fragment layouts
    pack_A_tf32<<<(MTOK*DIMM/4 + 255)/256, 256>>>(x,    xr,  MTOK*DIMM/4);
    pack_B_tf32<<<(QKVN*DIMM/2 + 255)/256, 256>>>(wqkv, wqr, QKVN*DIMM/2);
    pack_B_tf32<<<(DIMM*DIMM/2 + 255)/256, 256>>>(wout, wor, DIMM*DIMM/2);

    // 1) qkv = x @ w_qkv^T
    tgemm_nt<false><<<dim3(QKVN/128, MTOK/128), 256, TG_SMEM_BYTES>>>(
        xr, wqr, nullptr, qkvp, MTOK, QKVN, DIMM);
    // 2) q'/k' feature maps (half-chunk blocks, 2 CTAs/SM) + ksum partials
    feature_mma<<<dim3(NCHUNK, 4), 256, FEAT_SMEM_BYTES>>>(proj);
    // 3+4) fused ctx + out (direct-gmem A-frags, 2 CTAs/SM) -> packed att
    ctx_out_mma<<<NCHUNK, 256, CO_SMEM_BYTES>>>();
    // 5) final = att @ w_out^T + b_out
    tgemm_nt<true><<<dim3(DIMM/128, MTOK/128), 256, TG_SMEM_BYTES>>>(
        attp, wor, bout, (float*)d_out, MTOK, DIMM, DIMM);
}

// round 13
// speedup vs baseline: 3.9348x; 1.0981x over previous
#include <cuda_runtime.h>
#include <cstdint>

// ---------------- problem constants ----------------
#define NB   4
#define SEQ  4096
#define DIMM 512
#define NH   8
#define DHD  64
#define NF   256
#define CSZ  128
#define NCH  32
#define MTOK (NB*SEQ)            // 16384
#define QKVN (3*DIMM)            // 1536
#define NCHUNK (NB*NH*NCH)       // 1024

// ---------------- device scratch ----------------
__device__ float g_qkv  [MTOK * QKVN];
// q'/k' fragment-packed per-chunk (32768 u32 each chunk)
__device__ float g_qp   [NB*NH*SEQ*NF];
__device__ float g_kp   [NB*NH*SEQ*NF];
__device__ float g_ksumP[2 * NCHUNK * NF];     // [half][chunk][f] partials
// GEMM operands in fragment-packed tf32 global layouts
__device__ uint32_t g_att [MTOK * DIMM];   // packed A for GEMM2 (written by ctx_out)
__device__ uint32_t g_xr  [MTOK * DIMM];   // packed A for GEMM1
__device__ uint32_t g_wqr [QKVN * DIMM];   // packed B for GEMM1
__device__ uint32_t g_wor [DIMM * DIMM];   // packed B for GEMM2
__device__ uint32_t g_ppk [8 * 32 * 64];   // proj B-frags [ks8][nsub32][lane32][w2]

__device__ __forceinline__ uint32_t f2tf32(float f) {
    uint32_t r;
    asm("cvt.rna.tf32.f32 %0, %1;" : "=r"(r) : "f"(f));
    return r;
}

__device__ __forceinline__ void mma_tf32(float acc[4],
                                         uint32_t a0, uint32_t a1, uint32_t a2, uint32_t a3,
                                         uint32_t b0, uint32_t b1)
{
    asm volatile(
        "mma.sync.aligned.m16n8k8.row.col.f32.tf32.tf32.f32 "
        "{%0,%1,%2,%3}, {%4,%5,%6,%7}, {%8,%9}, {%0,%1,%2,%3};"
        : "+f"(acc[0]), "+f"(acc[1]), "+f"(acc[2]), "+f"(acc[3])
        : "r"(a0), "r"(a1), "r"(a2), "r"(a3), "r"(b0), "r"(b1));
}

// =====================================================================
// Pack kernels
// =====================================================================
__global__ void pack_A_tf32(const float* __restrict__ src, uint32_t* __restrict__ dst, int n4)
{
    int gid = blockIdx.x * blockDim.x + threadIdx.x;
    if (gid >= n4) return;
    const int lane = gid & 31, sub = (gid >> 5) & 7, kg = (gid >> 8) & 1;
    const int kt = (gid >> 9) & 31, tile = gid >> 14;
    const int qr = lane >> 2, qc = lane & 3;
    const int row = tile*128 + sub*16 + qr;
    const int col = kt*16 + kg*8 + qc;
    const float* s0 = src + (size_t)row * 512 + col;
    uint4 u;
    u.x = f2tf32(s0[0]);
    u.y = f2tf32(s0[8*512]);
    u.z = f2tf32(s0[4]);
    u.w = f2tf32(s0[8*512 + 4]);
    *(uint4*)(dst + (size_t)gid * 4) = u;
}

__global__ void pack_B_tf32(const float* __restrict__ src, uint32_t* __restrict__ dst, int n2)
{
    int gid = blockIdx.x * blockDim.x + threadIdx.x;
    if (gid >= n2) return;
    const int lane = gid & 31, nsub = (gid >> 5) & 15, kg = (gid >> 9) & 1;
    const int kt = (gid >> 10) & 31, tile = gid >> 15;
    const int qr = lane >> 2, qc = lane & 3;
    const int row = tile*128 + nsub*8 + qr;
    const int col = kt*16 + kg*8 + qc;
    const float* s0 = src + (size_t)row * 512 + col;
    uint2 u;
    u.x = f2tf32(s0[0]);
    u.y = f2tf32(s0[4]);
    *(uint2*)(dst + (size_t)gid * 2) = u;
}

// proj [256 f][64 d] -> B-frags [ks8][nsub32][lane32][w2]  (8192 uint2)
__global__ void pack_P_tf32(const float* __restrict__ proj, uint32_t* __restrict__ dst)
{
    int gid = blockIdx.x * blockDim.x + threadIdx.x;   // 0..8191
    if (gid >= 8192) return;
    const int ln = gid & 31, nsub = (gid >> 5) & 31, ks = gid >> 10;
    const int qr = ln >> 2, qc = ln & 3;
    const int f = nsub*8 + qr;
    const int d = ks*8 + qc;
    uint2 u;
    u.x = f2tf32(proj[f*DHD + d]);
    u.y = f2tf32(proj[f*DHD + d + 4]);
    *(uint2*)(dst + ks*2048 + nsub*64 + ln*2) = u;
}

// =====================================================================
// TF32 GEMM NT, BK=32 stages (2 kt-blocks/stage), 3-stage cp.async
// pipeline, 128x128 tile, 256 threads (8 warps, 4m x 2n), 2 CTAs/SM.
// stage (u32): A 4096 @0 | B 4096 @4096 ; stride 8192. 3 stages = 96KB.
// =====================================================================
#define TG_SMEM_BYTES (3 * 8192 * 4)     // 98304

template<bool BIAS>
__global__ __launch_bounds__(256, 2)
void tgemm_nt(const uint32_t* __restrict__ Apk, const uint32_t* __restrict__ Bpk,
              const float* __restrict__ bias, float* __restrict__ C,
              int M, int N, int K)
{
    extern __shared__ uint32_t smg[];
    const uint32_t smb = (uint32_t)__cvta_generic_to_shared(smg);

    const int tid  = threadIdx.x;
    const int lane = tid & 31;
    const int warp = tid >> 5;
    const int mg   = warp >> 1;
    const int ng   = warp & 1;
    const int qr   = lane >> 2;
    const int qc   = lane & 3;

    const int KT  = K >> 4;
    const int KT2 = K >> 5;              // 32-k stages
    const size_t aBase = (size_t)blockIdx.y * KT * 2048;
    const size_t bBase = (size_t)blockIdx.x * KT * 2048;
    const int bm = blockIdx.y * 128;
    const int bn = blockIdx.x * 128;

    auto issue = [&](int ktb, int s) {
        const uint32_t sb = smb + s * 8192 * 4;
        const uint32_t* gA = Apk + aBase + (size_t)ktb * 4096;
        const uint32_t* gB = Bpk + bBase + (size_t)ktb * 4096;
#pragma unroll
        for (int i = 0; i < 4; ++i) {
            const int j = tid + i * 256;
            asm volatile("cp.async.cg.shared.global [%0], [%1], 16;"
                         :: "r"(sb + j * 16), "l"(gA + j * 4) : "memory");
            asm volatile("cp.async.cg.shared.global [%0], [%1], 16;"
                         :: "r"(sb + 16384 + j * 16), "l"(gB + j * 4) : "memory");
        }
    };

    float acc[2][8][4];
#pragma unroll
    for (int i = 0; i < 2; i++)
#pragma unroll
        for (int nt = 0; nt < 8; nt++)
#pragma unroll
            for (int c = 0; c < 4; c++) acc[i][nt][c] = 0.f;

    // prologue: 2 stages in flight
    issue(0, 0);
    asm volatile("cp.async.commit_group;" ::: "memory");
    issue(1, 1);
    asm volatile("cp.async.commit_group;" ::: "memory");

    int stg = 0;
    for (int ktb = 0; ktb < KT2; ++ktb) {
        asm volatile("cp.async.wait_group 1;" ::: "memory");
        __syncthreads();
        const uint32_t* st = smg + stg * 8192;
#pragma unroll
        for (int sk = 0; sk < 4; ++sk) {          // 2 ktl x 2 kg
            const uint32_t* ab = st + sk * 1024;
            const uint32_t* bb = st + 4096 + sk * 1024;
            uint4 a[2];
#pragma unroll
            for (int i = 0; i < 2; i++)
                a[i] = *(const uint4*)&ab[(mg*2 + i) * 128 + lane*4];
            uint2 bf[8];
#pragma unroll
            for (int nt = 0; nt < 8; nt++)
                bf[nt] = *(const uint2*)&bb[(ng*8 + nt) * 64 + lane*2];
#pragma unroll
            for (int i = 0; i < 2; i++)
#pragma unroll
                for (int nt = 0; nt < 8; nt++)
                    mma_tf32(acc[i][nt], a[i].x, a[i].y, a[i].z, a[i].w,
                             bf[nt].x, bf[nt].y);
        }
        if (ktb + 2 < KT2) {
            const int ns = (stg + 2 >= 3) ? stg - 1 : stg + 2;
            issue(ktb + 2, ns);
        }
        asm volatile("cp.async.commit_group;" ::: "memory");
        stg = (stg + 1 == 3) ? 0 : stg + 1;
    }

    // epilogue
#pragma unroll
    for (int i = 0; i < 2; i++) {
        const int r0 = bm + (mg*2 + i) * 16 + qr;
#pragma unroll
        for (int nt = 0; nt < 8; nt++) {
            const int c0 = bn + (ng*8 + nt) * 8 + 2*qc;
            float v0 = acc[i][nt][0], v1 = acc[i][nt][1];
            float v2 = acc[i][nt][2], v3 = acc[i][nt][3];
            if (BIAS) {
                const float b0 = __ldg(bias + c0), b1 = __ldg(bias + c0 + 1);
                v0 += b0; v1 += b1; v2 += b0; v3 += b1;
            }
            *(float2*)(C + (size_t)r0       * N + c0) = make_float2(v0, v1);
            *(float2*)(C + (size_t)(r0 + 8) * N + c0) = make_float2(v2, v3);
        }
    }
}

// =====================================================================
// Feature kernel, half-chunk blocks (64 s-rows), 2 CTAs/SM.
// proj B-frags read directly from gmem (pre-packed, L2-resident).
// grid = (NCHUNK, 4): y = half*2 + isK.
// smem (u32): APK 8*516=4128 ; sm_e aliases base (64*264=16896)
//             RMAX @16896: 256 -> total 17152 u32 = 68608 B
// =====================================================================
#define FAPK_STRIDE 516
#define FRMAX_BASE  16896
#define FEAT_SMEM_BYTES (17152 * 4)

__global__ __launch_bounds__(256, 2)
void feature_mma(const uint32_t* __restrict__ Ppk)
{
    extern __shared__ uint32_t smu[];
    uint32_t* APK = smu;
    float*    sm_e = (float*)smu;
    float*    RMAX = (float*)(smu + FRMAX_BASE);

    const int cid  = blockIdx.x;
    const int isK  = blockIdx.y & 1;
    const int half = blockIdx.y >> 1;
    const int b  = cid >> 8;
    const int h  = (cid >> 5) & 7;
    const int cc = cid & 31;
    const size_t row0h  = (size_t)b * SEQ + (size_t)cc * CSZ + half * 64;
    const int   colbase = isK * DIMM + h * DHD;
    const float scale   = isK ? 1.0f : 0.125f;
    const int STR = isK ? 264 : 260;
    const int tid  = threadIdx.x;
    const int lane = tid & 31;
    const int warp = tid >> 5;
    const int wgm  = warp >> 2;     // 0..1 : 32 s-rows each
    const int fg   = warp & 3;      // 0..3 : 64 f each
    const int qr   = lane >> 2;
    const int qc   = lane & 3;

    // ---- load t half-chunk [64 s][64 d] -> packed A fragments ----
#pragma unroll
    for (int it = 0; it < 4; ++it) {
        const int idx4 = it * 256 + tid;          // 0..1023
        const int s  = idx4 >> 4;                 // 0..63
        const int d4 = (idx4 & 15) * 4;
        float4 v = *(const float4*)(g_qkv + (row0h + s) * QKVN + colbase + d4);
        const int ks   = d4 >> 3;
        const int hi   = (d4 >> 2) & 1;
        const int sub  = s >> 4;                  // 0..3
        const int qrS  = s & 7;
        const int halfS= (s >> 3) & 1;
        const int word = hi * 2 + halfS;
        uint32_t* base = APK + ks * FAPK_STRIDE + sub * 128 + (qrS << 4);
        base[0*4 + word] = f2tf32(v.x * scale);
        base[1*4 + word] = f2tf32(v.y * scale);
        base[2*4 + word] = f2tf32(v.z * scale);
        base[3*4 + word] = f2tf32(v.w * scale);
    }
    __syncthreads();

    float acc[2][8][4];
#pragma unroll
    for (int mt = 0; mt < 2; mt++)
#pragma unroll
        for (int nt = 0; nt < 8; nt++)
#pragma unroll
            for (int c = 0; c < 4; c++) acc[mt][nt][c] = 0.f;

    const int rl4 = lane * 4;
#pragma unroll
    for (int ks = 0; ks < 8; ++ks) {
        const uint32_t* abase = APK + ks * FAPK_STRIDE;
        const uint32_t* pbase = Ppk + ks * 2048;
        uint4 a0 = *(const uint4*)&abase[(wgm*2 + 0) * 128 + rl4];
        uint4 a1 = *(const uint4*)&abase[(wgm*2 + 1) * 128 + rl4];
#pragma unroll
        for (int nt = 0; nt < 8; nt++) {
            uint2 bb = __ldg((const uint2*)&pbase[(fg*8 + nt) * 64 + lane*2]);
            mma_tf32(acc[0][nt], a0.x, a0.y, a0.z, a0.w, bb.x, bb.y);
            mma_tf32(acc[1][nt], a1.x, a1.y, a1.z, a1.w, bb.x, bb.y);
        }
    }

    // rowmax: per-thread partial, qc-shuffle, 4 f-warps via smem
    float mloc[2][2];
#pragma unroll
    for (int mt = 0; mt < 2; mt++)
#pragma unroll
        for (int hh = 0; hh < 2; hh++) {
            float m = -1e30f;
#pragma unroll
            for (int nt = 0; nt < 8; nt++) {
                m = fmaxf(m, acc[mt][nt][hh*2+0]);
                m = fmaxf(m, acc[mt][nt][hh*2+1]);
            }
            m = fmaxf(m, __shfl_xor_sync(0xffffffffu, m, 1));
            m = fmaxf(m, __shfl_xor_sync(0xffffffffu, m, 2));
            mloc[mt][hh] = m;
        }
    if (qc == 0) {
#pragma unroll
        for (int mt = 0; mt < 2; mt++)
#pragma unroll
            for (int hh = 0; hh < 2; hh++)
                RMAX[fg*64 + wgm*32 + mt*16 + hh*8 + qr] = mloc[mt][hh];
    }
    __syncthreads();    // also fences APK reads before sm_e aliasing

    float rm[2][2];
#pragma unroll
    for (int mt = 0; mt < 2; mt++)
#pragma unroll
        for (int hh = 0; hh < 2; hh++) {
            const int row = wgm*32 + mt*16 + hh*8 + qr;
            float m = fmaxf(RMAX[row], RMAX[64 + row]);
            m = fmaxf(m, RMAX[128 + row]);
            rm[mt][hh] = fmaxf(m, RMAX[192 + row]);
        }

    // exp + tf32-round, stage into sm_e[row_local][STR]
#pragma unroll
    for (int mt = 0; mt < 2; mt++)
#pragma unroll
        for (int hh = 0; hh < 2; hh++) {
            const int row = wgm*32 + mt*16 + hh*8 + qr;
#pragma unroll
            for (int nt = 0; nt < 8; nt++) {
                const int f = fg*64 + nt*8 + 2*qc;
                float e0 = __expf(acc[mt][nt][hh*2+0] - rm[mt][hh]);
                float e1 = __expf(acc[mt][nt][hh*2+1] - rm[mt][hh]);
                sm_e[row*STR + f]     = __uint_as_float(f2tf32(e0));
                sm_e[row*STR + f + 1] = __uint_as_float(f2tf32(e1));
            }
        }
    __syncthreads();

    if (isK) {
        // k' half -> packed A-frags [ks16][sub16][lane][w4], ks in [8h, 8h+8)
        uint32_t* outp = (uint32_t*)g_kp + (size_t)cid * 32768;
#pragma unroll
        for (int it = 0; it < 16; ++it) {
            const int gid = it * 256 + tid;       // 0..4095
            const int ln  = gid & 31;
            const int sub = (gid >> 5) & 15;
            const int ksl = gid >> 9;             // 0..7
            const int ks  = half*8 + ksl;
            const int qc2 = ln & 3, qr2 = ln >> 2;
            const int s0l = ksl*8 + qc2;          // local row
            const int f0  = sub*16 + qr2;
            uint4 u;
            u.x = __float_as_uint(sm_e[s0l*264 + f0]);
            u.y = __float_as_uint(sm_e[s0l*264 + f0 + 8]);
            u.z = __float_as_uint(sm_e[(s0l+4)*264 + f0]);
            u.w = __float_as_uint(sm_e[(s0l+4)*264 + f0 + 8]);
            *(uint4*)(outp + (size_t)(ks*2048 + sub*128 + ln*4)) = u;
        }
        // ksum partial over the 64 local rows
        float s = 0.f;
#pragma unroll 8
        for (int r = 0; r < 64; ++r) s += sm_e[r*264 + tid];
        g_ksumP[((size_t)half * NCHUNK + cid) * NF + tid] = s;
    } else {
        // q' half -> packed A-frags [ks32][sub8][lane][w4], sub in [4h, 4h+4)
        uint32_t* outp = (uint32_t*)g_qp + (size_t)cid * 32768;
#pragma unroll
        for (int it = 0; it < 16; ++it) {
            const int gid = it * 256 + tid;       // 0..4095
            const int ln  = gid & 31;
            const int subl = (gid >> 5) & 3;      // 0..3
            const int ks  = gid >> 7;             // 0..31
            const int sub = half*4 + subl;
            const int qc2 = ln & 3, qr2 = ln >> 2;
            const int r0l = subl*16 + qr2;        // local row
            const int f0  = ks*8 + qc2;
            uint4 u;
            u.x = __float_as_uint(sm_e[r0l*260 + f0]);
            u.y = __float_as_uint(sm_e[(r0l+8)*260 + f0]);
            u.z = __float_as_uint(sm_e[r0l*260 + f0 + 4]);
            u.w = __float_as_uint(sm_e[(r0l+8)*260 + f0 + 4]);
            *(uint4*)(outp + (size_t)(ks*1024 + sub*128 + ln*4)) = u;
        }
    }
}

// =====================================================================
// Fused ctx + out kernel (unchanged from R12, passing) — 2 CTAs/SM.
// smem (u32): region0 @0: 16384 | VBp @16384: 8192 | SKu @24576: 256
// =====================================================================
#define CO_SMEM_BYTES (24832 * 4)

__global__ __launch_bounds__(256, 2)
void ctx_out_mma()
{
    extern __shared__ uint32_t smu[];
    float*    vpl = (float*)smu;
    uint32_t* CBp = smu;
    uint32_t* ATs = smu;
    uint32_t* VBp = smu + 16384;
    uint32_t* SKu = smu + 24576;

    const int cid = blockIdx.x;
    const int b  = cid >> 8;
    const int h  = (cid >> 5) & 7;
    const int cc = cid & 31;
    const size_t row0 = (size_t)b * SEQ + (size_t)cc * CSZ;
    const int vcol = 2 * DIMM + h * DHD;
    const int tid  = threadIdx.x;
    const int lane = tid & 31;
    const int warp = tid >> 5;
    const int qr   = lane >> 2;
    const int qc   = lane & 3;

    const uint32_t* kbase = (const uint32_t*)g_kp + (size_t)cid * 32768;
    const uint32_t* qbase = (const uint32_t*)g_qp + (size_t)cid * 32768;

#pragma unroll
    for (int it = 0; it < 8; ++it) {
        const int idx4 = it * 256 + tid;
        const int s  = idx4 >> 4;
        const int d4 = (idx4 & 15) * 4;
        *(float4*)(vpl + s*72 + d4) =
            *(const float4*)(g_qkv + (row0 + s) * QKVN + vcol + d4);
    }
    if (tid < NF)
        SKu[tid] = f2tf32(g_ksumP[(size_t)cid * NF + tid] +
                          g_ksumP[((size_t)NCHUNK + cid) * NF + tid]);
    __syncthreads();

#pragma unroll
    for (int it = 0; it < 16; ++it) {
        const int wid2 = it * 256 + tid;
        const int ln   = wid2 & 31;
        const int nsub = (wid2 >> 5) & 7;
        const int ks   = wid2 >> 8;
        const int qc2 = ln & 3, qr2 = ln >> 2;
        const int s0 = ks*8 + qc2, d0 = nsub*8 + qr2;
        uint2 u;
        u.x = f2tf32(vpl[s0*72 + d0]);
        u.y = f2tf32(vpl[(s0+4)*72 + d0]);
        *(uint2*)(VBp + wid2*2) = u;
    }
    __syncthreads();

    float acc[2][8][4];
#pragma unroll
    for (int mt = 0; mt < 2; mt++)
#pragma unroll
        for (int nt = 0; nt < 8; nt++)
#pragma unroll
            for (int c = 0; c < 4; c++) acc[mt][nt][c] = 0.f;

#pragma unroll 4
    for (int ks = 0; ks < 16; ++ks) {
        uint4 a0 = *(const uint4*)(kbase + ks*2048 + (warp*2 + 0)*128 + lane*4);
        uint4 a1 = *(const uint4*)(kbase + ks*2048 + (warp*2 + 1)*128 + lane*4);
#pragma unroll
        for (int nt = 0; nt < 8; nt++) {
            uint2 bb = *(const uint2*)(VBp + ks*512 + nt*64 + lane*2);
            mma_tf32(acc[0][nt], a0.x, a0.y, a0.z, a0.w, bb.x, bb.y);
            mma_tf32(acc[1][nt], a1.x, a1.y, a1.z, a1.w, bb.x, bb.y);
        }
    }
    __syncthreads();

#pragma unroll
    for (int mt = 0; mt < 2; mt++)
#pragma unroll
        for (int nt = 0; nt < 8; nt++)
#pragma unroll
            for (int c = 0; c < 4; c++) {
                const int f = warp*32 + mt*16 + qr + ((c & 2) << 2);
                const int d = nt*8 + 2*qc + (c & 1);
                CBp[(f>>3)*512 + (d>>3)*64 + ((d&7)*4 + (f&3))*2 + ((f>>2)&1)]
                    = f2tf32(acc[mt][nt][c]);
            }
    __syncthreads();

    float acc2[8][4];
    float accD[4];
#pragma unroll
    for (int c = 0; c < 4; c++) accD[c] = 0.f;
#pragma unroll
    for (int nt = 0; nt < 8; nt++)
#pragma unroll
        for (int c = 0; c < 4; c++) acc2[nt][c] = 0.f;

#pragma unroll 4
    for (int ks = 0; ks < 32; ++ks) {
        uint4 a0 = *(const uint4*)(qbase + ks*1024 + warp*128 + lane*4);
        const uint32_t sb0 = SKu[ks*8 + qc];
        const uint32_t sb1 = SKu[ks*8 + qc + 4];
#pragma unroll
        for (int nt = 0; nt < 8; nt++) {
            uint2 bb = *(const uint2*)(CBp + ks*512 + nt*64 + lane*2);
            mma_tf32(acc2[nt], a0.x, a0.y, a0.z, a0.w, bb.x, bb.y);
        }
        mma_tf32(accD, a0.x, a0.y, a0.z, a0.w, sb0, sb1);
    }
    __syncthreads();

    {
        const float d0 = 1.0f / (accD[0] + 1e-4f);
        const float d1 = 1.0f / (accD[2] + 1e-4f);
#pragma unroll
        for (int nt = 0; nt < 8; nt++) {
#pragma unroll
            for (int c = 0; c < 4; c++) {
                const int r   = warp*16 + qr + (c & 2) * 4;
                const int col = nt*8 + 2*qc + (c & 1);
                const float dinv = (c & 2) ? d1 : d0;
                const int idx = (col>>4)*2048 + ((col>>3)&1)*1024 + (r>>4)*128
                              + ((r&7)*4 + (col&3))*4 + ((col>>2)&1)*2 + ((r>>3)&1);
                ATs[idx] = f2tf32(acc2[nt][c] * dinv);
            }
        }
    }
    __syncthreads();

    {
        const int tile = b*32 + cc;
        uint4* gdst = (uint4*)(g_att + (size_t)tile * 65536 + (size_t)h * 8192);
        const uint4* ssrc = (const uint4*)ATs;
#pragma unroll
        for (int i = 0; i < 8; ++i)
            gdst[i*256 + tid] = ssrc[i*256 + tid];
    }
}

// =====================================================================
// launch
// =====================================================================
extern "C" void kernel_launch(void* const* d_in, const int* in_sizes, int n_in,
                              void* d_out, int out_size)
{
    const float *x = nullptr, *wqkv = nullptr, *wout = nullptr,
                *bout = nullptr, *proj = nullptr;
    for (int i = 0; i < n_in; i++) {
        switch (in_sizes[i]) {
            case MTOK * DIMM:  x    = (const float*)d_in[i]; break;
            case QKVN * DIMM:  wqkv = (const float*)d_in[i]; break;
            case DIMM * DIMM:  wout = (const float*)d_in[i]; break;
            case DIMM:         bout = (const float*)d_in[i]; break;
            case NF * DHD:     proj = (const float*)d_in[i]; break;
        }
    }

    cudaFuncSetAttribute(feature_mma, cudaFuncAttributeMaxDynamicSharedMemorySize, FEAT_SMEM_BYTES);
    cudaFuncSetAttribute(ctx_out_mma, cudaFuncAttributeMaxDynamicSharedMemorySize, CO_SMEM_BYTES);
    cudaFuncSetAttribute(tgemm_nt<false>, cudaFuncAttributeMaxDynamicSharedMemorySize, TG_SMEM_BYTES);
    cudaFuncSetAttribute(tgemm_nt<true>,  cudaFuncAttributeMaxDynamicSharedMemorySize, TG_SMEM_BYTES);

    float *qkvp = nullptr;
    uint32_t *attp = nullptr, *xr = nullptr, *wqr = nullptr, *wor = nullptr, *ppk = nullptr;
    cudaGetSymbolAddress((void**)&qkvp, g_qkv);
    cudaGetSymbolAddress((void**)&attp, g_att);
    cudaGetSymbolAddress((void**)&xr,   g_xr);
    cudaGetSymbolAddress((void**)&wqr,  g_wqr);
    cudaGetSymbolAddress((void**)&wor,  g_wor);
    cudaGetSymbolAddress((void**)&ppk,  g_ppk);

    // 0) pack GEMM operands + proj into tf32 fragment layouts
    pack_A_tf32<<<(MTOK*DIMM/4 + 255)/256, 256>>>(x,    xr,  MTOK*DIMM/4);
    pack_B_tf32<<<(QKVN*DIMM/2 + 255)/256, 256>>>(wqkv, wqr, QKVN*DIMM/2);
    pack_B_tf32<<<(DIMM*DIMM/2 + 255)/256, 256>>>(wout, wor, DIMM*DIMM/2);
    pack_P_tf32<<<32, 256>>>(proj, ppk);

    // 1) qkv = x @ w_qkv^T   (BK=32 stages, 3-stage pipeline, 2 CTAs/SM)
    tgemm_nt<false><<<dim3(QKVN/128, MTOK/128), 256, TG_SMEM_BYTES>>>(
        xr, wqr, nullptr, qkvp, MTOK, QKVN, DIMM);
    // 2) q'/k' feature maps (proj frags from gmem) + ksum partials
    feature_mma<<<dim3(NCHUNK, 4), 256, FEAT_SMEM_BYTES>>>(ppk);
    // 3+4) fused ctx + out -> packed att
    ctx_out_mma<<<NCHUNK, 256, CO_SMEM_BYTES>>>();
    // 5) final = att @ w_out^T + b_out
    tgemm_nt<true><<<dim3(DIMM/128, MTOK/128), 256, TG_SMEM_BYTES>>>(
        attp, wor, bout, (float*)d_out, MTOK, DIMM, DIMM);
}